// round 11
// baseline (speedup 1.0000x reference)
#include <cuda_runtime.h>
#include <math.h>
#include <stdint.h>

#define Bb 2
#define Tt 1024
#define Dd 1024
#define Hh 8
#define DEPTH 5
#define NTOK (Bb*Tt)

// ---------------- scratch (device globals; allocation-free) ----------------
__device__ float g_paths[NTOK*Hh*DEPTH];      // [token][h*5+d]
__device__ float g_xr[NTOK*Dd];               // tf32(rna) hi part of x
__device__ float g_xlo[NTOK*Dd];              // tf32 lo residual of x
__device__ float g_wph[Dd*128];               // Wp hi, padded [k][128]
__device__ float g_wpl[Dd*128];               // Wp lo, padded [k][128]
__device__ float g_pp[4*NTOK*128];            // paths split-K partial logits
__device__ float g_wvr[Dd*Dd];                // rounded Wv [k][n]
__device__ float g_wor[Dd*Dd];                // rounded Wo [k][n]
__device__ float g_v[NTOK*Dd];                // V = x@Wv, rounded
__device__ float g_ctx[NTOK*Dd];              // ctx, final normalized

// ---------------- helpers ----------------
__device__ __forceinline__ float rnaf(float f) {
    uint32_t r; asm("cvt.rna.tf32.f32 %0, %1;" : "=r"(r) : "f"(f));
    return __uint_as_float(r);
}
__device__ __forceinline__ uint32_t smem_u32(const void* p) {
    uint32_t a;
    asm("{ .reg .u64 t; cvta.to.shared.u64 t, %1; cvt.u32.u64 %0, t; }" : "=r"(a) : "l"(p));
    return a;
}
__device__ __forceinline__ void cp16(uint32_t dst, const void* src) {
    asm volatile("cp.async.cg.shared.global [%0], [%1], 16;" :: "r"(dst), "l"(src));
}
__device__ __forceinline__ void mma_tf32(float c[4],
                                         uint32_t a0, uint32_t a1, uint32_t a2, uint32_t a3,
                                         uint32_t b0, uint32_t b1) {
    asm volatile("mma.sync.aligned.m16n8k8.row.col.f32.tf32.tf32.f32 "
                 "{%0,%1,%2,%3}, {%4,%5,%6,%7}, {%8,%9}, {%0,%1,%2,%3};"
                 : "+f"(c[0]), "+f"(c[1]), "+f"(c[2]), "+f"(c[3])
                 : "r"(a0), "r"(a1), "r"(a2), "r"(a3), "r"(b0), "r"(b1));
}
__device__ __forceinline__ float expap(float x) {   // e^x, x in (0,1], deg-7
    float p = 1.98412698e-4f;
    p = fmaf(p, x, 1.38888889e-3f);
    p = fmaf(p, x, 8.33333333e-3f);
    p = fmaf(p, x, 4.16666667e-2f);
    p = fmaf(p, x, 1.66666667e-1f);
    p = fmaf(p, x, 0.5f);
    p = fmaf(p, x, 1.0f);
    p = fmaf(p, x, 1.0f);
    return p;
}

#define ASTRIDE 36
#define BSTRIDE 136

// ---------------------------------------------------------------------------
// dense tf32 GEMM (round-8 best): C[128,128] tile, 256 threads = 8 warps
// (2m x 4n, warp tile 64x32), BK=32, 3-stage cp.async.
// ---------------------------------------------------------------------------
#define A2FLOATS (128*ASTRIDE)                 // 4608
#define STAGEF2  (A2FLOATS + 32*BSTRIDE)       // 8960 floats
#define SMEM_GEMM2 (3*STAGEF2*4)               // 107520 B

__device__ __forceinline__ void load_stage2(uint32_t sb, int s,
                                            const float* A, int lda, int bm,
                                            const float* B, int ldb, int bn,
                                            int tid, int kt) {
    uint32_t sa = sb + s * (STAGEF2 * 4);
    uint32_t sB = sa + A2FLOATS * 4;
    int k0 = kt * 32;
    #pragma unroll
    for (int t = 0; t < 4; t++) {
        int c = tid + t * 256;
        int row = c >> 3, col = c & 7;
        cp16(sa + row * (ASTRIDE*4) + col * 16,
             A + (size_t)(bm + row) * lda + k0 + col * 4);
    }
    #pragma unroll
    for (int t = 0; t < 4; t++) {
        int c = tid + t * 256;
        int row = c >> 5, col = c & 31;
        cp16(sB + row * (BSTRIDE*4) + col * 16,
             B + (size_t)(k0 + row) * ldb + bn + col * 4);
    }
}

__global__ __launch_bounds__(256, 1) void gemm128(const float* __restrict__ A,
                                                  const float* __restrict__ Bw,
                                                  float* __restrict__ C,
                                                  int K, int N, int mode) {
    extern __shared__ float sm[];
    uint32_t sb = smem_u32(sm);
    int tid = threadIdx.x;
    int warp = tid >> 5, lane = tid & 31;
    int wm = (warp & 1) * 64;
    int wn = (warp >> 1) * 32;
    int tg = lane >> 2, tk = lane & 3;
    int bm = blockIdx.y * 128, bn = blockIdx.x * 128;
    int KT = K / 32;

    float acc[4][4][4];
    #pragma unroll
    for (int mt = 0; mt < 4; mt++)
        #pragma unroll
        for (int nt = 0; nt < 4; nt++)
            #pragma unroll
            for (int i = 0; i < 4; i++) acc[mt][nt][i] = 0.f;

    load_stage2(sb, 0, A, K, bm, Bw, N, bn, tid, 0);
    asm volatile("cp.async.commit_group;" ::: "memory");
    load_stage2(sb, 1, A, K, bm, Bw, N, bn, tid, 1);
    asm volatile("cp.async.commit_group;" ::: "memory");

    for (int it = 0; it < KT; it++) {
        asm volatile("cp.async.wait_group 1;" ::: "memory");
        __syncthreads();
        int pf = it + 2;
        if (pf < KT) load_stage2(sb, pf % 3, A, K, bm, Bw, N, bn, tid, pf);
        asm volatile("cp.async.commit_group;" ::: "memory");

        const float* As = sm + (it % 3) * STAGEF2;
        const float* Bs = As + A2FLOATS;
        #pragma unroll
        for (int kq = 0; kq < 32; kq += 8) {
            uint32_t af[4][4], bf[4][2];
            #pragma unroll
            for (int mt = 0; mt < 4; mt++) {
                int m = wm + mt * 16 + tg;
                af[mt][0] = __float_as_uint(As[m * ASTRIDE + kq + tk]);
                af[mt][1] = __float_as_uint(As[(m + 8) * ASTRIDE + kq + tk]);
                af[mt][2] = __float_as_uint(As[m * ASTRIDE + kq + tk + 4]);
                af[mt][3] = __float_as_uint(As[(m + 8) * ASTRIDE + kq + tk + 4]);
            }
            #pragma unroll
            for (int nt = 0; nt < 4; nt++) {
                int n = wn + nt * 8 + tg;
                bf[nt][0] = __float_as_uint(Bs[(kq + tk) * BSTRIDE + n]);
                bf[nt][1] = __float_as_uint(Bs[(kq + tk + 4) * BSTRIDE + n]);
            }
            #pragma unroll
            for (int mt = 0; mt < 4; mt++)
                #pragma unroll
                for (int nt = 0; nt < 4; nt++)
                    mma_tf32(acc[mt][nt], af[mt][0], af[mt][1], af[mt][2], af[mt][3],
                             bf[nt][0], bf[nt][1]);
        }
        __syncthreads();
    }

    #pragma unroll
    for (int mt = 0; mt < 4; mt++) {
        #pragma unroll
        for (int nt = 0; nt < 4; nt++) {
            int r0 = bm + wm + mt * 16 + tg;
            int cc = bn + wn + nt * 8 + tk * 2;
            float2 v0 = make_float2(acc[mt][nt][0], acc[mt][nt][1]);
            float2 v1 = make_float2(acc[mt][nt][2], acc[mt][nt][3]);
            if (mode == 1) {
                v0.x = rnaf(v0.x); v0.y = rnaf(v0.y);
                v1.x = rnaf(v1.x); v1.y = rnaf(v1.y);
            }
            *(float2*)&C[(size_t)r0 * N + cc]       = v0;
            *(float2*)&C[(size_t)(r0 + 8) * N + cc] = v1;
        }
    }
}

// ---------------------------------------------------------------------------
// Paired fused av: CTA j handles q-tiles (15-j) and (j) — equal 34 K-units
// per CTA, all tiles self-normalized, no partials. Grid (8, B*H), 256 thr.
// ---------------------------------------------------------------------------
#define AV_AS     0
#define AV_BS     (64*ASTRIDE)
#define AV_PQ     (AV_BS + 3*32*BSTRIDE)
#define AV_PK     (AV_PQ + 320)
#define AV_RS     (AV_PK + 160)
#define AV_FLOATS (AV_RS + 64)
#define SMEM_AV   (AV_FLOATS*4)

__device__ void av_one(int qt, const float* pb, const float* Bv,
                       float* ctxp, float* sm, uint32_t sb) {
    int tid = threadIdx.x;
    int warp = tid >> 5, lane = tid & 31;
    float* As  = sm + AV_AS;
    float* pqs = sm + AV_PQ;
    float* pks = sm + AV_PK;
    float* rsm = sm + AV_RS;
    int KT = 2 * (qt + 1);

    for (int idx = tid; idx < 64 * DEPTH; idx += 256)
        pqs[idx] = pb[(size_t)(qt * 64 + idx / DEPTH) * (Hh*DEPTH) + idx % DEPTH];

    {
        uint32_t sB = sb + AV_BS * 4;
        #pragma unroll
        for (int s = 0; s < 2; s++) {
            int kb = s * 32;
            #pragma unroll
            for (int t = 0; t < 4; t++) {
                int c = tid + t * 256;
                int row = c >> 5, col = c & 31;
                cp16(sB + s * (32*BSTRIDE*4) + row * (BSTRIDE*4) + col * 16,
                     Bv + (size_t)(kb + row) * Dd + col * 4);
            }
            asm volatile("cp.async.commit_group;" ::: "memory");
        }
    }

    int wm = (warp & 1) * 32;
    int wn = (warp >> 1) * 32;
    int tg = lane >> 2, tk = lane & 3;
    float acc[2][4][4];
    #pragma unroll
    for (int mt = 0; mt < 2; mt++)
        #pragma unroll
        for (int nt = 0; nt < 4; nt++)
            #pragma unroll
            for (int i = 0; i < 4; i++) acc[mt][nt][i] = 0.f;
    float rsum[8];
    #pragma unroll
    for (int i = 0; i < 8; i++) rsum[i] = 0.f;

    for (int it = 0; it < KT; it++) {
        int kb = it * 32;
        if (tid < 32 * DEPTH)
            pks[tid] = pb[(size_t)(kb + tid / DEPTH) * (Hh*DEPTH) + tid % DEPTH];
        __syncthreads();

        {
            float k0v = pks[lane*5+0], k1v = pks[lane*5+1], k2v = pks[lane*5+2],
                  k3v = pks[lane*5+3], k4v = pks[lane*5+4];
            float m0 = 1.f - k0v, m1 = 1.f - k1v, m2 = 1.f - k2v,
                  m3 = 1.f - k3v, m4 = 1.f - k4v;
            int kglob = kb + lane;
            #pragma unroll
            for (int jr = 0; jr < 8; jr++) {
                int row = warp * 8 + jr;
                const float* pq = pqs + row * 5;
                float p0 = pq[0], p1 = pq[1], p2 = pq[2], p3 = pq[3], p4 = pq[4];
                float prod = p0 * k0v + (1.f - p0) * m0;
                float s = prod;
                prod *= p1 * k1v + (1.f - p1) * m1; s += prod;
                prod *= p2 * k2v + (1.f - p2) * m2; s += prod;
                prod *= p3 * k3v + (1.f - p3) * m3; s += prod;
                prod *= p4 * k4v + (1.f - p4) * m4; s += prod;
                float ev = 0.f;
                if (kglob <= qt * 64 + row) ev = rnaf(expap(s * 0.2f));
                rsum[jr] += ev;
                As[row * ASTRIDE + lane] = ev;
            }
        }

        asm volatile("cp.async.wait_group 1;" ::: "memory");
        __syncthreads();

        int pf = it + 2;
        if (pf < KT) {
            uint32_t sB = sb + AV_BS * 4 + (pf % 3) * (32*BSTRIDE*4);
            int kb2 = pf * 32;
            #pragma unroll
            for (int t = 0; t < 4; t++) {
                int c = tid + t * 256;
                int row = c >> 5, col = c & 31;
                cp16(sB + row * (BSTRIDE*4) + col * 16,
                     Bv + (size_t)(kb2 + row) * Dd + col * 4);
            }
        }
        asm volatile("cp.async.commit_group;" ::: "memory");

        const float* Bs = sm + AV_BS + (it % 3) * (32*BSTRIDE);
        #pragma unroll
        for (int kq = 0; kq < 32; kq += 8) {
            uint32_t af[2][4], bf[4][2];
            #pragma unroll
            for (int mt = 0; mt < 2; mt++) {
                int m = wm + mt * 16 + tg;
                af[mt][0] = __float_as_uint(As[m * ASTRIDE + kq + tk]);
                af[mt][1] = __float_as_uint(As[(m + 8) * ASTRIDE + kq + tk]);
                af[mt][2] = __float_as_uint(As[m * ASTRIDE + kq + tk + 4]);
                af[mt][3] = __float_as_uint(As[(m + 8) * ASTRIDE + kq + tk + 4]);
            }
            #pragma unroll
            for (int nt = 0; nt < 4; nt++) {
                int n = wn + nt * 8 + tg;
                bf[nt][0] = __float_as_uint(Bs[(kq + tk) * BSTRIDE + n]);
                bf[nt][1] = __float_as_uint(Bs[(kq + tk + 4) * BSTRIDE + n]);
            }
            #pragma unroll
            for (int mt = 0; mt < 2; mt++)
                #pragma unroll
                for (int nt = 0; nt < 4; nt++)
                    mma_tf32(acc[mt][nt], af[mt][0], af[mt][1], af[mt][2], af[mt][3],
                             bf[nt][0], bf[nt][1]);
        }
    }

    #pragma unroll
    for (int jr = 0; jr < 8; jr++) {
        float s = rsum[jr];
        #pragma unroll
        for (int o = 16; o > 0; o >>= 1) s += __shfl_xor_sync(0xffffffffu, s, o);
        if (lane == 0) rsm[warp * 8 + jr] = s;
    }
    __syncthreads();

    // self-normalized final store
    #pragma unroll
    for (int mt = 0; mt < 2; mt++) {
        int rl0 = wm + mt * 16 + tg;
        float i0 = 1.f / rsm[rl0], i1 = 1.f / rsm[rl0 + 8];
        #pragma unroll
        for (int nt = 0; nt < 4; nt++) {
            int r0 = qt * 64 + rl0;
            int cc = wn + nt * 8 + tk * 2;
            *(float2*)&ctxp[(size_t)r0 * Dd + cc] =
                make_float2(rnaf(acc[mt][nt][0] * i0), rnaf(acc[mt][nt][1] * i0));
            *(float2*)&ctxp[(size_t)(r0 + 8) * Dd + cc] =
                make_float2(rnaf(acc[mt][nt][2] * i1), rnaf(acc[mt][nt][3] * i1));
        }
    }
    __syncthreads();   // smem reuse safety before next sub-job
}

__global__ __launch_bounds__(256) void av_paired(const float* __restrict__ paths,
                                                 const float* __restrict__ v,
                                                 float* __restrict__ ctx) {
    extern __shared__ float sm[];
    uint32_t sb = smem_u32(sm);
    int j = blockIdx.x, bh = blockIdx.y;
    int b = bh >> 3, h = bh & 7;
    const float* pb = paths + (size_t)(b * Tt) * (Hh*DEPTH) + h * DEPTH;
    const float* Bv = v + (size_t)b * Tt * Dd + h * 128;
    float* ctxp = ctx + (size_t)b * Tt * Dd + h * 128;

    av_one(15 - j, pb, Bv, ctxp, sm, sb);   // long tile first
    av_one(j,      pb, Bv, ctxp, sm, sb);   // short tile
}

// ---------------------------------------------------------------------------
// paths GEMM split-K x4 (split-tf32) + sigmoid combine — unchanged
// ---------------------------------------------------------------------------
#define PSTAGEF (2*64*36 + 2*32*136)
#define SMEM_PATHS (2*PSTAGEF*4)

__device__ __forceinline__ void paths_load(uint32_t sb, int s,
                                           const float* xh, const float* xl, int bm,
                                           const float* wh, const float* wl,
                                           int tid, int kt) {
    uint32_t base = sb + s * (PSTAGEF * 4);
    uint32_t xh_o = base;
    uint32_t xl_o = base + 64*36*4;
    uint32_t wh_o = xl_o + 64*36*4;
    uint32_t wl_o = wh_o + 32*136*4;
    int k0 = kt * 32;
    #pragma unroll
    for (int t = 0; t < 2; t++) {
        int c = tid + t * 256;
        int row = c >> 3, col = c & 7;
        size_t go = (size_t)(bm + row) * Dd + k0 + col * 4;
        uint32_t so = row * (36*4) + col * 16;
        cp16(xh_o + so, xh + go);
        cp16(xl_o + so, xl + go);
    }
    #pragma unroll
    for (int t = 0; t < 4; t++) {
        int c = tid + t * 256;
        int row = c >> 5, col = c & 31;
        size_t go = (size_t)(k0 + row) * 128 + col * 4;
        uint32_t so = row * (136*4) + col * 16;
        cp16(wh_o + so, wh + go);
        cp16(wl_o + so, wl + go);
    }
}

__global__ __launch_bounds__(256) void paths_gemm(const float* __restrict__ xh0,
                                                  const float* __restrict__ xl0,
                                                  const float* __restrict__ wh0,
                                                  const float* __restrict__ wl0,
                                                  float* __restrict__ pp) {
    extern __shared__ float sm[];
    uint32_t sb = smem_u32(sm);
    int tid = threadIdx.x;
    int warp = tid >> 5, lane = tid & 31;
    int wm = (warp & 1) * 32;
    int wn = (warp >> 1) * 32;
    int tg = lane >> 2, tk = lane & 3;
    int bm = blockIdx.x * 64;
    int sp = blockIdx.y;
    const float* xh = xh0 + sp * 256;
    const float* xl = xl0 + sp * 256;
    const float* wh = wh0 + (size_t)(sp * 256) * 128;
    const float* wl = wl0 + (size_t)(sp * 256) * 128;
    float* out = pp + (size_t)sp * NTOK * 128;
    const int KT = 8;

    float acc[2][4][4];
    #pragma unroll
    for (int mt = 0; mt < 2; mt++)
        #pragma unroll
        for (int nt = 0; nt < 4; nt++)
            #pragma unroll
            for (int i = 0; i < 4; i++) acc[mt][nt][i] = 0.f;

    paths_load(sb, 0, xh, xl, bm, wh, wl, tid, 0);
    asm volatile("cp.async.commit_group;" ::: "memory");

    for (int it = 0; it < KT; it++) {
        int pf = it + 1;
        if (pf < KT) {
            paths_load(sb, pf & 1, xh, xl, bm, wh, wl, tid, pf);
            asm volatile("cp.async.commit_group;" ::: "memory");
            asm volatile("cp.async.wait_group 1;" ::: "memory");
        } else {
            asm volatile("cp.async.wait_group 0;" ::: "memory");
        }
        __syncthreads();

        const float* Xh = sm + (it & 1) * PSTAGEF;
        const float* Xl = Xh + 64*36;
        const float* Wh = Xl + 64*36;
        const float* Wl = Wh + 32*136;
        #pragma unroll
        for (int kq = 0; kq < 32; kq += 8) {
            uint32_t ah[2][4], al[2][4], bh[4][2], bl[4][2];
            #pragma unroll
            for (int mt = 0; mt < 2; mt++) {
                int m = wm + mt * 16 + tg;
                ah[mt][0] = __float_as_uint(Xh[m * 36 + kq + tk]);
                ah[mt][1] = __float_as_uint(Xh[(m + 8) * 36 + kq + tk]);
                ah[mt][2] = __float_as_uint(Xh[m * 36 + kq + tk + 4]);
                ah[mt][3] = __float_as_uint(Xh[(m + 8) * 36 + kq + tk + 4]);
                al[mt][0] = __float_as_uint(Xl[m * 36 + kq + tk]);
                al[mt][1] = __float_as_uint(Xl[(m + 8) * 36 + kq + tk]);
                al[mt][2] = __float_as_uint(Xl[m * 36 + kq + tk + 4]);
                al[mt][3] = __float_as_uint(Xl[(m + 8) * 36 + kq + tk + 4]);
            }
            #pragma unroll
            for (int nt = 0; nt < 4; nt++) {
                int n = wn + nt * 8 + tg;
                bh[nt][0] = __float_as_uint(Wh[(kq + tk) * 136 + n]);
                bh[nt][1] = __float_as_uint(Wh[(kq + tk + 4) * 136 + n]);
                bl[nt][0] = __float_as_uint(Wl[(kq + tk) * 136 + n]);
                bl[nt][1] = __float_as_uint(Wl[(kq + tk + 4) * 136 + n]);
            }
            #pragma unroll
            for (int mt = 0; mt < 2; mt++)
                #pragma unroll
                for (int nt = 0; nt < 4; nt++) {
                    mma_tf32(acc[mt][nt], ah[mt][0], ah[mt][1], ah[mt][2], ah[mt][3],
                             bh[nt][0], bh[nt][1]);
                    mma_tf32(acc[mt][nt], ah[mt][0], ah[mt][1], ah[mt][2], ah[mt][3],
                             bl[nt][0], bl[nt][1]);
                    mma_tf32(acc[mt][nt], al[mt][0], al[mt][1], al[mt][2], al[mt][3],
                             bh[nt][0], bh[nt][1]);
                }
        }
        __syncthreads();
    }

    #pragma unroll
    for (int mt = 0; mt < 2; mt++) {
        #pragma unroll
        for (int nt = 0; nt < 4; nt++) {
            int cc = wn + nt * 8 + tk * 2;
            if (cc < Hh * DEPTH) {
                int r0 = bm + wm + mt * 16 + tg;
                out[(size_t)r0 * 128 + cc]           = acc[mt][nt][0];
                out[(size_t)r0 * 128 + cc + 1]       = acc[mt][nt][1];
                out[(size_t)(r0 + 8) * 128 + cc]     = acc[mt][nt][2];
                out[(size_t)(r0 + 8) * 128 + cc + 1] = acc[mt][nt][3];
            }
        }
    }
}

__global__ __launch_bounds__(256) void sigmoid_comb(const float* __restrict__ pp,
                                                    const float* __restrict__ bp,
                                                    float* __restrict__ paths) {
    int tok = blockIdx.x * 4 + (threadIdx.x >> 6);
    int c = threadIdx.x & 63;
    if (c < Hh * DEPTH) {
        float z = bp[c];
        #pragma unroll
        for (int s = 0; s < 4; s++)
            z += pp[(size_t)s * NTOK * 128 + (size_t)tok * 128 + c];
        paths[(size_t)tok * (Hh*DEPTH) + c] = 1.f / (1.f + expf(-z));
    }
}

// ---------------- merged staging ----------------
__global__ __launch_bounds__(256) void prep_all(const float4* __restrict__ x,
                                                float4* __restrict__ xh,
                                                float4* __restrict__ xl,
                                                const float4* __restrict__ Wv,
                                                float4* __restrict__ wvr,
                                                const float4* __restrict__ Wo,
                                                float4* __restrict__ wor,
                                                const float* __restrict__ Wp) {
    int i = blockIdx.x * 256 + threadIdx.x;
    if (i < NTOK*Dd/4) {
        float4 v = x[i];
        float4 h = make_float4(rnaf(v.x), rnaf(v.y), rnaf(v.z), rnaf(v.w));
        xh[i] = h;
        xl[i] = make_float4(rnaf(v.x - h.x), rnaf(v.y - h.y), rnaf(v.z - h.z), rnaf(v.w - h.w));
    }
    if (i < Dd*Dd/4) {
        float4 a = Wv[i], b = Wo[i];
        wvr[i] = make_float4(rnaf(a.x), rnaf(a.y), rnaf(a.z), rnaf(a.w));
        wor[i] = make_float4(rnaf(b.x), rnaf(b.y), rnaf(b.z), rnaf(b.w));
    }
    if (i < Dd*128) {
        int k = i >> 7, n = i & 127;
        float h = 0.f, l = 0.f;
        if (n < Hh * DEPTH) {
            float w = Wp[(size_t)k * (Hh * DEPTH) + n];
            h = rnaf(w);
            l = rnaf(w - h);
        }
        g_wph[i] = h;
        g_wpl[i] = l;
    }
}

// ---------------------------------------------------------------------------
extern "C" void kernel_launch(void* const* d_in, const int* in_sizes, int n_in,
                              void* d_out, int out_size) {
    const float* x  = (const float*)d_in[0];
    const float* Wp = (const float*)d_in[1];
    const float* bp = (const float*)d_in[2];
    const float* Wv = (const float*)d_in[3];
    const float* Wo = (const float*)d_in[4];
    float* out = (float*)d_out;

    float *paths, *xr, *xlo, *wph, *wpl, *pp, *wvr, *wor, *v, *ctx;
    cudaGetSymbolAddress((void**)&paths, g_paths);
    cudaGetSymbolAddress((void**)&xr,    g_xr);
    cudaGetSymbolAddress((void**)&xlo,   g_xlo);
    cudaGetSymbolAddress((void**)&wph,   g_wph);
    cudaGetSymbolAddress((void**)&wpl,   g_wpl);
    cudaGetSymbolAddress((void**)&pp,    g_pp);
    cudaGetSymbolAddress((void**)&wvr,   g_wvr);
    cudaGetSymbolAddress((void**)&wor,   g_wor);
    cudaGetSymbolAddress((void**)&v,     g_v);
    cudaGetSymbolAddress((void**)&ctx,   g_ctx);

    cudaFuncSetAttribute(gemm128,    cudaFuncAttributeMaxDynamicSharedMemorySize, SMEM_GEMM2);
    cudaFuncSetAttribute(av_paired,  cudaFuncAttributeMaxDynamicSharedMemorySize, SMEM_AV);
    cudaFuncSetAttribute(paths_gemm, cudaFuncAttributeMaxDynamicSharedMemorySize, SMEM_PATHS);

    // one-time side stream + events (same captured work every call)
    static cudaStream_t s2 = nullptr;
    static cudaEvent_t evP = nullptr, evV = nullptr;
    if (!s2) {
        cudaStreamCreateWithFlags(&s2, cudaStreamNonBlocking);
        cudaEventCreateWithFlags(&evP, cudaEventDisableTiming);
        cudaEventCreateWithFlags(&evV, cudaEventDisableTiming);
    }

    // staging (default stream)
    prep_all<<<(NTOK*Dd/4 + 255)/256, 256>>>((const float4*)x, (float4*)xr, (float4*)xlo,
                                             (const float4*)Wv, (float4*)wvr,
                                             (const float4*)Wo, (float4*)wor, Wp);

    // fork: V = x @ Wv on side stream, overlapped with paths chain
    cudaEventRecord(evP, 0);
    cudaStreamWaitEvent(s2, evP, 0);
    gemm128<<<dim3(Dd/128, NTOK/128), 256, SMEM_GEMM2, s2>>>(xr, wvr, v, Dd, Dd, 1);
    cudaEventRecord(evV, s2);

    // paths = sigmoid(x @ Wp + bp) on default stream (hidden under V gemm)
    paths_gemm<<<dim3(NTOK/64, 4), 256, SMEM_PATHS>>>(xr, xlo, wph, wpl, pp);
    sigmoid_comb<<<NTOK/4, 256>>>(pp, bp, paths);

    // join, then fused sim+softmax+attn@V (pair-balanced, self-normalized)
    cudaStreamWaitEvent(0, evV, 0);
    av_paired<<<dim3(8, Bb*Hh), 256, SMEM_AV>>>(paths, v, ctx);

    // out = ctx @ Wo
    gemm128<<<dim3(Dd/128, NTOK/128), 256, SMEM_GEMM2>>>(ctx, wor, out, Dd, Dd, 0);
}

// round 12
// speedup vs baseline: 1.0430x; 1.0430x over previous
#include <cuda_runtime.h>
#include <math.h>
#include <stdint.h>

#define Bb 2
#define Tt 1024
#define Dd 1024
#define Hh 8
#define DEPTH 5
#define NTOK (Bb*Tt)

// ---------------- scratch (device globals; allocation-free) ----------------
__device__ float g_paths[NTOK*Hh*DEPTH];      // [token][h*5+d]
__device__ float g_xr[NTOK*Dd];               // tf32(rna) hi part of x
__device__ float g_xlo[NTOK*Dd];              // tf32 lo residual of x
__device__ float g_wph[Dd*128];               // Wp hi, padded [k][128]
__device__ float g_wpl[Dd*128];               // Wp lo, padded [k][128]
__device__ float g_pp[4*NTOK*128];            // paths split-K partial logits
__device__ float g_wvr[Dd*Dd];                // rounded Wv [k][n]
__device__ float g_wor[Dd*Dd];                // rounded Wo [k][n]
__device__ float g_v[NTOK*Dd];                // V = x@Wv, rounded
__device__ float g_ctx[NTOK*Dd];              // ctx (t<512 final; t>=512 partial slot0)
__device__ float g_ctx2[NTOK*Dd];             // ctx partial slot1 (t>=512 only)
__device__ float g_rs[2*Bb*Hh*Tt];            // row sums [slot][bh][t]

// av jobs (24/bh, longest first). qt<8 full (self-normalized); qt>=8 split.
__constant__ int c_qt[24] = {15,15,14,14,13,13,12,12,11,11,10,10, 9, 9, 8, 8, 7, 6, 5, 4, 3, 2, 1, 0};
__constant__ int c_k0[24] = { 0,16, 0,15, 0,14, 0,13, 0,12, 0,11, 0,10, 0, 9, 0, 0, 0, 0, 0, 0, 0, 0};
__constant__ int c_kt[24] = {16,16,15,15,14,14,13,13,12,12,11,11,10,10, 9, 9,16,14,12,10, 8, 6, 4, 2};
__constant__ int c_ds[24] = { 0, 1, 0, 1, 0, 1, 0, 1, 0, 1, 0, 1, 0, 1, 0, 1, 0, 0, 0, 0, 0, 0, 0, 0};

// ---------------- helpers ----------------
__device__ __forceinline__ float rnaf(float f) {
    uint32_t r; asm("cvt.rna.tf32.f32 %0, %1;" : "=r"(r) : "f"(f));
    return __uint_as_float(r);
}
__device__ __forceinline__ uint32_t smem_u32(const void* p) {
    uint32_t a;
    asm("{ .reg .u64 t; cvta.to.shared.u64 t, %1; cvt.u32.u64 %0, t; }" : "=r"(a) : "l"(p));
    return a;
}
__device__ __forceinline__ void cp16(uint32_t dst, const void* src) {
    asm volatile("cp.async.cg.shared.global [%0], [%1], 16;" :: "r"(dst), "l"(src));
}
__device__ __forceinline__ void mma_tf32(float c[4],
                                         uint32_t a0, uint32_t a1, uint32_t a2, uint32_t a3,
                                         uint32_t b0, uint32_t b1) {
    asm volatile("mma.sync.aligned.m16n8k8.row.col.f32.tf32.tf32.f32 "
                 "{%0,%1,%2,%3}, {%4,%5,%6,%7}, {%8,%9}, {%0,%1,%2,%3};"
                 : "+f"(c[0]), "+f"(c[1]), "+f"(c[2]), "+f"(c[3])
                 : "r"(a0), "r"(a1), "r"(a2), "r"(a3), "r"(b0), "r"(b1));
}
__device__ __forceinline__ float expap(float x) {   // e^x, x in (0,1], deg-7
    float p = 1.98412698e-4f;
    p = fmaf(p, x, 1.38888889e-3f);
    p = fmaf(p, x, 8.33333333e-3f);
    p = fmaf(p, x, 4.16666667e-2f);
    p = fmaf(p, x, 1.66666667e-1f);
    p = fmaf(p, x, 0.5f);
    p = fmaf(p, x, 1.0f);
    p = fmaf(p, x, 1.0f);
    return p;
}

#define ASTRIDE 36
#define BSTRIDE 136

// ---------------------------------------------------------------------------
// dense tf32 GEMM (round-8 best): C[128,128] tile, 256 threads = 8 warps
// (2m x 4n, warp tile 64x32), BK=32, 3-stage cp.async.
// ---------------------------------------------------------------------------
#define A2FLOATS (128*ASTRIDE)                 // 4608
#define STAGEF2  (A2FLOATS + 32*BSTRIDE)       // 8960 floats
#define SMEM_GEMM2 (3*STAGEF2*4)               // 107520 B

__device__ __forceinline__ void load_stage2(uint32_t sb, int s,
                                            const float* A, int lda, int bm,
                                            const float* B, int ldb, int bn,
                                            int tid, int kt) {
    uint32_t sa = sb + s * (STAGEF2 * 4);
    uint32_t sB = sa + A2FLOATS * 4;
    int k0 = kt * 32;
    #pragma unroll
    for (int t = 0; t < 4; t++) {
        int c = tid + t * 256;
        int row = c >> 3, col = c & 7;
        cp16(sa + row * (ASTRIDE*4) + col * 16,
             A + (size_t)(bm + row) * lda + k0 + col * 4);
    }
    #pragma unroll
    for (int t = 0; t < 4; t++) {
        int c = tid + t * 256;
        int row = c >> 5, col = c & 31;
        cp16(sB + row * (BSTRIDE*4) + col * 16,
             B + (size_t)(k0 + row) * ldb + bn + col * 4);
    }
}

__global__ __launch_bounds__(256, 1) void gemm128(const float* __restrict__ A,
                                                  const float* __restrict__ Bw,
                                                  float* __restrict__ C,
                                                  int K, int N, int mode) {
    extern __shared__ float sm[];
    uint32_t sb = smem_u32(sm);
    int tid = threadIdx.x;
    int warp = tid >> 5, lane = tid & 31;
    int wm = (warp & 1) * 64;
    int wn = (warp >> 1) * 32;
    int tg = lane >> 2, tk = lane & 3;
    int bm = blockIdx.y * 128, bn = blockIdx.x * 128;
    int KT = K / 32;

    float acc[4][4][4];
    #pragma unroll
    for (int mt = 0; mt < 4; mt++)
        #pragma unroll
        for (int nt = 0; nt < 4; nt++)
            #pragma unroll
            for (int i = 0; i < 4; i++) acc[mt][nt][i] = 0.f;

    load_stage2(sb, 0, A, K, bm, Bw, N, bn, tid, 0);
    asm volatile("cp.async.commit_group;" ::: "memory");
    load_stage2(sb, 1, A, K, bm, Bw, N, bn, tid, 1);
    asm volatile("cp.async.commit_group;" ::: "memory");

    for (int it = 0; it < KT; it++) {
        asm volatile("cp.async.wait_group 1;" ::: "memory");
        __syncthreads();
        int pf = it + 2;
        if (pf < KT) load_stage2(sb, pf % 3, A, K, bm, Bw, N, bn, tid, pf);
        asm volatile("cp.async.commit_group;" ::: "memory");

        const float* As = sm + (it % 3) * STAGEF2;
        const float* Bs = As + A2FLOATS;
        #pragma unroll
        for (int kq = 0; kq < 32; kq += 8) {
            uint32_t af[4][4], bf[4][2];
            #pragma unroll
            for (int mt = 0; mt < 4; mt++) {
                int m = wm + mt * 16 + tg;
                af[mt][0] = __float_as_uint(As[m * ASTRIDE + kq + tk]);
                af[mt][1] = __float_as_uint(As[(m + 8) * ASTRIDE + kq + tk]);
                af[mt][2] = __float_as_uint(As[m * ASTRIDE + kq + tk + 4]);
                af[mt][3] = __float_as_uint(As[(m + 8) * ASTRIDE + kq + tk + 4]);
            }
            #pragma unroll
            for (int nt = 0; nt < 4; nt++) {
                int n = wn + nt * 8 + tg;
                bf[nt][0] = __float_as_uint(Bs[(kq + tk) * BSTRIDE + n]);
                bf[nt][1] = __float_as_uint(Bs[(kq + tk + 4) * BSTRIDE + n]);
            }
            #pragma unroll
            for (int mt = 0; mt < 4; mt++)
                #pragma unroll
                for (int nt = 0; nt < 4; nt++)
                    mma_tf32(acc[mt][nt], af[mt][0], af[mt][1], af[mt][2], af[mt][3],
                             bf[nt][0], bf[nt][1]);
        }
        __syncthreads();
    }

    #pragma unroll
    for (int mt = 0; mt < 4; mt++) {
        #pragma unroll
        for (int nt = 0; nt < 4; nt++) {
            int r0 = bm + wm + mt * 16 + tg;
            int cc = bn + wn + nt * 8 + tk * 2;
            float2 v0 = make_float2(acc[mt][nt][0], acc[mt][nt][1]);
            float2 v1 = make_float2(acc[mt][nt][2], acc[mt][nt][3]);
            if (mode == 1) {
                v0.x = rnaf(v0.x); v0.y = rnaf(v0.y);
                v1.x = rnaf(v1.x); v1.y = rnaf(v1.y);
            }
            *(float2*)&C[(size_t)r0 * N + cc]       = v0;
            *(float2*)&C[(size_t)(r0 + 8) * N + cc] = v1;
        }
    }
}

// ---------------------------------------------------------------------------
// Fused av, pipelined: whole-job k-paths preloaded; e-tile double-buffered so
// iteration it issues MMA(it) then computes e-tile(it+1) — FMA overlaps tensor.
// One __syncthreads per iteration.
// smem (floats): As[2] 2*2304 | Bs[3] 3*4352 | pqs 320 | pkAll 2560 | rsm 64
// ---------------------------------------------------------------------------
#define AV_AS     0
#define AV_BS     (2*64*ASTRIDE)                   // 4608
#define AV_PQ     (AV_BS + 3*32*BSTRIDE)           // 17664
#define AV_PK     (AV_PQ + 320)                    // 17984
#define AV_RS     (AV_PK + 16*32*DEPTH)            // 20544
#define AV_FLOATS (AV_RS + 64)                     // 20608
#define SMEM_AV   (AV_FLOATS*4)                    // 82432 B

__global__ __launch_bounds__(256) void av_fused(const float* __restrict__ paths,
                                                const float* __restrict__ v,
                                                float* __restrict__ ctx,
                                                float* __restrict__ ctx2,
                                                float* __restrict__ rs) {
    extern __shared__ float sm[];
    uint32_t sb = smem_u32(sm);
    int j = blockIdx.x, bh = blockIdx.y;
    int qt = c_qt[j], k0t = c_k0[j], KT = c_kt[j], ds = c_ds[j];
    int b = bh >> 3, h = bh & 7;
    int tid = threadIdx.x;
    int warp = tid >> 5, lane = tid & 31;

    const float* pb = paths + (size_t)(b * Tt) * (Hh*DEPTH) + h * DEPTH;
    const float* Bv = v + (size_t)b * Tt * Dd + h * 128;
    float* pqs = sm + AV_PQ;
    float* pka = sm + AV_PK;
    float* rsm = sm + AV_RS;

    // preload q-tile paths and the ENTIRE job's k-paths
    for (int idx = tid; idx < 64 * DEPTH; idx += 256)
        pqs[idx] = pb[(size_t)(qt * 64 + idx / DEPTH) * (Hh*DEPTH) + idx % DEPTH];
    int npk = KT * 32 * DEPTH;
    for (int idx = tid; idx < npk; idx += 256)
        pka[idx] = pb[(size_t)(k0t * 32 + idx / DEPTH) * (Hh*DEPTH) + idx % DEPTH];

    // prefetch V stages 0,1
    {
        uint32_t sB = sb + AV_BS * 4;
        #pragma unroll
        for (int s = 0; s < 2; s++) {
            int kb = (k0t + s) * 32;
            #pragma unroll
            for (int t = 0; t < 4; t++) {
                int c = tid + t * 256;
                int row = c >> 5, col = c & 31;
                cp16(sB + s * (32*BSTRIDE*4) + row * (BSTRIDE*4) + col * 16,
                     Bv + (size_t)(kb + row) * Dd + col * 4);
            }
            asm volatile("cp.async.commit_group;" ::: "memory");
        }
    }

    int wm = (warp & 1) * 32;
    int wn = (warp >> 1) * 32;
    int tg = lane >> 2, tk = lane & 3;
    float acc[2][4][4];
    #pragma unroll
    for (int mt = 0; mt < 2; mt++)
        #pragma unroll
        for (int nt = 0; nt < 4; nt++)
            #pragma unroll
            for (int i = 0; i < 4; i++) acc[mt][nt][i] = 0.f;
    float rsum[8];
    #pragma unroll
    for (int i = 0; i < 8; i++) rsum[i] = 0.f;

    __syncthreads();   // pqs / pka visible

    // e-tile 0 into As buffer 0
    {
        const float* pk = pka;
        float* Ab = sm + AV_AS;
        float k0v = pk[lane*5+0], k1v = pk[lane*5+1], k2v = pk[lane*5+2],
              k3v = pk[lane*5+3], k4v = pk[lane*5+4];
        float m0 = 1.f - k0v, m1 = 1.f - k1v, m2 = 1.f - k2v, m3 = 1.f - k3v, m4 = 1.f - k4v;
        int kglob = k0t * 32 + lane;
        #pragma unroll
        for (int jr = 0; jr < 8; jr++) {
            int row = warp * 8 + jr;
            const float* pq = pqs + row * 5;
            float p0 = pq[0], p1 = pq[1], p2 = pq[2], p3 = pq[3], p4 = pq[4];
            float prod = p0 * k0v + (1.f - p0) * m0;
            float s = prod;
            prod *= p1 * k1v + (1.f - p1) * m1; s += prod;
            prod *= p2 * k2v + (1.f - p2) * m2; s += prod;
            prod *= p3 * k3v + (1.f - p3) * m3; s += prod;
            prod *= p4 * k4v + (1.f - p4) * m4; s += prod;
            float ev = 0.f;
            if (kglob <= qt * 64 + row) ev = rnaf(expap(s * 0.2f));
            rsum[jr] += ev;
            Ab[row * ASTRIDE + lane] = ev;
        }
    }

    for (int it = 0; it < KT; it++) {
        asm volatile("cp.async.wait_group 1;" ::: "memory");
        __syncthreads();   // Bs[it%3] ready; e-tile(it) visible; As[(it+1)&1] free

        // prefetch V stage it+2
        int pf = it + 2;
        if (pf < KT) {
            uint32_t sB = sb + AV_BS * 4 + (pf % 3) * (32*BSTRIDE*4);
            int kb2 = (k0t + pf) * 32;
            #pragma unroll
            for (int t = 0; t < 4; t++) {
                int c = tid + t * 256;
                int row = c >> 5, col = c & 31;
                cp16(sB + row * (BSTRIDE*4) + col * 16,
                     Bv + (size_t)(kb2 + row) * Dd + col * 4);
            }
        }
        asm volatile("cp.async.commit_group;" ::: "memory");

        // MMA(it) from As[it&1]
        {
            const float* As = sm + AV_AS + (it & 1) * (64*ASTRIDE);
            const float* Bs = sm + AV_BS + (it % 3) * (32*BSTRIDE);
            #pragma unroll
            for (int kq = 0; kq < 32; kq += 8) {
                uint32_t af[2][4], bf[4][2];
                #pragma unroll
                for (int mt = 0; mt < 2; mt++) {
                    int m = wm + mt * 16 + tg;
                    af[mt][0] = __float_as_uint(As[m * ASTRIDE + kq + tk]);
                    af[mt][1] = __float_as_uint(As[(m + 8) * ASTRIDE + kq + tk]);
                    af[mt][2] = __float_as_uint(As[m * ASTRIDE + kq + tk + 4]);
                    af[mt][3] = __float_as_uint(As[(m + 8) * ASTRIDE + kq + tk + 4]);
                }
                #pragma unroll
                for (int nt = 0; nt < 4; nt++) {
                    int n = wn + nt * 8 + tg;
                    bf[nt][0] = __float_as_uint(Bs[(kq + tk) * BSTRIDE + n]);
                    bf[nt][1] = __float_as_uint(Bs[(kq + tk + 4) * BSTRIDE + n]);
                }
                #pragma unroll
                for (int mt = 0; mt < 2; mt++)
                    #pragma unroll
                    for (int nt = 0; nt < 4; nt++)
                        mma_tf32(acc[mt][nt], af[mt][0], af[mt][1], af[mt][2], af[mt][3],
                                 bf[nt][0], bf[nt][1]);
            }
        }

        // e-tile(it+1) into the other As buffer (overlaps MMA drain)
        if (it + 1 < KT) {
            const float* pk = pka + (it + 1) * (32*DEPTH);
            float* Ab = sm + AV_AS + ((it + 1) & 1) * (64*ASTRIDE);
            float k0v = pk[lane*5+0], k1v = pk[lane*5+1], k2v = pk[lane*5+2],
                  k3v = pk[lane*5+3], k4v = pk[lane*5+4];
            float m0 = 1.f - k0v, m1 = 1.f - k1v, m2 = 1.f - k2v, m3 = 1.f - k3v, m4 = 1.f - k4v;
            int kglob = (k0t + it + 1) * 32 + lane;
            #pragma unroll
            for (int jr = 0; jr < 8; jr++) {
                int row = warp * 8 + jr;
                const float* pq = pqs + row * 5;
                float p0 = pq[0], p1 = pq[1], p2 = pq[2], p3 = pq[3], p4 = pq[4];
                float prod = p0 * k0v + (1.f - p0) * m0;
                float s = prod;
                prod *= p1 * k1v + (1.f - p1) * m1; s += prod;
                prod *= p2 * k2v + (1.f - p2) * m2; s += prod;
                prod *= p3 * k3v + (1.f - p3) * m3; s += prod;
                prod *= p4 * k4v + (1.f - p4) * m4; s += prod;
                float ev = 0.f;
                if (kglob <= qt * 64 + row) ev = rnaf(expap(s * 0.2f));
                rsum[jr] += ev;
                Ab[row * ASTRIDE + lane] = ev;
            }
        }
    }

    #pragma unroll
    for (int jr = 0; jr < 8; jr++) {
        float s = rsum[jr];
        #pragma unroll
        for (int o = 16; o > 0; o >>= 1) s += __shfl_xor_sync(0xffffffffu, s, o);
        if (lane == 0) rsm[warp * 8 + jr] = s;
    }
    __syncthreads();

    if (qt < 8) {
        float* C = ctx + (size_t)b * Tt * Dd + h * 128;
        #pragma unroll
        for (int mt = 0; mt < 2; mt++) {
            int rl0 = wm + mt * 16 + tg;
            float i0 = 1.f / rsm[rl0], i1 = 1.f / rsm[rl0 + 8];
            #pragma unroll
            for (int nt = 0; nt < 4; nt++) {
                int r0 = qt * 64 + rl0;
                int cc = wn + nt * 8 + tk * 2;
                *(float2*)&C[(size_t)r0 * Dd + cc] =
                    make_float2(rnaf(acc[mt][nt][0] * i0), rnaf(acc[mt][nt][1] * i0));
                *(float2*)&C[(size_t)(r0 + 8) * Dd + cc] =
                    make_float2(rnaf(acc[mt][nt][2] * i1), rnaf(acc[mt][nt][3] * i1));
            }
        }
    } else {
        if (tid < 64) {
            float* rsp = rs + (size_t)ds * (Bb*Hh) * Tt + (size_t)bh * Tt + qt * 64;
            rsp[tid] = rsm[tid];
        }
        float* C = (ds ? ctx2 : ctx) + (size_t)b * Tt * Dd + h * 128;
        #pragma unroll
        for (int mt = 0; mt < 2; mt++) {
            #pragma unroll
            for (int nt = 0; nt < 4; nt++) {
                int r0 = qt * 64 + wm + mt * 16 + tg;
                int cc = wn + nt * 8 + tk * 2;
                *(float2*)&C[(size_t)r0 * Dd + cc]       = make_float2(acc[mt][nt][0], acc[mt][nt][1]);
                *(float2*)&C[(size_t)(r0 + 8) * Dd + cc] = make_float2(acc[mt][nt][2], acc[mt][nt][3]);
            }
        }
    }
}

// normalize + combine rows t>=512 only
__global__ __launch_bounds__(256) void ctx_norm(float4* __restrict__ ctx,
                                                const float4* __restrict__ ctx2,
                                                const float* __restrict__ rs) {
    int i = blockIdx.x * 256 + threadIdx.x;
    const int per_b = 512 * Dd / 4;
    if (i < Bb * per_b) {
        int b = i / per_b;
        int off = i - b * per_b;
        int t = 512 + off / (Dd / 4);
        int c4 = off % (Dd / 4);
        int bh = b * 8 + (c4 >> 5);
        size_t gi = (size_t)b * Tt * (Dd/4) + (size_t)t * (Dd/4) + c4;
        float denom = rs[(size_t)bh * Tt + t] + rs[(size_t)(Bb*Hh) * Tt + (size_t)bh * Tt + t];
        float inv = 1.f / denom;
        float4 xa = ctx[gi], xb = ctx2[gi];
        ctx[gi] = make_float4(rnaf((xa.x + xb.x) * inv), rnaf((xa.y + xb.y) * inv),
                              rnaf((xa.z + xb.z) * inv), rnaf((xa.w + xb.w) * inv));
    }
}

// ---------------------------------------------------------------------------
// paths GEMM split-K x4 (split-tf32) + sigmoid combine — unchanged from R8
// ---------------------------------------------------------------------------
#define PSTAGEF (2*64*36 + 2*32*136)
#define SMEM_PATHS (2*PSTAGEF*4)

__device__ __forceinline__ void paths_load(uint32_t sb, int s,
                                           const float* xh, const float* xl, int bm,
                                           const float* wh, const float* wl,
                                           int tid, int kt) {
    uint32_t base = sb + s * (PSTAGEF * 4);
    uint32_t xh_o = base;
    uint32_t xl_o = base + 64*36*4;
    uint32_t wh_o = xl_o + 64*36*4;
    uint32_t wl_o = wh_o + 32*136*4;
    int k0 = kt * 32;
    #pragma unroll
    for (int t = 0; t < 2; t++) {
        int c = tid + t * 256;
        int row = c >> 3, col = c & 7;
        size_t go = (size_t)(bm + row) * Dd + k0 + col * 4;
        uint32_t so = row * (36*4) + col * 16;
        cp16(xh_o + so, xh + go);
        cp16(xl_o + so, xl + go);
    }
    #pragma unroll
    for (int t = 0; t < 4; t++) {
        int c = tid + t * 256;
        int row = c >> 5, col = c & 31;
        size_t go = (size_t)(k0 + row) * 128 + col * 4;
        uint32_t so = row * (136*4) + col * 16;
        cp16(wh_o + so, wh + go);
        cp16(wl_o + so, wl + go);
    }
}

__global__ __launch_bounds__(256) void paths_gemm(const float* __restrict__ xh0,
                                                  const float* __restrict__ xl0,
                                                  const float* __restrict__ wh0,
                                                  const float* __restrict__ wl0,
                                                  float* __restrict__ pp) {
    extern __shared__ float sm[];
    uint32_t sb = smem_u32(sm);
    int tid = threadIdx.x;
    int warp = tid >> 5, lane = tid & 31;
    int wm = (warp & 1) * 32;
    int wn = (warp >> 1) * 32;
    int tg = lane >> 2, tk = lane & 3;
    int bm = blockIdx.x * 64;
    int sp = blockIdx.y;
    const float* xh = xh0 + sp * 256;
    const float* xl = xl0 + sp * 256;
    const float* wh = wh0 + (size_t)(sp * 256) * 128;
    const float* wl = wl0 + (size_t)(sp * 256) * 128;
    float* out = pp + (size_t)sp * NTOK * 128;
    const int KT = 8;

    float acc[2][4][4];
    #pragma unroll
    for (int mt = 0; mt < 2; mt++)
        #pragma unroll
        for (int nt = 0; nt < 4; nt++)
            #pragma unroll
            for (int i = 0; i < 4; i++) acc[mt][nt][i] = 0.f;

    paths_load(sb, 0, xh, xl, bm, wh, wl, tid, 0);
    asm volatile("cp.async.commit_group;" ::: "memory");

    for (int it = 0; it < KT; it++) {
        int pf = it + 1;
        if (pf < KT) {
            paths_load(sb, pf & 1, xh, xl, bm, wh, wl, tid, pf);
            asm volatile("cp.async.commit_group;" ::: "memory");
            asm volatile("cp.async.wait_group 1;" ::: "memory");
        } else {
            asm volatile("cp.async.wait_group 0;" ::: "memory");
        }
        __syncthreads();

        const float* Xh = sm + (it & 1) * PSTAGEF;
        const float* Xl = Xh + 64*36;
        const float* Wh = Xl + 64*36;
        const float* Wl = Wh + 32*136;
        #pragma unroll
        for (int kq = 0; kq < 32; kq += 8) {
            uint32_t ah[2][4], al[2][4], bh[4][2], bl[4][2];
            #pragma unroll
            for (int mt = 0; mt < 2; mt++) {
                int m = wm + mt * 16 + tg;
                ah[mt][0] = __float_as_uint(Xh[m * 36 + kq + tk]);
                ah[mt][1] = __float_as_uint(Xh[(m + 8) * 36 + kq + tk]);
                ah[mt][2] = __float_as_uint(Xh[m * 36 + kq + tk + 4]);
                ah[mt][3] = __float_as_uint(Xh[(m + 8) * 36 + kq + tk + 4]);
                al[mt][0] = __float_as_uint(Xl[m * 36 + kq + tk]);
                al[mt][1] = __float_as_uint(Xl[(m + 8) * 36 + kq + tk]);
                al[mt][2] = __float_as_uint(Xl[m * 36 + kq + tk + 4]);
                al[mt][3] = __float_as_uint(Xl[(m + 8) * 36 + kq + tk + 4]);
            }
            #pragma unroll
            for (int nt = 0; nt < 4; nt++) {
                int n = wn + nt * 8 + tg;
                bh[nt][0] = __float_as_uint(Wh[(kq + tk) * 136 + n]);
                bh[nt][1] = __float_as_uint(Wh[(kq + tk + 4) * 136 + n]);
                bl[nt][0] = __float_as_uint(Wl[(kq + tk) * 136 + n]);
                bl[nt][1] = __float_as_uint(Wl[(kq + tk + 4) * 136 + n]);
            }
            #pragma unroll
            for (int mt = 0; mt < 2; mt++)
                #pragma unroll
                for (int nt = 0; nt < 4; nt++) {
                    mma_tf32(acc[mt][nt], ah[mt][0], ah[mt][1], ah[mt][2], ah[mt][3],
                             bh[nt][0], bh[nt][1]);
                    mma_tf32(acc[mt][nt], ah[mt][0], ah[mt][1], ah[mt][2], ah[mt][3],
                             bl[nt][0], bl[nt][1]);
                    mma_tf32(acc[mt][nt], al[mt][0], al[mt][1], al[mt][2], al[mt][3],
                             bh[nt][0], bh[nt][1]);
                }
        }
        __syncthreads();
    }

    #pragma unroll
    for (int mt = 0; mt < 2; mt++) {
        #pragma unroll
        for (int nt = 0; nt < 4; nt++) {
            int cc = wn + nt * 8 + tk * 2;
            if (cc < Hh * DEPTH) {
                int r0 = bm + wm + mt * 16 + tg;
                out[(size_t)r0 * 128 + cc]           = acc[mt][nt][0];
                out[(size_t)r0 * 128 + cc + 1]       = acc[mt][nt][1];
                out[(size_t)(r0 + 8) * 128 + cc]     = acc[mt][nt][2];
                out[(size_t)(r0 + 8) * 128 + cc + 1] = acc[mt][nt][3];
            }
        }
    }
}

__global__ __launch_bounds__(256) void sigmoid_comb(const float* __restrict__ pp,
                                                    const float* __restrict__ bp,
                                                    float* __restrict__ paths) {
    int tok = blockIdx.x * 4 + (threadIdx.x >> 6);
    int c = threadIdx.x & 63;
    if (c < Hh * DEPTH) {
        float z = bp[c];
        #pragma unroll
        for (int s = 0; s < 4; s++)
            z += pp[(size_t)s * NTOK * 128 + (size_t)tok * 128 + c];
        paths[(size_t)tok * (Hh*DEPTH) + c] = 1.f / (1.f + expf(-z));
    }
}

// ---------------- merged staging ----------------
__global__ __launch_bounds__(256) void prep_all(const float4* __restrict__ x,
                                                float4* __restrict__ xh,
                                                float4* __restrict__ xl,
                                                const float4* __restrict__ Wv,
                                                float4* __restrict__ wvr,
                                                const float4* __restrict__ Wo,
                                                float4* __restrict__ wor,
                                                const float* __restrict__ Wp) {
    int i = blockIdx.x * 256 + threadIdx.x;
    if (i < NTOK*Dd/4) {
        float4 v = x[i];
        float4 h = make_float4(rnaf(v.x), rnaf(v.y), rnaf(v.z), rnaf(v.w));
        xh[i] = h;
        xl[i] = make_float4(rnaf(v.x - h.x), rnaf(v.y - h.y), rnaf(v.z - h.z), rnaf(v.w - h.w));
    }
    if (i < Dd*Dd/4) {
        float4 a = Wv[i], b = Wo[i];
        wvr[i] = make_float4(rnaf(a.x), rnaf(a.y), rnaf(a.z), rnaf(a.w));
        wor[i] = make_float4(rnaf(b.x), rnaf(b.y), rnaf(b.z), rnaf(b.w));
    }
    if (i < Dd*128) {
        int k = i >> 7, n = i & 127;
        float h = 0.f, l = 0.f;
        if (n < Hh * DEPTH) {
            float w = Wp[(size_t)k * (Hh * DEPTH) + n];
            h = rnaf(w);
            l = rnaf(w - h);
        }
        g_wph[i] = h;
        g_wpl[i] = l;
    }
}

// ---------------------------------------------------------------------------
extern "C" void kernel_launch(void* const* d_in, const int* in_sizes, int n_in,
                              void* d_out, int out_size) {
    const float* x  = (const float*)d_in[0];
    const float* Wp = (const float*)d_in[1];
    const float* bp = (const float*)d_in[2];
    const float* Wv = (const float*)d_in[3];
    const float* Wo = (const float*)d_in[4];
    float* out = (float*)d_out;

    float *paths, *xr, *xlo, *wph, *wpl, *pp, *wvr, *wor, *v, *ctx, *ctx2, *rs;
    cudaGetSymbolAddress((void**)&paths, g_paths);
    cudaGetSymbolAddress((void**)&xr,    g_xr);
    cudaGetSymbolAddress((void**)&xlo,   g_xlo);
    cudaGetSymbolAddress((void**)&wph,   g_wph);
    cudaGetSymbolAddress((void**)&wpl,   g_wpl);
    cudaGetSymbolAddress((void**)&pp,    g_pp);
    cudaGetSymbolAddress((void**)&wvr,   g_wvr);
    cudaGetSymbolAddress((void**)&wor,   g_wor);
    cudaGetSymbolAddress((void**)&v,     g_v);
    cudaGetSymbolAddress((void**)&ctx,   g_ctx);
    cudaGetSymbolAddress((void**)&ctx2,  g_ctx2);
    cudaGetSymbolAddress((void**)&rs,    g_rs);

    cudaFuncSetAttribute(gemm128,    cudaFuncAttributeMaxDynamicSharedMemorySize, SMEM_GEMM2);
    cudaFuncSetAttribute(av_fused,   cudaFuncAttributeMaxDynamicSharedMemorySize, SMEM_AV);
    cudaFuncSetAttribute(paths_gemm, cudaFuncAttributeMaxDynamicSharedMemorySize, SMEM_PATHS);

    // merged staging
    prep_all<<<(NTOK*Dd/4 + 255)/256, 256>>>((const float4*)x, (float4*)xr, (float4*)xlo,
                                             (const float4*)Wv, (float4*)wvr,
                                             (const float4*)Wo, (float4*)wor, Wp);

    // paths = sigmoid(x @ Wp + bp)
    paths_gemm<<<dim3(NTOK/64, 4), 256, SMEM_PATHS>>>(xr, xlo, wph, wpl, pp);
    sigmoid_comb<<<NTOK/4, 256>>>(pp, bp, paths);

    // V = x @ Wv (rounded store)
    gemm128<<<dim3(Dd/128, NTOK/128), 256, SMEM_GEMM2>>>(xr, wvr, v, Dd, Dd, 1);

    // fused sim+softmax+attn@V (pipelined)
    av_fused<<<dim3(24, Bb*Hh), 256, SMEM_AV>>>(paths, v, ctx, ctx2, rs);

    // combine split rows (t >= 512)
    ctx_norm<<<(Bb*512*Dd/4 + 255)/256, 256>>>((float4*)ctx, (const float4*)ctx2, rs);

    // out = ctx @ Wo
    gemm128<<<dim3(Dd/128, NTOK/128), 256, SMEM_GEMM2>>>(ctx, wor, out, Dd, Dd, 0);
}

// round 13
// speedup vs baseline: 1.0813x; 1.0366x over previous
#include <cuda_runtime.h>
#include <math.h>
#include <stdint.h>

#define Bb 2
#define Tt 1024
#define Dd 1024
#define Hh 8
#define DEPTH 5
#define NTOK (Bb*Tt)

// ---------------- scratch (device globals; allocation-free) ----------------
__device__ float g_paths[NTOK*Hh*DEPTH];      // [token][h*5+d]
__device__ float g_xr[NTOK*Dd];               // tf32(rna) hi part of x
__device__ float g_xlo[NTOK*Dd];              // tf32 lo residual of x
__device__ float g_wph[Dd*128];               // Wp hi, padded [k][128]
__device__ float g_wpl[Dd*128];               // Wp lo, padded [k][128]
__device__ float g_pp[4*NTOK*128];            // paths split-K partial logits
__device__ float g_v[NTOK*Dd];                // V = x@Wv, rounded
__device__ float g_ctx[NTOK*Dd];              // ctx (t<512 final; t>=512 partial slot0)
__device__ float g_ctx2[NTOK*Dd];             // ctx partial slot1 (t>=512 only)
__device__ float g_rs[2*Bb*Hh*Tt];            // row sums [slot][bh][t]

// av jobs (24/bh, longest first). qt<8 full (self-normalized); qt>=8 split.
__constant__ int c_qt[24] = {15,15,14,14,13,13,12,12,11,11,10,10, 9, 9, 8, 8, 7, 6, 5, 4, 3, 2, 1, 0};
__constant__ int c_k0[24] = { 0,16, 0,15, 0,14, 0,13, 0,12, 0,11, 0,10, 0, 9, 0, 0, 0, 0, 0, 0, 0, 0};
__constant__ int c_kt[24] = {16,16,15,15,14,14,13,13,12,12,11,11,10,10, 9, 9,16,14,12,10, 8, 6, 4, 2};
__constant__ int c_ds[24] = { 0, 1, 0, 1, 0, 1, 0, 1, 0, 1, 0, 1, 0, 1, 0, 1, 0, 0, 0, 0, 0, 0, 0, 0};

// ---------------- helpers ----------------
__device__ __forceinline__ float rnaf(float f) {
    uint32_t r; asm("cvt.rna.tf32.f32 %0, %1;" : "=r"(r) : "f"(f));
    return __uint_as_float(r);
}
__device__ __forceinline__ uint32_t smem_u32(const void* p) {
    uint32_t a;
    asm("{ .reg .u64 t; cvta.to.shared.u64 t, %1; cvt.u32.u64 %0, t; }" : "=r"(a) : "l"(p));
    return a;
}
__device__ __forceinline__ void cp16(uint32_t dst, const void* src) {
    asm volatile("cp.async.cg.shared.global [%0], [%1], 16;" :: "r"(dst), "l"(src));
}
__device__ __forceinline__ void cp4(uint32_t dst, const void* src) {
    asm volatile("cp.async.ca.shared.global [%0], [%1], 4;" :: "r"(dst), "l"(src));
}
__device__ __forceinline__ void mma_tf32(float c[4],
                                         uint32_t a0, uint32_t a1, uint32_t a2, uint32_t a3,
                                         uint32_t b0, uint32_t b1) {
    asm volatile("mma.sync.aligned.m16n8k8.row.col.f32.tf32.tf32.f32 "
                 "{%0,%1,%2,%3}, {%4,%5,%6,%7}, {%8,%9}, {%0,%1,%2,%3};"
                 : "+f"(c[0]), "+f"(c[1]), "+f"(c[2]), "+f"(c[3])
                 : "r"(a0), "r"(a1), "r"(a2), "r"(a3), "r"(b0), "r"(b1));
}
__device__ __forceinline__ float expap(float x) {   // e^x, x in (0,1], deg-7
    float p = 1.98412698e-4f;
    p = fmaf(p, x, 1.38888889e-3f);
    p = fmaf(p, x, 8.33333333e-3f);
    p = fmaf(p, x, 4.16666667e-2f);
    p = fmaf(p, x, 1.66666667e-1f);
    p = fmaf(p, x, 0.5f);
    p = fmaf(p, x, 1.0f);
    p = fmaf(p, x, 1.0f);
    return p;
}

#define ASTRIDE 36
#define BSTRIDE 136

// ---------------------------------------------------------------------------
// dense tf32 GEMM (R8 core): C[128,128] tile, 256 threads = 8 warps
// (2m x 4n, warp tile 64x32), BK=32, 3-stage cp.async.
// B is the RAW weight matrix [k][n]; rna rounding applied on B fragments
// in-register (bit-identical to pre-staged rounding).
// ---------------------------------------------------------------------------
#define A2FLOATS (128*ASTRIDE)                 // 4608
#define STAGEF2  (A2FLOATS + 32*BSTRIDE)       // 8960 floats
#define SMEM_GEMM2 (3*STAGEF2*4)               // 107520 B

__device__ __forceinline__ void load_stage2(uint32_t sb, int s,
                                            const float* A, int lda, int bm,
                                            const float* B, int ldb, int bn,
                                            int tid, int kt) {
    uint32_t sa = sb + s * (STAGEF2 * 4);
    uint32_t sB = sa + A2FLOATS * 4;
    int k0 = kt * 32;
    #pragma unroll
    for (int t = 0; t < 4; t++) {
        int c = tid + t * 256;
        int row = c >> 3, col = c & 7;
        cp16(sa + row * (ASTRIDE*4) + col * 16,
             A + (size_t)(bm + row) * lda + k0 + col * 4);
    }
    #pragma unroll
    for (int t = 0; t < 4; t++) {
        int c = tid + t * 256;
        int row = c >> 5, col = c & 31;
        cp16(sB + row * (BSTRIDE*4) + col * 16,
             B + (size_t)(k0 + row) * ldb + bn + col * 4);
    }
}

__global__ __launch_bounds__(256, 1) void gemm128(const float* __restrict__ A,
                                                  const float* __restrict__ Bw,
                                                  float* __restrict__ C,
                                                  int K, int N, int mode) {
    extern __shared__ float sm[];
    uint32_t sb = smem_u32(sm);
    int tid = threadIdx.x;
    int warp = tid >> 5, lane = tid & 31;
    int wm = (warp & 1) * 64;
    int wn = (warp >> 1) * 32;
    int tg = lane >> 2, tk = lane & 3;
    int bm = blockIdx.y * 128, bn = blockIdx.x * 128;
    int KT = K / 32;

    float acc[4][4][4];
    #pragma unroll
    for (int mt = 0; mt < 4; mt++)
        #pragma unroll
        for (int nt = 0; nt < 4; nt++)
            #pragma unroll
            for (int i = 0; i < 4; i++) acc[mt][nt][i] = 0.f;

    load_stage2(sb, 0, A, K, bm, Bw, N, bn, tid, 0);
    asm volatile("cp.async.commit_group;" ::: "memory");
    load_stage2(sb, 1, A, K, bm, Bw, N, bn, tid, 1);
    asm volatile("cp.async.commit_group;" ::: "memory");

    for (int it = 0; it < KT; it++) {
        asm volatile("cp.async.wait_group 1;" ::: "memory");
        __syncthreads();
        int pf = it + 2;
        if (pf < KT) load_stage2(sb, pf % 3, A, K, bm, Bw, N, bn, tid, pf);
        asm volatile("cp.async.commit_group;" ::: "memory");

        const float* As = sm + (it % 3) * STAGEF2;
        const float* Bs = As + A2FLOATS;
        #pragma unroll
        for (int kq = 0; kq < 32; kq += 8) {
            uint32_t af[4][4], bf[4][2];
            #pragma unroll
            for (int mt = 0; mt < 4; mt++) {
                int m = wm + mt * 16 + tg;
                af[mt][0] = __float_as_uint(As[m * ASTRIDE + kq + tk]);
                af[mt][1] = __float_as_uint(As[(m + 8) * ASTRIDE + kq + tk]);
                af[mt][2] = __float_as_uint(As[m * ASTRIDE + kq + tk + 4]);
                af[mt][3] = __float_as_uint(As[(m + 8) * ASTRIDE + kq + tk + 4]);
            }
            #pragma unroll
            for (int nt = 0; nt < 4; nt++) {
                int n = wn + nt * 8 + tg;
                bf[nt][0] = __float_as_uint(rnaf(Bs[(kq + tk) * BSTRIDE + n]));
                bf[nt][1] = __float_as_uint(rnaf(Bs[(kq + tk + 4) * BSTRIDE + n]));
            }
            #pragma unroll
            for (int mt = 0; mt < 4; mt++)
                #pragma unroll
                for (int nt = 0; nt < 4; nt++)
                    mma_tf32(acc[mt][nt], af[mt][0], af[mt][1], af[mt][2], af[mt][3],
                             bf[nt][0], bf[nt][1]);
        }
        __syncthreads();
    }

    #pragma unroll
    for (int mt = 0; mt < 4; mt++) {
        #pragma unroll
        for (int nt = 0; nt < 4; nt++) {
            int r0 = bm + wm + mt * 16 + tg;
            int cc = bn + wn + nt * 8 + tk * 2;
            float2 v0 = make_float2(acc[mt][nt][0], acc[mt][nt][1]);
            float2 v1 = make_float2(acc[mt][nt][2], acc[mt][nt][3]);
            if (mode == 1) {
                v0.x = rnaf(v0.x); v0.y = rnaf(v0.y);
                v1.x = rnaf(v1.x); v1.y = rnaf(v1.y);
            }
            *(float2*)&C[(size_t)r0 * N + cc]       = v0;
            *(float2*)&C[(size_t)(r0 + 8) * N + cc] = v1;
        }
    }
}

// ---------------------------------------------------------------------------
// Fused av, pipelined at 3 CTAs/SM: e-tile double-buffered (MMA(it) overlaps
// e-compute(it+1)); k-paths double-buffered via 4B cp.async in the same
// commit groups as V stages. smem 73.5KB. One __syncthreads per K-tile.
// smem (floats): As[2] 4608 | Bs[3] 13056 | pqs 320 | pks[2] 320 | rsm 64
// ---------------------------------------------------------------------------
#define AV_AS     0
#define AV_BS     (2*64*ASTRIDE)                   // 4608
#define AV_PQ     (AV_BS + 3*32*BSTRIDE)           // 17664
#define AV_PKS    (AV_PQ + 320)                    // 17984
#define AV_RS     (AV_PKS + 320)                   // 18304
#define AV_FLOATS (AV_RS + 64)                     // 18368
#define SMEM_AV   (AV_FLOATS*4)                    // 73472 B

__device__ __forceinline__ void av_prefetch(uint32_t sb, const float* Bv,
                                            const float* pb, int kt, int tid) {
    // V stage kt -> Bs[kt%3]
    uint32_t sB = sb + (AV_BS + (kt % 3) * (32*BSTRIDE)) * 4;
    int kb = kt * 32;
    #pragma unroll
    for (int t = 0; t < 4; t++) {
        int c = tid + t * 256;
        int row = c >> 5, col = c & 31;
        cp16(sB + row * (BSTRIDE*4) + col * 16,
             Bv + (size_t)(kb + row) * Dd + col * 4);
    }
    // k-paths stage kt -> pks[kt&1]  (160 floats, 4B each)
    if (tid < 32 * DEPTH) {
        int k = tid / DEPTH, d = tid - k * DEPTH;
        cp4(sb + (AV_PKS + (kt & 1) * 160 + tid) * 4,
            pb + (size_t)(kb + k) * (Hh*DEPTH) + d);
    }
}

__device__ __forceinline__ void av_etile(float* Ab, const float* pks, const float* pqs,
                                         int kglob0, int qmax, int warp, int lane,
                                         float rsum[8]) {
    float k0v = pks[lane*5+0], k1v = pks[lane*5+1], k2v = pks[lane*5+2],
          k3v = pks[lane*5+3], k4v = pks[lane*5+4];
    float m0 = 1.f - k0v, m1 = 1.f - k1v, m2 = 1.f - k2v, m3 = 1.f - k3v, m4 = 1.f - k4v;
    int kglob = kglob0 + lane;
    #pragma unroll
    for (int jr = 0; jr < 8; jr++) {
        int row = warp * 8 + jr;
        const float* pq = pqs + row * 5;
        float p0 = pq[0], p1 = pq[1], p2 = pq[2], p3 = pq[3], p4 = pq[4];
        float prod = p0 * k0v + (1.f - p0) * m0;
        float s = prod;
        prod *= p1 * k1v + (1.f - p1) * m1; s += prod;
        prod *= p2 * k2v + (1.f - p2) * m2; s += prod;
        prod *= p3 * k3v + (1.f - p3) * m3; s += prod;
        prod *= p4 * k4v + (1.f - p4) * m4; s += prod;
        float ev = 0.f;
        if (kglob <= qmax + row) ev = rnaf(expap(s * 0.2f));
        rsum[jr] += ev;
        Ab[row * ASTRIDE + lane] = ev;
    }
}

__global__ __launch_bounds__(256, 3) void av_fused(const float* __restrict__ paths,
                                                   const float* __restrict__ v,
                                                   float* __restrict__ ctx,
                                                   float* __restrict__ ctx2,
                                                   float* __restrict__ rs) {
    extern __shared__ float sm[];
    uint32_t sb = smem_u32(sm);
    int j = blockIdx.x, bh = blockIdx.y;
    int qt = c_qt[j], k0t = c_k0[j], KT = c_kt[j], ds = c_ds[j];
    int b = bh >> 3, h = bh & 7;
    int tid = threadIdx.x;
    int warp = tid >> 5, lane = tid & 31;

    const float* pb = paths + (size_t)(b * Tt) * (Hh*DEPTH) + h * DEPTH;
    const float* Bv = v + (size_t)b * Tt * Dd + h * 128;
    float* pqs = sm + AV_PQ;
    float* rsm = sm + AV_RS;
    int qmax = qt * 64;

    // prologue: stages 0,1 (V + k-paths), q-tile paths
    av_prefetch(sb, Bv, pb, k0t + 0, tid);
    asm volatile("cp.async.commit_group;" ::: "memory");
    av_prefetch(sb, Bv, pb, k0t + 1, tid);
    asm volatile("cp.async.commit_group;" ::: "memory");

    for (int idx = tid; idx < 64 * DEPTH; idx += 256)
        pqs[idx] = pb[(size_t)(qt * 64 + idx / DEPTH) * (Hh*DEPTH) + idx % DEPTH];

    int wm = (warp & 1) * 32;
    int wn = (warp >> 1) * 32;
    int tg = lane >> 2, tk = lane & 3;
    float acc[2][4][4];
    #pragma unroll
    for (int mt = 0; mt < 2; mt++)
        #pragma unroll
        for (int nt = 0; nt < 4; nt++)
            #pragma unroll
            for (int i = 0; i < 4; i++) acc[mt][nt][i] = 0.f;
    float rsum[8];
    #pragma unroll
    for (int i = 0; i < 8; i++) rsum[i] = 0.f;

    asm volatile("cp.async.wait_group 1;" ::: "memory");   // stage 0 landed
    __syncthreads();                                       // + pqs visible

    // e-tile 0 -> As[0]
    av_etile(sm + AV_AS + (k0t & 1) * 0 /*As[0]*/,
             sm + AV_PKS + (k0t & 1) * 160, pqs, (k0t + 0) * 32, qmax, warp, lane, rsum);
    // NOTE: As buffer parity tracked by local iteration (it), not global kt.

    for (int it = 0; it < KT; it++) {
        asm volatile("cp.async.wait_group 1;" ::: "memory");   // group(it) done
        __syncthreads();                                       // Bs(it) + As[it&1] visible

        int pf = it + 2;
        if (pf < KT) av_prefetch(sb, Bv, pb, k0t + pf, tid);
        asm volatile("cp.async.commit_group;" ::: "memory");

        // MMA(it)
        {
            const float* As = sm + AV_AS + (it & 1) * (64*ASTRIDE);
            const float* Bs = sm + AV_BS + ((k0t + it) % 3) * (32*BSTRIDE);
            #pragma unroll
            for (int kq = 0; kq < 32; kq += 8) {
                uint32_t af[2][4], bf[4][2];
                #pragma unroll
                for (int mt = 0; mt < 2; mt++) {
                    int m = wm + mt * 16 + tg;
                    af[mt][0] = __float_as_uint(As[m * ASTRIDE + kq + tk]);
                    af[mt][1] = __float_as_uint(As[(m + 8) * ASTRIDE + kq + tk]);
                    af[mt][2] = __float_as_uint(As[m * ASTRIDE + kq + tk + 4]);
                    af[mt][3] = __float_as_uint(As[(m + 8) * ASTRIDE + kq + tk + 4]);
                }
                #pragma unroll
                for (int nt = 0; nt < 4; nt++) {
                    int n = wn + nt * 8 + tg;
                    bf[nt][0] = __float_as_uint(Bs[(kq + tk) * BSTRIDE + n]);
                    bf[nt][1] = __float_as_uint(Bs[(kq + tk + 4) * BSTRIDE + n]);
                }
                #pragma unroll
                for (int mt = 0; mt < 2; mt++)
                    #pragma unroll
                    for (int nt = 0; nt < 4; nt++)
                        mma_tf32(acc[mt][nt], af[mt][0], af[mt][1], af[mt][2], af[mt][3],
                                 bf[nt][0], bf[nt][1]);
            }
        }

        // e-tile(it+1) into the other As buffer (overlaps MMA drain)
        if (it + 1 < KT) {
            asm volatile("cp.async.wait_group 1;" ::: "memory");   // group(it+1) done -> pks ready
            av_etile(sm + AV_AS + ((it + 1) & 1) * (64*ASTRIDE),
                     sm + AV_PKS + ((k0t + it + 1) & 1) * 160, pqs,
                     (k0t + it + 1) * 32, qmax, warp, lane, rsum);
        }
    }

    #pragma unroll
    for (int jr = 0; jr < 8; jr++) {
        float s = rsum[jr];
        #pragma unroll
        for (int o = 16; o > 0; o >>= 1) s += __shfl_xor_sync(0xffffffffu, s, o);
        if (lane == 0) rsm[warp * 8 + jr] = s;
    }
    __syncthreads();

    if (qt < 8) {
        float* C = ctx + (size_t)b * Tt * Dd + h * 128;
        #pragma unroll
        for (int mt = 0; mt < 2; mt++) {
            int rl0 = wm + mt * 16 + tg;
            float i0 = 1.f / rsm[rl0], i1 = 1.f / rsm[rl0 + 8];
            #pragma unroll
            for (int nt = 0; nt < 4; nt++) {
                int r0 = qt * 64 + rl0;
                int cc = wn + nt * 8 + tk * 2;
                *(float2*)&C[(size_t)r0 * Dd + cc] =
                    make_float2(rnaf(acc[mt][nt][0] * i0), rnaf(acc[mt][nt][1] * i0));
                *(float2*)&C[(size_t)(r0 + 8) * Dd + cc] =
                    make_float2(rnaf(acc[mt][nt][2] * i1), rnaf(acc[mt][nt][3] * i1));
            }
        }
    } else {
        if (tid < 64) {
            float* rsp = rs + (size_t)ds * (Bb*Hh) * Tt + (size_t)bh * Tt + qt * 64;
            rsp[tid] = rsm[tid];
        }
        float* C = (ds ? ctx2 : ctx) + (size_t)b * Tt * Dd + h * 128;
        #pragma unroll
        for (int mt = 0; mt < 2; mt++) {
            #pragma unroll
            for (int nt = 0; nt < 4; nt++) {
                int r0 = qt * 64 + wm + mt * 16 + tg;
                int cc = wn + nt * 8 + tk * 2;
                *(float2*)&C[(size_t)r0 * Dd + cc]       = make_float2(acc[mt][nt][0], acc[mt][nt][1]);
                *(float2*)&C[(size_t)(r0 + 8) * Dd + cc] = make_float2(acc[mt][nt][2], acc[mt][nt][3]);
            }
        }
    }
}

// normalize + combine rows t>=512 only
__global__ __launch_bounds__(256) void ctx_norm(float4* __restrict__ ctx,
                                                const float4* __restrict__ ctx2,
                                                const float* __restrict__ rs) {
    int i = blockIdx.x * 256 + threadIdx.x;
    const int per_b = 512 * Dd / 4;
    if (i < Bb * per_b) {
        int b = i / per_b;
        int off = i - b * per_b;
        int t = 512 + off / (Dd / 4);
        int c4 = off % (Dd / 4);
        int bh = b * 8 + (c4 >> 5);
        size_t gi = (size_t)b * Tt * (Dd/4) + (size_t)t * (Dd/4) + c4;
        float denom = rs[(size_t)bh * Tt + t] + rs[(size_t)(Bb*Hh) * Tt + (size_t)bh * Tt + t];
        float inv = 1.f / denom;
        float4 xa = ctx[gi], xb = ctx2[gi];
        ctx[gi] = make_float4(rnaf((xa.x + xb.x) * inv), rnaf((xa.y + xb.y) * inv),
                              rnaf((xa.z + xb.z) * inv), rnaf((xa.w + xb.w) * inv));
    }
}

// ---------------------------------------------------------------------------
// paths GEMM split-K x4 (split-tf32) + sigmoid combine — unchanged from R8
// ---------------------------------------------------------------------------
#define PSTAGEF (2*64*36 + 2*32*136)
#define SMEM_PATHS (2*PSTAGEF*4)

__device__ __forceinline__ void paths_load(uint32_t sb, int s,
                                           const float* xh, const float* xl, int bm,
                                           const float* wh, const float* wl,
                                           int tid, int kt) {
    uint32_t base = sb + s * (PSTAGEF * 4);
    uint32_t xh_o = base;
    uint32_t xl_o = base + 64*36*4;
    uint32_t wh_o = xl_o + 64*36*4;
    uint32_t wl_o = wh_o + 32*136*4;
    int k0 = kt * 32;
    #pragma unroll
    for (int t = 0; t < 2; t++) {
        int c = tid + t * 256;
        int row = c >> 3, col = c & 7;
        size_t go = (size_t)(bm + row) * Dd + k0 + col * 4;
        uint32_t so = row * (36*4) + col * 16;
        cp16(xh_o + so, xh + go);
        cp16(xl_o + so, xl + go);
    }
    #pragma unroll
    for (int t = 0; t < 4; t++) {
        int c = tid + t * 256;
        int row = c >> 5, col = c & 31;
        size_t go = (size_t)(k0 + row) * 128 + col * 4;
        uint32_t so = row * (136*4) + col * 16;
        cp16(wh_o + so, wh + go);
        cp16(wl_o + so, wl + go);
    }
}

__global__ __launch_bounds__(256) void paths_gemm(const float* __restrict__ xh0,
                                                  const float* __restrict__ xl0,
                                                  const float* __restrict__ wh0,
                                                  const float* __restrict__ wl0,
                                                  float* __restrict__ pp) {
    extern __shared__ float sm[];
    uint32_t sb = smem_u32(sm);
    int tid = threadIdx.x;
    int warp = tid >> 5, lane = tid & 31;
    int wm = (warp & 1) * 32;
    int wn = (warp >> 1) * 32;
    int tg = lane >> 2, tk = lane & 3;
    int bm = blockIdx.x * 64;
    int sp = blockIdx.y;
    const float* xh = xh0 + sp * 256;
    const float* xl = xl0 + sp * 256;
    const float* wh = wh0 + (size_t)(sp * 256) * 128;
    const float* wl = wl0 + (size_t)(sp * 256) * 128;
    float* out = pp + (size_t)sp * NTOK * 128;
    const int KT = 8;

    float acc[2][4][4];
    #pragma unroll
    for (int mt = 0; mt < 2; mt++)
        #pragma unroll
        for (int nt = 0; nt < 4; nt++)
            #pragma unroll
            for (int i = 0; i < 4; i++) acc[mt][nt][i] = 0.f;

    paths_load(sb, 0, xh, xl, bm, wh, wl, tid, 0);
    asm volatile("cp.async.commit_group;" ::: "memory");

    for (int it = 0; it < KT; it++) {
        int pf = it + 1;
        if (pf < KT) {
            paths_load(sb, pf & 1, xh, xl, bm, wh, wl, tid, pf);
            asm volatile("cp.async.commit_group;" ::: "memory");
            asm volatile("cp.async.wait_group 1;" ::: "memory");
        } else {
            asm volatile("cp.async.wait_group 0;" ::: "memory");
        }
        __syncthreads();

        const float* Xh = sm + (it & 1) * PSTAGEF;
        const float* Xl = Xh + 64*36;
        const float* Wh = Xl + 64*36;
        const float* Wl = Wh + 32*136;
        #pragma unroll
        for (int kq = 0; kq < 32; kq += 8) {
            uint32_t ah[2][4], al[2][4], bh[4][2], bl[4][2];
            #pragma unroll
            for (int mt = 0; mt < 2; mt++) {
                int m = wm + mt * 16 + tg;
                ah[mt][0] = __float_as_uint(Xh[m * 36 + kq + tk]);
                ah[mt][1] = __float_as_uint(Xh[(m + 8) * 36 + kq + tk]);
                ah[mt][2] = __float_as_uint(Xh[m * 36 + kq + tk + 4]);
                ah[mt][3] = __float_as_uint(Xh[(m + 8) * 36 + kq + tk + 4]);
                al[mt][0] = __float_as_uint(Xl[m * 36 + kq + tk]);
                al[mt][1] = __float_as_uint(Xl[(m + 8) * 36 + kq + tk]);
                al[mt][2] = __float_as_uint(Xl[m * 36 + kq + tk + 4]);
                al[mt][3] = __float_as_uint(Xl[(m + 8) * 36 + kq + tk + 4]);
            }
            #pragma unroll
            for (int nt = 0; nt < 4; nt++) {
                int n = wn + nt * 8 + tg;
                bh[nt][0] = __float_as_uint(Wh[(kq + tk) * 136 + n]);
                bh[nt][1] = __float_as_uint(Wh[(kq + tk + 4) * 136 + n]);
                bl[nt][0] = __float_as_uint(Wl[(kq + tk) * 136 + n]);
                bl[nt][1] = __float_as_uint(Wl[(kq + tk + 4) * 136 + n]);
            }
            #pragma unroll
            for (int mt = 0; mt < 2; mt++)
                #pragma unroll
                for (int nt = 0; nt < 4; nt++) {
                    mma_tf32(acc[mt][nt], ah[mt][0], ah[mt][1], ah[mt][2], ah[mt][3],
                             bh[nt][0], bh[nt][1]);
                    mma_tf32(acc[mt][nt], ah[mt][0], ah[mt][1], ah[mt][2], ah[mt][3],
                             bl[nt][0], bl[nt][1]);
                    mma_tf32(acc[mt][nt], al[mt][0], al[mt][1], al[mt][2], al[mt][3],
                             bh[nt][0], bh[nt][1]);
                }
        }
        __syncthreads();
    }

    #pragma unroll
    for (int mt = 0; mt < 2; mt++) {
        #pragma unroll
        for (int nt = 0; nt < 4; nt++) {
            int cc = wn + nt * 8 + tk * 2;
            if (cc < Hh * DEPTH) {
                int r0 = bm + wm + mt * 16 + tg;
                out[(size_t)r0 * 128 + cc]           = acc[mt][nt][0];
                out[(size_t)r0 * 128 + cc + 1]       = acc[mt][nt][1];
                out[(size_t)(r0 + 8) * 128 + cc]     = acc[mt][nt][2];
                out[(size_t)(r0 + 8) * 128 + cc + 1] = acc[mt][nt][3];
            }
        }
    }
}

__global__ __launch_bounds__(256) void sigmoid_comb(const float* __restrict__ pp,
                                                    const float* __restrict__ bp,
                                                    float* __restrict__ paths) {
    int tok = blockIdx.x * 4 + (threadIdx.x >> 6);
    int c = threadIdx.x & 63;
    if (c < Hh * DEPTH) {
        float z = bp[c];
        #pragma unroll
        for (int s = 0; s < 4; s++)
            z += pp[(size_t)s * NTOK * 128 + (size_t)tok * 128 + c];
        paths[(size_t)tok * (Hh*DEPTH) + c] = 1.f / (1.f + expf(-z));
    }
}

// ---------------- staging: x split + Wp pad only (weights read raw) --------
__global__ __launch_bounds__(256) void prep_all(const float4* __restrict__ x,
                                                float4* __restrict__ xh,
                                                float4* __restrict__ xl,
                                                const float* __restrict__ Wp) {
    int i = blockIdx.x * 256 + threadIdx.x;
    if (i < NTOK*Dd/4) {
        float4 v = x[i];
        float4 h = make_float4(rnaf(v.x), rnaf(v.y), rnaf(v.z), rnaf(v.w));
        xh[i] = h;
        xl[i] = make_float4(rnaf(v.x - h.x), rnaf(v.y - h.y), rnaf(v.z - h.z), rnaf(v.w - h.w));
    }
    if (i < Dd*128) {
        int k = i >> 7, n = i & 127;
        float h = 0.f, l = 0.f;
        if (n < Hh * DEPTH) {
            float w = Wp[(size_t)k * (Hh * DEPTH) + n];
            h = rnaf(w);
            l = rnaf(w - h);
        }
        g_wph[i] = h;
        g_wpl[i] = l;
    }
}

// ---------------------------------------------------------------------------
extern "C" void kernel_launch(void* const* d_in, const int* in_sizes, int n_in,
                              void* d_out, int out_size) {
    const float* x  = (const float*)d_in[0];
    const float* Wp = (const float*)d_in[1];
    const float* bp = (const float*)d_in[2];
    const float* Wv = (const float*)d_in[3];
    const float* Wo = (const float*)d_in[4];
    float* out = (float*)d_out;

    float *paths, *xr, *xlo, *wph, *wpl, *pp, *v, *ctx, *ctx2, *rs;
    cudaGetSymbolAddress((void**)&paths, g_paths);
    cudaGetSymbolAddress((void**)&xr,    g_xr);
    cudaGetSymbolAddress((void**)&xlo,   g_xlo);
    cudaGetSymbolAddress((void**)&wph,   g_wph);
    cudaGetSymbolAddress((void**)&wpl,   g_wpl);
    cudaGetSymbolAddress((void**)&pp,    g_pp);
    cudaGetSymbolAddress((void**)&v,     g_v);
    cudaGetSymbolAddress((void**)&ctx,   g_ctx);
    cudaGetSymbolAddress((void**)&ctx2,  g_ctx2);
    cudaGetSymbolAddress((void**)&rs,    g_rs);

    cudaFuncSetAttribute(gemm128,    cudaFuncAttributeMaxDynamicSharedMemorySize, SMEM_GEMM2);
    cudaFuncSetAttribute(av_fused,   cudaFuncAttributeMaxDynamicSharedMemorySize, SMEM_AV);
    cudaFuncSetAttribute(paths_gemm, cudaFuncAttributeMaxDynamicSharedMemorySize, SMEM_PATHS);

    // staging (x split + Wp pad; weights consumed raw by gemm128)
    prep_all<<<(NTOK*Dd/4 + 255)/256, 256>>>((const float4*)x, (float4*)xr, (float4*)xlo, Wp);

    // paths = sigmoid(x @ Wp + bp)
    paths_gemm<<<dim3(NTOK/64, 4), 256, SMEM_PATHS>>>(xr, xlo, wph, wpl, pp);
    sigmoid_comb<<<NTOK/4, 256>>>(pp, bp, paths);

    // V = x @ Wv (rounded store; Wv rounded in-register)
    gemm128<<<dim3(Dd/128, NTOK/128), 256, SMEM_GEMM2>>>(xr, Wv, v, Dd, Dd, 1);

    // fused sim+softmax+attn@V (pipelined, 3 CTAs/SM)
    av_fused<<<dim3(24, Bb*Hh), 256, SMEM_AV>>>(paths, v, ctx, ctx2, rs);

    // combine split rows (t >= 512)
    ctx_norm<<<(Bb*512*Dd/4 + 255)/256, 256>>>((float4*)ctx, (const float4*)ctx2, rs);

    // out = ctx @ Wo (Wo rounded in-register)
    gemm128<<<dim3(Dd/128, NTOK/128), 256, SMEM_GEMM2>>>(ctx, Wo, out, Dd, Dd, 0);
}

// round 14
// speedup vs baseline: 1.0868x; 1.0051x over previous
#include <cuda_runtime.h>
#include <math.h>
#include <stdint.h>

#define Bb 2
#define Tt 1024
#define Dd 1024
#define Hh 8
#define DEPTH 5
#define NTOK (Bb*Tt)

// ---------------- scratch (device globals; allocation-free) ----------------
__device__ float g_paths[NTOK*Hh*DEPTH];      // [token][h*5+d]
__device__ float g_xr[NTOK*Dd];               // tf32(rna) hi part of x
__device__ float g_xlo[NTOK*Dd];              // tf32 lo residual of x
__device__ float g_wph[Dd*128];               // Wp hi, padded [k][128]
__device__ float g_wpl[Dd*128];               // Wp lo, padded [k][128]
__device__ float g_pp[4*NTOK*40];             // paths split-K partials (compact)
__device__ float g_v[NTOK*Dd];                // V = x@Wv, rounded
__device__ float g_ctx[NTOK*Dd];              // ctx (t<512 final; t>=512 partial slot0)
__device__ float g_ctx2[NTOK*Dd];             // ctx partial slot1 (t>=512 only)
__device__ float g_rs[2*Bb*Hh*Tt];            // row sums [slot][bh][t]

// av jobs (24/bh, longest first). qt<8 full (self-normalized); qt>=8 split.
__constant__ int c_qt[24] = {15,15,14,14,13,13,12,12,11,11,10,10, 9, 9, 8, 8, 7, 6, 5, 4, 3, 2, 1, 0};
__constant__ int c_k0[24] = { 0,16, 0,15, 0,14, 0,13, 0,12, 0,11, 0,10, 0, 9, 0, 0, 0, 0, 0, 0, 0, 0};
__constant__ int c_kt[24] = {16,16,15,15,14,14,13,13,12,12,11,11,10,10, 9, 9,16,14,12,10, 8, 6, 4, 2};
__constant__ int c_ds[24] = { 0, 1, 0, 1, 0, 1, 0, 1, 0, 1, 0, 1, 0, 1, 0, 1, 0, 0, 0, 0, 0, 0, 0, 0};

// ---------------- helpers ----------------
__device__ __forceinline__ float rnaf(float f) {
    uint32_t r; asm("cvt.rna.tf32.f32 %0, %1;" : "=r"(r) : "f"(f));
    return __uint_as_float(r);
}
__device__ __forceinline__ uint32_t smem_u32(const void* p) {
    uint32_t a;
    asm("{ .reg .u64 t; cvta.to.shared.u64 t, %1; cvt.u32.u64 %0, t; }" : "=r"(a) : "l"(p));
    return a;
}
__device__ __forceinline__ void cp16(uint32_t dst, const void* src) {
    asm volatile("cp.async.cg.shared.global [%0], [%1], 16;" :: "r"(dst), "l"(src));
}
__device__ __forceinline__ void cp4(uint32_t dst, const void* src) {
    asm volatile("cp.async.ca.shared.global [%0], [%1], 4;" :: "r"(dst), "l"(src));
}
__device__ __forceinline__ void mma_tf32(float c[4],
                                         uint32_t a0, uint32_t a1, uint32_t a2, uint32_t a3,
                                         uint32_t b0, uint32_t b1) {
    asm volatile("mma.sync.aligned.m16n8k8.row.col.f32.tf32.tf32.f32 "
                 "{%0,%1,%2,%3}, {%4,%5,%6,%7}, {%8,%9}, {%0,%1,%2,%3};"
                 : "+f"(c[0]), "+f"(c[1]), "+f"(c[2]), "+f"(c[3])
                 : "r"(a0), "r"(a1), "r"(a2), "r"(a3), "r"(b0), "r"(b1));
}
__device__ __forceinline__ float expap(float x) {   // e^x, x in (0,1], deg-7
    float p = 1.98412698e-4f;
    p = fmaf(p, x, 1.38888889e-3f);
    p = fmaf(p, x, 8.33333333e-3f);
    p = fmaf(p, x, 4.16666667e-2f);
    p = fmaf(p, x, 1.66666667e-1f);
    p = fmaf(p, x, 0.5f);
    p = fmaf(p, x, 1.0f);
    p = fmaf(p, x, 1.0f);
    return p;
}

#define ASTRIDE 36
#define BSTRIDE 136

// ---------------------------------------------------------------------------
// dense tf32 GEMM tile (R8 core): C[128,128], 256 threads = 8 warps
// (2m x 4n, warp tile 64x32), BK=32, 3-stage cp.async. B raw, rna on frags.
// ---------------------------------------------------------------------------
#define A2FLOATS (128*ASTRIDE)                 // 4608
#define STAGEF2  (A2FLOATS + 32*BSTRIDE)       // 8960 floats
#define SMEM_GEMM2 (3*STAGEF2*4)               // 107520 B

__device__ __forceinline__ void load_stage2(uint32_t sb, int s,
                                            const float* A, int lda, int bm,
                                            const float* B, int ldb, int bn,
                                            int tid, int kt) {
    uint32_t sa = sb + s * (STAGEF2 * 4);
    uint32_t sB = sa + A2FLOATS * 4;
    int k0 = kt * 32;
    #pragma unroll
    for (int t = 0; t < 4; t++) {
        int c = tid + t * 256;
        int row = c >> 3, col = c & 7;
        cp16(sa + row * (ASTRIDE*4) + col * 16,
             A + (size_t)(bm + row) * lda + k0 + col * 4);
    }
    #pragma unroll
    for (int t = 0; t < 4; t++) {
        int c = tid + t * 256;
        int row = c >> 5, col = c & 31;
        cp16(sB + row * (BSTRIDE*4) + col * 16,
             B + (size_t)(k0 + row) * ldb + bn + col * 4);
    }
}

__device__ void dense_tile(const float* __restrict__ A, const float* __restrict__ Bw,
                           float* __restrict__ C, int K, int N, int mode,
                           int bm, int bn, float* sm, uint32_t sb) {
    int tid = threadIdx.x;
    int warp = tid >> 5, lane = tid & 31;
    int wm = (warp & 1) * 64;
    int wn = (warp >> 1) * 32;
    int tg = lane >> 2, tk = lane & 3;
    int KT = K / 32;

    float acc[4][4][4];
    #pragma unroll
    for (int mt = 0; mt < 4; mt++)
        #pragma unroll
        for (int nt = 0; nt < 4; nt++)
            #pragma unroll
            for (int i = 0; i < 4; i++) acc[mt][nt][i] = 0.f;

    load_stage2(sb, 0, A, K, bm, Bw, N, bn, tid, 0);
    asm volatile("cp.async.commit_group;" ::: "memory");
    load_stage2(sb, 1, A, K, bm, Bw, N, bn, tid, 1);
    asm volatile("cp.async.commit_group;" ::: "memory");

    for (int it = 0; it < KT; it++) {
        asm volatile("cp.async.wait_group 1;" ::: "memory");
        __syncthreads();
        int pf = it + 2;
        if (pf < KT) load_stage2(sb, pf % 3, A, K, bm, Bw, N, bn, tid, pf);
        asm volatile("cp.async.commit_group;" ::: "memory");

        const float* As = sm + (it % 3) * STAGEF2;
        const float* Bs = As + A2FLOATS;
        #pragma unroll
        for (int kq = 0; kq < 32; kq += 8) {
            uint32_t af[4][4], bf[4][2];
            #pragma unroll
            for (int mt = 0; mt < 4; mt++) {
                int m = wm + mt * 16 + tg;
                af[mt][0] = __float_as_uint(As[m * ASTRIDE + kq + tk]);
                af[mt][1] = __float_as_uint(As[(m + 8) * ASTRIDE + kq + tk]);
                af[mt][2] = __float_as_uint(As[m * ASTRIDE + kq + tk + 4]);
                af[mt][3] = __float_as_uint(As[(m + 8) * ASTRIDE + kq + tk + 4]);
            }
            #pragma unroll
            for (int nt = 0; nt < 4; nt++) {
                int n = wn + nt * 8 + tg;
                bf[nt][0] = __float_as_uint(rnaf(Bs[(kq + tk) * BSTRIDE + n]));
                bf[nt][1] = __float_as_uint(rnaf(Bs[(kq + tk + 4) * BSTRIDE + n]));
            }
            #pragma unroll
            for (int mt = 0; mt < 4; mt++)
                #pragma unroll
                for (int nt = 0; nt < 4; nt++)
                    mma_tf32(acc[mt][nt], af[mt][0], af[mt][1], af[mt][2], af[mt][3],
                             bf[nt][0], bf[nt][1]);
        }
        __syncthreads();
    }

    #pragma unroll
    for (int mt = 0; mt < 4; mt++) {
        #pragma unroll
        for (int nt = 0; nt < 4; nt++) {
            int r0 = bm + wm + mt * 16 + tg;
            int cc = bn + wn + nt * 8 + tk * 2;
            float2 v0 = make_float2(acc[mt][nt][0], acc[mt][nt][1]);
            float2 v1 = make_float2(acc[mt][nt][2], acc[mt][nt][3]);
            if (mode == 1) {
                v0.x = rnaf(v0.x); v0.y = rnaf(v0.y);
                v1.x = rnaf(v1.x); v1.y = rnaf(v1.y);
            }
            *(float2*)&C[(size_t)r0 * N + cc]       = v0;
            *(float2*)&C[(size_t)(r0 + 8) * N + cc] = v1;
        }
    }
}

// ---------------------------------------------------------------------------
// paths GEMM tile (split-tf32, split-K x4), compact pp output [tok][40]
// ---------------------------------------------------------------------------
#define PSTAGEF (2*64*36 + 2*32*136)
#define SMEM_PATHS (2*PSTAGEF*4)

__device__ __forceinline__ void paths_load(uint32_t sb, int s,
                                           const float* xh, const float* xl, int bm,
                                           const float* wh, const float* wl,
                                           int tid, int kt) {
    uint32_t base = sb + s * (PSTAGEF * 4);
    uint32_t xh_o = base;
    uint32_t xl_o = base + 64*36*4;
    uint32_t wh_o = xl_o + 64*36*4;
    uint32_t wl_o = wh_o + 32*136*4;
    int k0 = kt * 32;
    #pragma unroll
    for (int t = 0; t < 2; t++) {
        int c = tid + t * 256;
        int row = c >> 3, col = c & 7;
        size_t go = (size_t)(bm + row) * Dd + k0 + col * 4;
        uint32_t so = row * (36*4) + col * 16;
        cp16(xh_o + so, xh + go);
        cp16(xl_o + so, xl + go);
    }
    #pragma unroll
    for (int t = 0; t < 4; t++) {
        int c = tid + t * 256;
        int row = c >> 5, col = c & 31;
        size_t go = (size_t)(k0 + row) * 128 + col * 4;
        uint32_t so = row * (136*4) + col * 16;
        cp16(wh_o + so, wh + go);
        cp16(wl_o + so, wl + go);
    }
}

__device__ void paths_tile(const float* __restrict__ xh0, const float* __restrict__ xl0,
                           const float* __restrict__ wh0, const float* __restrict__ wl0,
                           float* __restrict__ pp, int bm, int sp,
                           float* sm, uint32_t sb) {
    int tid = threadIdx.x;
    int warp = tid >> 5, lane = tid & 31;
    int wm = (warp & 1) * 32;
    int wn = (warp >> 1) * 32;
    int tg = lane >> 2, tk = lane & 3;
    const float* xh = xh0 + sp * 256;
    const float* xl = xl0 + sp * 256;
    const float* wh = wh0 + (size_t)(sp * 256) * 128;
    const float* wl = wl0 + (size_t)(sp * 256) * 128;
    float* out = pp + (size_t)sp * NTOK * 40;
    const int KT = 8;

    float acc[2][4][4];
    #pragma unroll
    for (int mt = 0; mt < 2; mt++)
        #pragma unroll
        for (int nt = 0; nt < 4; nt++)
            #pragma unroll
            for (int i = 0; i < 4; i++) acc[mt][nt][i] = 0.f;

    paths_load(sb, 0, xh, xl, bm, wh, wl, tid, 0);
    asm volatile("cp.async.commit_group;" ::: "memory");

    for (int it = 0; it < KT; it++) {
        int pf = it + 1;
        if (pf < KT) {
            paths_load(sb, pf & 1, xh, xl, bm, wh, wl, tid, pf);
            asm volatile("cp.async.commit_group;" ::: "memory");
            asm volatile("cp.async.wait_group 1;" ::: "memory");
        } else {
            asm volatile("cp.async.wait_group 0;" ::: "memory");
        }
        __syncthreads();

        const float* Xh = sm + (it & 1) * PSTAGEF;
        const float* Xl = Xh + 64*36;
        const float* Wh = Xl + 64*36;
        const float* Wl = Wh + 32*136;
        #pragma unroll
        for (int kq = 0; kq < 32; kq += 8) {
            uint32_t ah[2][4], al[2][4], bh[4][2], bl[4][2];
            #pragma unroll
            for (int mt = 0; mt < 2; mt++) {
                int m = wm + mt * 16 + tg;
                ah[mt][0] = __float_as_uint(Xh[m * 36 + kq + tk]);
                ah[mt][1] = __float_as_uint(Xh[(m + 8) * 36 + kq + tk]);
                ah[mt][2] = __float_as_uint(Xh[m * 36 + kq + tk + 4]);
                ah[mt][3] = __float_as_uint(Xh[(m + 8) * 36 + kq + tk + 4]);
                al[mt][0] = __float_as_uint(Xl[m * 36 + kq + tk]);
                al[mt][1] = __float_as_uint(Xl[(m + 8) * 36 + kq + tk]);
                al[mt][2] = __float_as_uint(Xl[m * 36 + kq + tk + 4]);
                al[mt][3] = __float_as_uint(Xl[(m + 8) * 36 + kq + tk + 4]);
            }
            #pragma unroll
            for (int nt = 0; nt < 4; nt++) {
                int n = wn + nt * 8 + tg;
                bh[nt][0] = __float_as_uint(Wh[(kq + tk) * 136 + n]);
                bh[nt][1] = __float_as_uint(Wh[(kq + tk + 4) * 136 + n]);
                bl[nt][0] = __float_as_uint(Wl[(kq + tk) * 136 + n]);
                bl[nt][1] = __float_as_uint(Wl[(kq + tk + 4) * 136 + n]);
            }
            #pragma unroll
            for (int mt = 0; mt < 2; mt++)
                #pragma unroll
                for (int nt = 0; nt < 4; nt++) {
                    mma_tf32(acc[mt][nt], ah[mt][0], ah[mt][1], ah[mt][2], ah[mt][3],
                             bh[nt][0], bh[nt][1]);
                    mma_tf32(acc[mt][nt], ah[mt][0], ah[mt][1], ah[mt][2], ah[mt][3],
                             bl[nt][0], bl[nt][1]);
                    mma_tf32(acc[mt][nt], al[mt][0], al[mt][1], al[mt][2], al[mt][3],
                             bh[nt][0], bh[nt][1]);
                }
        }
        __syncthreads();
    }

    #pragma unroll
    for (int mt = 0; mt < 2; mt++) {
        #pragma unroll
        for (int nt = 0; nt < 4; nt++) {
            int cc = wn + nt * 8 + tk * 2;
            if (cc < Hh * DEPTH) {
                int r0 = bm + wm + mt * 16 + tg;
                out[(size_t)r0 * 40 + cc]           = acc[mt][nt][0];
                out[(size_t)r0 * 40 + cc + 1]       = acc[mt][nt][1];
                out[(size_t)(r0 + 8) * 40 + cc]     = acc[mt][nt][2];
                out[(size_t)(r0 + 8) * 40 + cc + 1] = acc[mt][nt][3];
            }
        }
    }
}

// fat kernel: bid<128 -> V-gemm tile; bid>=128 -> paths tile. grid 256.
__global__ __launch_bounds__(256, 1) void fat_vp(const float* __restrict__ xr,
                                                 const float* __restrict__ xlo,
                                                 const float* __restrict__ Wv,
                                                 float* __restrict__ v,
                                                 const float* __restrict__ wph,
                                                 const float* __restrict__ wpl,
                                                 float* __restrict__ pp) {
    extern __shared__ float sm[];
    uint32_t sb = smem_u32(sm);
    int bid = blockIdx.x;
    if (bid < 128) {
        dense_tile(xr, Wv, v, Dd, Dd, 1, (bid >> 3) * 128, (bid & 7) * 128, sm, sb);
    } else {
        int p = bid - 128;
        paths_tile(xr, xlo, wph, wpl, pp, (p & 31) * 64, p >> 5, sm, sb);
    }
}

// Wo gemm: plain dense
__global__ __launch_bounds__(256, 1) void gemm128(const float* __restrict__ A,
                                                  const float* __restrict__ Bw,
                                                  float* __restrict__ C,
                                                  int K, int N, int mode) {
    extern __shared__ float sm[];
    uint32_t sb = smem_u32(sm);
    dense_tile(A, Bw, C, K, N, mode, blockIdx.y * 128, blockIdx.x * 128, sm, sb);
}

// ---------------------------------------------------------------------------
// Fused av (R13): pipelined at 3 CTAs/SM, e-tile double-buffered, k-paths
// rolled into cp.async groups.
// ---------------------------------------------------------------------------
#define AV_AS     0
#define AV_BS     (2*64*ASTRIDE)                   // 4608
#define AV_PQ     (AV_BS + 3*32*BSTRIDE)           // 17664
#define AV_PKS    (AV_PQ + 320)                    // 17984
#define AV_RS     (AV_PKS + 320)                   // 18304
#define AV_FLOATS (AV_RS + 64)                     // 18368
#define SMEM_AV   (AV_FLOATS*4)                    // 73472 B

__device__ __forceinline__ void av_prefetch(uint32_t sb, const float* Bv,
                                            const float* pb, int kt, int tid) {
    uint32_t sB = sb + (AV_BS + (kt % 3) * (32*BSTRIDE)) * 4;
    int kb = kt * 32;
    #pragma unroll
    for (int t = 0; t < 4; t++) {
        int c = tid + t * 256;
        int row = c >> 5, col = c & 31;
        cp16(sB + row * (BSTRIDE*4) + col * 16,
             Bv + (size_t)(kb + row) * Dd + col * 4);
    }
    if (tid < 32 * DEPTH) {
        int k = tid / DEPTH, d = tid - k * DEPTH;
        cp4(sb + (AV_PKS + (kt & 1) * 160 + tid) * 4,
            pb + (size_t)(kb + k) * (Hh*DEPTH) + d);
    }
}

__device__ __forceinline__ void av_etile(float* Ab, const float* pks, const float* pqs,
                                         int kglob0, int qmax, int warp, int lane,
                                         float rsum[8]) {
    float k0v = pks[lane*5+0], k1v = pks[lane*5+1], k2v = pks[lane*5+2],
          k3v = pks[lane*5+3], k4v = pks[lane*5+4];
    float m0 = 1.f - k0v, m1 = 1.f - k1v, m2 = 1.f - k2v, m3 = 1.f - k3v, m4 = 1.f - k4v;
    int kglob = kglob0 + lane;
    #pragma unroll
    for (int jr = 0; jr < 8; jr++) {
        int row = warp * 8 + jr;
        const float* pq = pqs + row * 5;
        float p0 = pq[0], p1 = pq[1], p2 = pq[2], p3 = pq[3], p4 = pq[4];
        float prod = p0 * k0v + (1.f - p0) * m0;
        float s = prod;
        prod *= p1 * k1v + (1.f - p1) * m1; s += prod;
        prod *= p2 * k2v + (1.f - p2) * m2; s += prod;
        prod *= p3 * k3v + (1.f - p3) * m3; s += prod;
        prod *= p4 * k4v + (1.f - p4) * m4; s += prod;
        float ev = 0.f;
        if (kglob <= qmax + row) ev = rnaf(expap(s * 0.2f));
        rsum[jr] += ev;
        Ab[row * ASTRIDE + lane] = ev;
    }
}

__global__ __launch_bounds__(256, 3) void av_fused(const float* __restrict__ paths,
                                                   const float* __restrict__ v,
                                                   float* __restrict__ ctx,
                                                   float* __restrict__ ctx2,
                                                   float* __restrict__ rs) {
    extern __shared__ float sm[];
    uint32_t sb = smem_u32(sm);
    int j = blockIdx.x, bh = blockIdx.y;
    int qt = c_qt[j], k0t = c_k0[j], KT = c_kt[j], ds = c_ds[j];
    int b = bh >> 3, h = bh & 7;
    int tid = threadIdx.x;
    int warp = tid >> 5, lane = tid & 31;

    const float* pb = paths + (size_t)(b * Tt) * (Hh*DEPTH) + h * DEPTH;
    const float* Bv = v + (size_t)b * Tt * Dd + h * 128;
    float* pqs = sm + AV_PQ;
    float* rsm = sm + AV_RS;
    int qmax = qt * 64;

    av_prefetch(sb, Bv, pb, k0t + 0, tid);
    asm volatile("cp.async.commit_group;" ::: "memory");
    av_prefetch(sb, Bv, pb, k0t + 1, tid);
    asm volatile("cp.async.commit_group;" ::: "memory");

    for (int idx = tid; idx < 64 * DEPTH; idx += 256)
        pqs[idx] = pb[(size_t)(qt * 64 + idx / DEPTH) * (Hh*DEPTH) + idx % DEPTH];

    int wm = (warp & 1) * 32;
    int wn = (warp >> 1) * 32;
    int tg = lane >> 2, tk = lane & 3;
    float acc[2][4][4];
    #pragma unroll
    for (int mt = 0; mt < 2; mt++)
        #pragma unroll
        for (int nt = 0; nt < 4; nt++)
            #pragma unroll
            for (int i = 0; i < 4; i++) acc[mt][nt][i] = 0.f;
    float rsum[8];
    #pragma unroll
    for (int i = 0; i < 8; i++) rsum[i] = 0.f;

    asm volatile("cp.async.wait_group 1;" ::: "memory");
    __syncthreads();

    av_etile(sm + AV_AS, sm + AV_PKS + (k0t & 1) * 160, pqs,
             (k0t + 0) * 32, qmax, warp, lane, rsum);

    for (int it = 0; it < KT; it++) {
        asm volatile("cp.async.wait_group 1;" ::: "memory");
        __syncthreads();

        int pf = it + 2;
        if (pf < KT) av_prefetch(sb, Bv, pb, k0t + pf, tid);
        asm volatile("cp.async.commit_group;" ::: "memory");

        {
            const float* As = sm + AV_AS + (it & 1) * (64*ASTRIDE);
            const float* Bs = sm + AV_BS + ((k0t + it) % 3) * (32*BSTRIDE);
            #pragma unroll
            for (int kq = 0; kq < 32; kq += 8) {
                uint32_t af[2][4], bf[4][2];
                #pragma unroll
                for (int mt = 0; mt < 2; mt++) {
                    int m = wm + mt * 16 + tg;
                    af[mt][0] = __float_as_uint(As[m * ASTRIDE + kq + tk]);
                    af[mt][1] = __float_as_uint(As[(m + 8) * ASTRIDE + kq + tk]);
                    af[mt][2] = __float_as_uint(As[m * ASTRIDE + kq + tk + 4]);
                    af[mt][3] = __float_as_uint(As[(m + 8) * ASTRIDE + kq + tk + 4]);
                }
                #pragma unroll
                for (int nt = 0; nt < 4; nt++) {
                    int n = wn + nt * 8 + tg;
                    bf[nt][0] = __float_as_uint(Bs[(kq + tk) * BSTRIDE + n]);
                    bf[nt][1] = __float_as_uint(Bs[(kq + tk + 4) * BSTRIDE + n]);
                }
                #pragma unroll
                for (int mt = 0; mt < 2; mt++)
                    #pragma unroll
                    for (int nt = 0; nt < 4; nt++)
                        mma_tf32(acc[mt][nt], af[mt][0], af[mt][1], af[mt][2], af[mt][3],
                                 bf[nt][0], bf[nt][1]);
            }
        }

        if (it + 1 < KT) {
            asm volatile("cp.async.wait_group 1;" ::: "memory");
            av_etile(sm + AV_AS + ((it + 1) & 1) * (64*ASTRIDE),
                     sm + AV_PKS + ((k0t + it + 1) & 1) * 160, pqs,
                     (k0t + it + 1) * 32, qmax, warp, lane, rsum);
        }
    }

    #pragma unroll
    for (int jr = 0; jr < 8; jr++) {
        float s = rsum[jr];
        #pragma unroll
        for (int o = 16; o > 0; o >>= 1) s += __shfl_xor_sync(0xffffffffu, s, o);
        if (lane == 0) rsm[warp * 8 + jr] = s;
    }
    __syncthreads();

    if (qt < 8) {
        float* C = ctx + (size_t)b * Tt * Dd + h * 128;
        #pragma unroll
        for (int mt = 0; mt < 2; mt++) {
            int rl0 = wm + mt * 16 + tg;
            float i0 = 1.f / rsm[rl0], i1 = 1.f / rsm[rl0 + 8];
            #pragma unroll
            for (int nt = 0; nt < 4; nt++) {
                int r0 = qt * 64 + rl0;
                int cc = wn + nt * 8 + tk * 2;
                *(float2*)&C[(size_t)r0 * Dd + cc] =
                    make_float2(rnaf(acc[mt][nt][0] * i0), rnaf(acc[mt][nt][1] * i0));
                *(float2*)&C[(size_t)(r0 + 8) * Dd + cc] =
                    make_float2(rnaf(acc[mt][nt][2] * i1), rnaf(acc[mt][nt][3] * i1));
            }
        }
    } else {
        if (tid < 64) {
            float* rsp = rs + (size_t)ds * (Bb*Hh) * Tt + (size_t)bh * Tt + qt * 64;
            rsp[tid] = rsm[tid];
        }
        float* C = (ds ? ctx2 : ctx) + (size_t)b * Tt * Dd + h * 128;
        #pragma unroll
        for (int mt = 0; mt < 2; mt++) {
            #pragma unroll
            for (int nt = 0; nt < 4; nt++) {
                int r0 = qt * 64 + wm + mt * 16 + tg;
                int cc = wn + nt * 8 + tk * 2;
                *(float2*)&C[(size_t)r0 * Dd + cc]       = make_float2(acc[mt][nt][0], acc[mt][nt][1]);
                *(float2*)&C[(size_t)(r0 + 8) * Dd + cc] = make_float2(acc[mt][nt][2], acc[mt][nt][3]);
            }
        }
    }
}

// normalize + combine rows t>=512 only
__global__ __launch_bounds__(256) void ctx_norm(float4* __restrict__ ctx,
                                                const float4* __restrict__ ctx2,
                                                const float* __restrict__ rs) {
    int i = blockIdx.x * 256 + threadIdx.x;
    const int per_b = 512 * Dd / 4;
    if (i < Bb * per_b) {
        int b = i / per_b;
        int off = i - b * per_b;
        int t = 512 + off / (Dd / 4);
        int c4 = off % (Dd / 4);
        int bh = b * 8 + (c4 >> 5);
        size_t gi = (size_t)b * Tt * (Dd/4) + (size_t)t * (Dd/4) + c4;
        float denom = rs[(size_t)bh * Tt + t] + rs[(size_t)(Bb*Hh) * Tt + (size_t)bh * Tt + t];
        float inv = 1.f / denom;
        float4 xa = ctx[gi], xb = ctx2[gi];
        ctx[gi] = make_float4(rnaf((xa.x + xb.x) * inv), rnaf((xa.y + xb.y) * inv),
                              rnaf((xa.z + xb.z) * inv), rnaf((xa.w + xb.w) * inv));
    }
}

__global__ __launch_bounds__(256) void sigmoid_comb(const float* __restrict__ pp,
                                                    const float* __restrict__ bp,
                                                    float* __restrict__ paths) {
    int tok = blockIdx.x * 4 + (threadIdx.x >> 6);
    int c = threadIdx.x & 63;
    if (c < Hh * DEPTH) {
        float z = bp[c];
        #pragma unroll
        for (int s = 0; s < 4; s++)
            z += pp[(size_t)s * NTOK * 40 + (size_t)tok * 40 + c];
        paths[(size_t)tok * (Hh*DEPTH) + c] = 1.f / (1.f + expf(-z));
    }
}

// ---------------- staging: x split + Wp pad ----------------
__global__ __launch_bounds__(256) void prep_all(const float4* __restrict__ x,
                                                float4* __restrict__ xh,
                                                float4* __restrict__ xl,
                                                const float* __restrict__ Wp) {
    int i = blockIdx.x * 256 + threadIdx.x;
    if (i < NTOK*Dd/4) {
        float4 v = x[i];
        float4 h = make_float4(rnaf(v.x), rnaf(v.y), rnaf(v.z), rnaf(v.w));
        xh[i] = h;
        xl[i] = make_float4(rnaf(v.x - h.x), rnaf(v.y - h.y), rnaf(v.z - h.z), rnaf(v.w - h.w));
    }
    if (i < Dd*128) {
        int k = i >> 7, n = i & 127;
        float h = 0.f, l = 0.f;
        if (n < Hh * DEPTH) {
            float w = Wp[(size_t)k * (Hh * DEPTH) + n];
            h = rnaf(w);
            l = rnaf(w - h);
        }
        g_wph[i] = h;
        g_wpl[i] = l;
    }
}

// ---------------------------------------------------------------------------
extern "C" void kernel_launch(void* const* d_in, const int* in_sizes, int n_in,
                              void* d_out, int out_size) {
    const float* x  = (const float*)d_in[0];
    const float* Wp = (const float*)d_in[1];
    const float* bp = (const float*)d_in[2];
    const float* Wv = (const float*)d_in[3];
    const float* Wo = (const float*)d_in[4];
    float* out = (float*)d_out;

    float *paths, *xr, *xlo, *wph, *wpl, *pp, *v, *ctx, *ctx2, *rs;
    cudaGetSymbolAddress((void**)&paths, g_paths);
    cudaGetSymbolAddress((void**)&xr,    g_xr);
    cudaGetSymbolAddress((void**)&xlo,   g_xlo);
    cudaGetSymbolAddress((void**)&wph,   g_wph);
    cudaGetSymbolAddress((void**)&wpl,   g_wpl);
    cudaGetSymbolAddress((void**)&pp,    g_pp);
    cudaGetSymbolAddress((void**)&v,     g_v);
    cudaGetSymbolAddress((void**)&ctx,   g_ctx);
    cudaGetSymbolAddress((void**)&ctx2,  g_ctx2);
    cudaGetSymbolAddress((void**)&rs,    g_rs);

    cudaFuncSetAttribute(fat_vp,     cudaFuncAttributeMaxDynamicSharedMemorySize, SMEM_GEMM2);
    cudaFuncSetAttribute(gemm128,    cudaFuncAttributeMaxDynamicSharedMemorySize, SMEM_GEMM2);
    cudaFuncSetAttribute(av_fused,   cudaFuncAttributeMaxDynamicSharedMemorySize, SMEM_AV);

    // staging (x split + Wp pad; weights consumed raw)
    prep_all<<<(NTOK*Dd/4 + 255)/256, 256>>>((const float4*)x, (float4*)xr, (float4*)xlo, Wp);

    // fat kernel: V = x@Wv (128 tiles) + paths partial GEMM (128 tiles)
    fat_vp<<<256, 256, SMEM_GEMM2>>>(xr, xlo, Wv, v, wph, wpl, pp);

    // sigmoid + split-K combine -> paths table
    sigmoid_comb<<<NTOK/4, 256>>>(pp, bp, paths);

    // fused sim+softmax+attn@V (pipelined, 3 CTAs/SM)
    av_fused<<<dim3(24, Bb*Hh), 256, SMEM_AV>>>(paths, v, ctx, ctx2, rs);

    // combine split rows (t >= 512)
    ctx_norm<<<(Bb*512*Dd/4 + 255)/256, 256>>>((float4*)ctx, (const float4*)ctx2, rs);

    // out = ctx @ Wo
    gemm128<<<dim3(Dd/128, NTOK/128), 256, SMEM_GEMM2>>>(ctx, Wo, out, Dd, Dd, 0);
}

// round 15
// speedup vs baseline: 1.1297x; 1.0394x over previous
#include <cuda_runtime.h>
#include <math.h>
#include <stdint.h>

#define Bb 2
#define Tt 1024
#define Dd 1024
#define Hh 8
#define DEPTH 5
#define NTOK (Bb*Tt)

// ---------------- scratch (device globals; allocation-free) ----------------
__device__ float g_paths[NTOK*Hh*DEPTH];      // [token][h*5+d]
__device__ float g_xr[NTOK*Dd];               // tf32(rna) x
__device__ float g_wph[Dd*128];               // Wp hi, padded [k][128]
__device__ float g_wpl[Dd*128];               // Wp lo, padded [k][128]
__device__ float g_pp[4*NTOK*40];             // paths split-K partials (compact)
__device__ float g_v[NTOK*Dd];                // V = x@Wv, rounded
__device__ float g_ctx[NTOK*Dd];              // ctx (t<512 final; t>=512 partial slot0)
__device__ float g_ctx2[NTOK*Dd];             // ctx partial slot1 (t>=512 only)
__device__ float g_rs[2*Bb*Hh*Tt];            // row sums [slot][bh][t]

// av jobs (24/bh, longest first). qt<8 full (self-normalized); qt>=8 split.
__constant__ int c_qt[24] = {15,15,14,14,13,13,12,12,11,11,10,10, 9, 9, 8, 8, 7, 6, 5, 4, 3, 2, 1, 0};
__constant__ int c_k0[24] = { 0,16, 0,15, 0,14, 0,13, 0,12, 0,11, 0,10, 0, 9, 0, 0, 0, 0, 0, 0, 0, 0};
__constant__ int c_kt[24] = {16,16,15,15,14,14,13,13,12,12,11,11,10,10, 9, 9,16,14,12,10, 8, 6, 4, 2};
__constant__ int c_ds[24] = { 0, 1, 0, 1, 0, 1, 0, 1, 0, 1, 0, 1, 0, 1, 0, 1, 0, 0, 0, 0, 0, 0, 0, 0};

// ---------------- helpers ----------------
__device__ __forceinline__ float rnaf(float f) {
    uint32_t r; asm("cvt.rna.tf32.f32 %0, %1;" : "=r"(r) : "f"(f));
    return __uint_as_float(r);
}
__device__ __forceinline__ uint32_t smem_u32(const void* p) {
    uint32_t a;
    asm("{ .reg .u64 t; cvta.to.shared.u64 t, %1; cvt.u32.u64 %0, t; }" : "=r"(a) : "l"(p));
    return a;
}
__device__ __forceinline__ void cp16(uint32_t dst, const void* src) {
    asm volatile("cp.async.cg.shared.global [%0], [%1], 16;" :: "r"(dst), "l"(src));
}
__device__ __forceinline__ void cp4(uint32_t dst, const void* src) {
    asm volatile("cp.async.ca.shared.global [%0], [%1], 4;" :: "r"(dst), "l"(src));
}
__device__ __forceinline__ void mma_tf32(float c[4],
                                         uint32_t a0, uint32_t a1, uint32_t a2, uint32_t a3,
                                         uint32_t b0, uint32_t b1) {
    asm volatile("mma.sync.aligned.m16n8k8.row.col.f32.tf32.tf32.f32 "
                 "{%0,%1,%2,%3}, {%4,%5,%6,%7}, {%8,%9}, {%0,%1,%2,%3};"
                 : "+f"(c[0]), "+f"(c[1]), "+f"(c[2]), "+f"(c[3])
                 : "r"(a0), "r"(a1), "r"(a2), "r"(a3), "r"(b0), "r"(b1));
}

#define ASTRIDE 36
#define BSTRIDE 136

// ---------------------------------------------------------------------------
// dense tf32 GEMM tile: C[128,128], 256 threads = 8 warps (2m x 4n,
// warp tile 64x32), BK=32, 3-stage cp.async. B raw, rna on frags.
// ---------------------------------------------------------------------------
#define A2FLOATS (128*ASTRIDE)                 // 4608
#define STAGEF2  (A2FLOATS + 32*BSTRIDE)       // 8960 floats
#define SMEM_GEMM2 (3*STAGEF2*4)               // 107520 B

__device__ __forceinline__ void load_stage2(uint32_t sb, int s,
                                            const float* A, int lda, int bm,
                                            const float* B, int ldb, int bn,
                                            int tid, int kt) {
    uint32_t sa = sb + s * (STAGEF2 * 4);
    uint32_t sB = sa + A2FLOATS * 4;
    int k0 = kt * 32;
    #pragma unroll
    for (int t = 0; t < 4; t++) {
        int c = tid + t * 256;
        int row = c >> 3, col = c & 7;
        cp16(sa + row * (ASTRIDE*4) + col * 16,
             A + (size_t)(bm + row) * lda + k0 + col * 4);
    }
    #pragma unroll
    for (int t = 0; t < 4; t++) {
        int c = tid + t * 256;
        int row = c >> 5, col = c & 31;
        cp16(sB + row * (BSTRIDE*4) + col * 16,
             B + (size_t)(k0 + row) * ldb + bn + col * 4);
    }
}

__device__ void dense_tile(const float* __restrict__ A, const float* __restrict__ Bw,
                           float* __restrict__ C, int K, int N, int mode,
                           int bm, int bn, float* sm, uint32_t sb) {
    int tid = threadIdx.x;
    int warp = tid >> 5, lane = tid & 31;
    int wm = (warp & 1) * 64;
    int wn = (warp >> 1) * 32;
    int tg = lane >> 2, tk = lane & 3;
    int KT = K / 32;

    float acc[4][4][4];
    #pragma unroll
    for (int mt = 0; mt < 4; mt++)
        #pragma unroll
        for (int nt = 0; nt < 4; nt++)
            #pragma unroll
            for (int i = 0; i < 4; i++) acc[mt][nt][i] = 0.f;

    load_stage2(sb, 0, A, K, bm, Bw, N, bn, tid, 0);
    asm volatile("cp.async.commit_group;" ::: "memory");
    load_stage2(sb, 1, A, K, bm, Bw, N, bn, tid, 1);
    asm volatile("cp.async.commit_group;" ::: "memory");

    for (int it = 0; it < KT; it++) {
        asm volatile("cp.async.wait_group 1;" ::: "memory");
        __syncthreads();
        int pf = it + 2;
        if (pf < KT) load_stage2(sb, pf % 3, A, K, bm, Bw, N, bn, tid, pf);
        asm volatile("cp.async.commit_group;" ::: "memory");

        const float* As = sm + (it % 3) * STAGEF2;
        const float* Bs = As + A2FLOATS;
        #pragma unroll
        for (int kq = 0; kq < 32; kq += 8) {
            uint32_t af[4][4], bf[4][2];
            #pragma unroll
            for (int mt = 0; mt < 4; mt++) {
                int m = wm + mt * 16 + tg;
                af[mt][0] = __float_as_uint(As[m * ASTRIDE + kq + tk]);
                af[mt][1] = __float_as_uint(As[(m + 8) * ASTRIDE + kq + tk]);
                af[mt][2] = __float_as_uint(As[m * ASTRIDE + kq + tk + 4]);
                af[mt][3] = __float_as_uint(As[(m + 8) * ASTRIDE + kq + tk + 4]);
            }
            #pragma unroll
            for (int nt = 0; nt < 4; nt++) {
                int n = wn + nt * 8 + tg;
                bf[nt][0] = __float_as_uint(rnaf(Bs[(kq + tk) * BSTRIDE + n]));
                bf[nt][1] = __float_as_uint(rnaf(Bs[(kq + tk + 4) * BSTRIDE + n]));
            }
            #pragma unroll
            for (int mt = 0; mt < 4; mt++)
                #pragma unroll
                for (int nt = 0; nt < 4; nt++)
                    mma_tf32(acc[mt][nt], af[mt][0], af[mt][1], af[mt][2], af[mt][3],
                             bf[nt][0], bf[nt][1]);
        }
        __syncthreads();
    }

    #pragma unroll
    for (int mt = 0; mt < 4; mt++) {
        #pragma unroll
        for (int nt = 0; nt < 4; nt++) {
            int r0 = bm + wm + mt * 16 + tg;
            int cc = bn + wn + nt * 8 + tk * 2;
            float2 v0 = make_float2(acc[mt][nt][0], acc[mt][nt][1]);
            float2 v1 = make_float2(acc[mt][nt][2], acc[mt][nt][3]);
            if (mode == 1) {
                v0.x = rnaf(v0.x); v0.y = rnaf(v0.y);
                v1.x = rnaf(v1.x); v1.y = rnaf(v1.y);
            }
            *(float2*)&C[(size_t)r0 * N + cc]       = v0;
            *(float2*)&C[(size_t)(r0 + 8) * N + cc] = v1;
        }
    }
}

// ---------------------------------------------------------------------------
// paths GEMM tile: logits = xh @ (Wph + Wpl)  (xl*wh term dropped; error
// ~u*|logit| -> paths err <= 2.5e-5). Split-K x4, compact pp [tok][40].
// ---------------------------------------------------------------------------
#define PSTAGEF (64*36 + 2*32*136)    // 11008 floats
#define SMEM_PATHS (2*PSTAGEF*4)

__device__ __forceinline__ void paths_load(uint32_t sb, int s,
                                           const float* xh, int bm,
                                           const float* wh, const float* wl,
                                           int tid, int kt) {
    uint32_t base = sb + s * (PSTAGEF * 4);
    uint32_t xh_o = base;
    uint32_t wh_o = base + 64*36*4;
    uint32_t wl_o = wh_o + 32*136*4;
    int k0 = kt * 32;
    #pragma unroll
    for (int t = 0; t < 2; t++) {
        int c = tid + t * 256;
        int row = c >> 3, col = c & 7;
        cp16(xh_o + row * (36*4) + col * 16,
             xh + (size_t)(bm + row) * Dd + k0 + col * 4);
    }
    #pragma unroll
    for (int t = 0; t < 4; t++) {
        int c = tid + t * 256;
        int row = c >> 5, col = c & 31;
        size_t go = (size_t)(k0 + row) * 128 + col * 4;
        uint32_t so = row * (136*4) + col * 16;
        cp16(wh_o + so, wh + go);
        cp16(wl_o + so, wl + go);
    }
}

__device__ void paths_tile(const float* __restrict__ xh0,
                           const float* __restrict__ wh0, const float* __restrict__ wl0,
                           float* __restrict__ pp, int bm, int sp,
                           float* sm, uint32_t sb) {
    int tid = threadIdx.x;
    int warp = tid >> 5, lane = tid & 31;
    int wm = (warp & 1) * 32;
    int wn = (warp >> 1) * 32;
    int tg = lane >> 2, tk = lane & 3;
    const float* xh = xh0 + sp * 256;
    const float* wh = wh0 + (size_t)(sp * 256) * 128;
    const float* wl = wl0 + (size_t)(sp * 256) * 128;
    float* out = pp + (size_t)sp * NTOK * 40;
    const int KT = 8;

    float acc[2][4][4];
    #pragma unroll
    for (int mt = 0; mt < 2; mt++)
        #pragma unroll
        for (int nt = 0; nt < 4; nt++)
            #pragma unroll
            for (int i = 0; i < 4; i++) acc[mt][nt][i] = 0.f;

    paths_load(sb, 0, xh, bm, wh, wl, tid, 0);
    asm volatile("cp.async.commit_group;" ::: "memory");

    for (int it = 0; it < KT; it++) {
        int pf = it + 1;
        if (pf < KT) {
            paths_load(sb, pf & 1, xh, bm, wh, wl, tid, pf);
            asm volatile("cp.async.commit_group;" ::: "memory");
            asm volatile("cp.async.wait_group 1;" ::: "memory");
        } else {
            asm volatile("cp.async.wait_group 0;" ::: "memory");
        }
        __syncthreads();

        const float* Xh = sm + (it & 1) * PSTAGEF;
        const float* Wh = Xh + 64*36;
        const float* Wl = Wh + 32*136;
        #pragma unroll
        for (int kq = 0; kq < 32; kq += 8) {
            uint32_t ah[2][4], bh[4][2], bl[4][2];
            #pragma unroll
            for (int mt = 0; mt < 2; mt++) {
                int m = wm + mt * 16 + tg;
                ah[mt][0] = __float_as_uint(Xh[m * 36 + kq + tk]);
                ah[mt][1] = __float_as_uint(Xh[(m + 8) * 36 + kq + tk]);
                ah[mt][2] = __float_as_uint(Xh[m * 36 + kq + tk + 4]);
                ah[mt][3] = __float_as_uint(Xh[(m + 8) * 36 + kq + tk + 4]);
            }
            #pragma unroll
            for (int nt = 0; nt < 4; nt++) {
                int n = wn + nt * 8 + tg;
                bh[nt][0] = __float_as_uint(Wh[(kq + tk) * 136 + n]);
                bh[nt][1] = __float_as_uint(Wh[(kq + tk + 4) * 136 + n]);
                bl[nt][0] = __float_as_uint(Wl[(kq + tk) * 136 + n]);
                bl[nt][1] = __float_as_uint(Wl[(kq + tk + 4) * 136 + n]);
            }
            #pragma unroll
            for (int mt = 0; mt < 2; mt++)
                #pragma unroll
                for (int nt = 0; nt < 4; nt++) {
                    mma_tf32(acc[mt][nt], ah[mt][0], ah[mt][1], ah[mt][2], ah[mt][3],
                             bh[nt][0], bh[nt][1]);
                    mma_tf32(acc[mt][nt], ah[mt][0], ah[mt][1], ah[mt][2], ah[mt][3],
                             bl[nt][0], bl[nt][1]);
                }
        }
        __syncthreads();
    }

    #pragma unroll
    for (int mt = 0; mt < 2; mt++) {
        #pragma unroll
        for (int nt = 0; nt < 4; nt++) {
            int cc = wn + nt * 8 + tk * 2;
            if (cc < Hh * DEPTH) {
                int r0 = bm + wm + mt * 16 + tg;
                out[(size_t)r0 * 40 + cc]           = acc[mt][nt][0];
                out[(size_t)r0 * 40 + cc + 1]       = acc[mt][nt][1];
                out[(size_t)(r0 + 8) * 40 + cc]     = acc[mt][nt][2];
                out[(size_t)(r0 + 8) * 40 + cc + 1] = acc[mt][nt][3];
            }
        }
    }
}

// fat kernel: bid<128 -> V-gemm tile; bid>=128 -> paths tile. grid 256.
__global__ __launch_bounds__(256, 1) void fat_vp(const float* __restrict__ xr,
                                                 const float* __restrict__ Wv,
                                                 float* __restrict__ v,
                                                 const float* __restrict__ wph,
                                                 const float* __restrict__ wpl,
                                                 float* __restrict__ pp) {
    extern __shared__ float sm[];
    uint32_t sb = smem_u32(sm);
    int bid = blockIdx.x;
    if (bid < 128) {
        dense_tile(xr, Wv, v, Dd, Dd, 1, (bid >> 3) * 128, (bid & 7) * 128, sm, sb);
    } else {
        int p = bid - 128;
        paths_tile(xr, wph, wpl, pp, (p & 31) * 64, p >> 5, sm, sb);
    }
}

__global__ __launch_bounds__(256, 1) void gemm128(const float* __restrict__ A,
                                                  const float* __restrict__ Bw,
                                                  float* __restrict__ C,
                                                  int K, int N, int mode) {
    extern __shared__ float sm[];
    uint32_t sb = smem_u32(sm);
    dense_tile(A, Bw, C, K, N, mode, blockIdx.y * 128, blockIdx.x * 128, sm, sb);
}

// ---------------------------------------------------------------------------
// Fused av (R13 pipeline): 3 CTAs/SM, e-tile double-buffered, k-paths in
// cp.async groups. Exp via MUFU (__expf) to offload the FMA/issue pressure.
// ---------------------------------------------------------------------------
#define AV_AS     0
#define AV_BS     (2*64*ASTRIDE)                   // 4608
#define AV_PQ     (AV_BS + 3*32*BSTRIDE)           // 17664
#define AV_PKS    (AV_PQ + 320)                    // 17984
#define AV_RS     (AV_PKS + 320)                   // 18304
#define AV_FLOATS (AV_RS + 64)                     // 18368
#define SMEM_AV   (AV_FLOATS*4)                    // 73472 B

__device__ __forceinline__ void av_prefetch(uint32_t sb, const float* Bv,
                                            const float* pb, int kt, int tid) {
    uint32_t sB = sb + (AV_BS + (kt % 3) * (32*BSTRIDE)) * 4;
    int kb = kt * 32;
    #pragma unroll
    for (int t = 0; t < 4; t++) {
        int c = tid + t * 256;
        int row = c >> 5, col = c & 31;
        cp16(sB + row * (BSTRIDE*4) + col * 16,
             Bv + (size_t)(kb + row) * Dd + col * 4);
    }
    if (tid < 32 * DEPTH) {
        int k = tid / DEPTH, d = tid - k * DEPTH;
        cp4(sb + (AV_PKS + (kt & 1) * 160 + tid) * 4,
            pb + (size_t)(kb + k) * (Hh*DEPTH) + d);
    }
}

__device__ __forceinline__ void av_etile(float* Ab, const float* pks, const float* pqs,
                                         int kglob0, int qmax, int warp, int lane,
                                         float rsum[8]) {
    float k0v = pks[lane*5+0], k1v = pks[lane*5+1], k2v = pks[lane*5+2],
          k3v = pks[lane*5+3], k4v = pks[lane*5+4];
    float m0 = 1.f - k0v, m1 = 1.f - k1v, m2 = 1.f - k2v, m3 = 1.f - k3v, m4 = 1.f - k4v;
    int kglob = kglob0 + lane;
    #pragma unroll
    for (int jr = 0; jr < 8; jr++) {
        int row = warp * 8 + jr;
        const float* pq = pqs + row * 5;
        float p0 = pq[0], p1 = pq[1], p2 = pq[2], p3 = pq[3], p4 = pq[4];
        float prod = p0 * k0v + (1.f - p0) * m0;
        float s = prod;
        prod *= p1 * k1v + (1.f - p1) * m1; s += prod;
        prod *= p2 * k2v + (1.f - p2) * m2; s += prod;
        prod *= p3 * k3v + (1.f - p3) * m3; s += prod;
        prod *= p4 * k4v + (1.f - p4) * m4; s += prod;
        float ev = 0.f;
        if (kglob <= qmax + row) ev = rnaf(__expf(s * 0.2f));
        rsum[jr] += ev;
        Ab[row * ASTRIDE + lane] = ev;
    }
}

__global__ __launch_bounds__(256, 3) void av_fused(const float* __restrict__ paths,
                                                   const float* __restrict__ v,
                                                   float* __restrict__ ctx,
                                                   float* __restrict__ ctx2,
                                                   float* __restrict__ rs) {
    extern __shared__ float sm[];
    uint32_t sb = smem_u32(sm);
    int j = blockIdx.x, bh = blockIdx.y;
    int qt = c_qt[j], k0t = c_k0[j], KT = c_kt[j], ds = c_ds[j];
    int b = bh >> 3, h = bh & 7;
    int tid = threadIdx.x;
    int warp = tid >> 5, lane = tid & 31;

    const float* pb = paths + (size_t)(b * Tt) * (Hh*DEPTH) + h * DEPTH;
    const float* Bv = v + (size_t)b * Tt * Dd + h * 128;
    float* pqs = sm + AV_PQ;
    float* rsm = sm + AV_RS;
    int qmax = qt * 64;

    av_prefetch(sb, Bv, pb, k0t + 0, tid);
    asm volatile("cp.async.commit_group;" ::: "memory");
    av_prefetch(sb, Bv, pb, k0t + 1, tid);
    asm volatile("cp.async.commit_group;" ::: "memory");

    for (int idx = tid; idx < 64 * DEPTH; idx += 256)
        pqs[idx] = pb[(size_t)(qt * 64 + idx / DEPTH) * (Hh*DEPTH) + idx % DEPTH];

    int wm = (warp & 1) * 32;
    int wn = (warp >> 1) * 32;
    int tg = lane >> 2, tk = lane & 3;
    float acc[2][4][4];
    #pragma unroll
    for (int mt = 0; mt < 2; mt++)
        #pragma unroll
        for (int nt = 0; nt < 4; nt++)
            #pragma unroll
            for (int i = 0; i < 4; i++) acc[mt][nt][i] = 0.f;
    float rsum[8];
    #pragma unroll
    for (int i = 0; i < 8; i++) rsum[i] = 0.f;

    asm volatile("cp.async.wait_group 1;" ::: "memory");
    __syncthreads();

    av_etile(sm + AV_AS, sm + AV_PKS + (k0t & 1) * 160, pqs,
             (k0t + 0) * 32, qmax, warp, lane, rsum);

    for (int it = 0; it < KT; it++) {
        asm volatile("cp.async.wait_group 1;" ::: "memory");
        __syncthreads();

        int pf = it + 2;
        if (pf < KT) av_prefetch(sb, Bv, pb, k0t + pf, tid);
        asm volatile("cp.async.commit_group;" ::: "memory");

        {
            const float* As = sm + AV_AS + (it & 1) * (64*ASTRIDE);
            const float* Bs = sm + AV_BS + ((k0t + it) % 3) * (32*BSTRIDE);
            #pragma unroll
            for (int kq = 0; kq < 32; kq += 8) {
                uint32_t af[2][4], bf[4][2];
                #pragma unroll
                for (int mt = 0; mt < 2; mt++) {
                    int m = wm + mt * 16 + tg;
                    af[mt][0] = __float_as_uint(As[m * ASTRIDE + kq + tk]);
                    af[mt][1] = __float_as_uint(As[(m + 8) * ASTRIDE + kq + tk]);
                    af[mt][2] = __float_as_uint(As[m * ASTRIDE + kq + tk + 4]);
                    af[mt][3] = __float_as_uint(As[(m + 8) * ASTRIDE + kq + tk + 4]);
                }
                #pragma unroll
                for (int nt = 0; nt < 4; nt++) {
                    int n = wn + nt * 8 + tg;
                    bf[nt][0] = __float_as_uint(Bs[(kq + tk) * BSTRIDE + n]);
                    bf[nt][1] = __float_as_uint(Bs[(kq + tk + 4) * BSTRIDE + n]);
                }
                #pragma unroll
                for (int mt = 0; mt < 2; mt++)
                    #pragma unroll
                    for (int nt = 0; nt < 4; nt++)
                        mma_tf32(acc[mt][nt], af[mt][0], af[mt][1], af[mt][2], af[mt][3],
                                 bf[nt][0], bf[nt][1]);
            }
        }

        if (it + 1 < KT) {
            asm volatile("cp.async.wait_group 1;" ::: "memory");
            av_etile(sm + AV_AS + ((it + 1) & 1) * (64*ASTRIDE),
                     sm + AV_PKS + ((k0t + it + 1) & 1) * 160, pqs,
                     (k0t + it + 1) * 32, qmax, warp, lane, rsum);
        }
    }

    #pragma unroll
    for (int jr = 0; jr < 8; jr++) {
        float s = rsum[jr];
        #pragma unroll
        for (int o = 16; o > 0; o >>= 1) s += __shfl_xor_sync(0xffffffffu, s, o);
        if (lane == 0) rsm[warp * 8 + jr] = s;
    }
    __syncthreads();

    if (qt < 8) {
        float* C = ctx + (size_t)b * Tt * Dd + h * 128;
        #pragma unroll
        for (int mt = 0; mt < 2; mt++) {
            int rl0 = wm + mt * 16 + tg;
            float i0 = 1.f / rsm[rl0], i1 = 1.f / rsm[rl0 + 8];
            #pragma unroll
            for (int nt = 0; nt < 4; nt++) {
                int r0 = qt * 64 + rl0;
                int cc = wn + nt * 8 + tk * 2;
                *(float2*)&C[(size_t)r0 * Dd + cc] =
                    make_float2(rnaf(acc[mt][nt][0] * i0), rnaf(acc[mt][nt][1] * i0));
                *(float2*)&C[(size_t)(r0 + 8) * Dd + cc] =
                    make_float2(rnaf(acc[mt][nt][2] * i1), rnaf(acc[mt][nt][3] * i1));
            }
        }
    } else {
        if (tid < 64) {
            float* rsp = rs + (size_t)ds * (Bb*Hh) * Tt + (size_t)bh * Tt + qt * 64;
            rsp[tid] = rsm[tid];
        }
        float* C = (ds ? ctx2 : ctx) + (size_t)b * Tt * Dd + h * 128;
        #pragma unroll
        for (int mt = 0; mt < 2; mt++) {
            #pragma unroll
            for (int nt = 0; nt < 4; nt++) {
                int r0 = qt * 64 + wm + mt * 16 + tg;
                int cc = wn + nt * 8 + tk * 2;
                *(float2*)&C[(size_t)r0 * Dd + cc]       = make_float2(acc[mt][nt][0], acc[mt][nt][1]);
                *(float2*)&C[(size_t)(r0 + 8) * Dd + cc] = make_float2(acc[mt][nt][2], acc[mt][nt][3]);
            }
        }
    }
}

// normalize + combine rows t>=512 only
__global__ __launch_bounds__(256) void ctx_norm(float4* __restrict__ ctx,
                                                const float4* __restrict__ ctx2,
                                                const float* __restrict__ rs) {
    int i = blockIdx.x * 256 + threadIdx.x;
    const int per_b = 512 * Dd / 4;
    if (i < Bb * per_b) {
        int b = i / per_b;
        int off = i - b * per_b;
        int t = 512 + off / (Dd / 4);
        int c4 = off % (Dd / 4);
        int bh = b * 8 + (c4 >> 5);
        size_t gi = (size_t)b * Tt * (Dd/4) + (size_t)t * (Dd/4) + c4;
        float denom = rs[(size_t)bh * Tt + t] + rs[(size_t)(Bb*Hh) * Tt + (size_t)bh * Tt + t];
        float inv = 1.f / denom;
        float4 xa = ctx[gi], xb = ctx2[gi];
        ctx[gi] = make_float4(rnaf((xa.x + xb.x) * inv), rnaf((xa.y + xb.y) * inv),
                              rnaf((xa.z + xb.z) * inv), rnaf((xa.w + xb.w) * inv));
    }
}

__global__ __launch_bounds__(256) void sigmoid_comb(const float* __restrict__ pp,
                                                    const float* __restrict__ bp,
                                                    float* __restrict__ paths) {
    int tok = blockIdx.x * 4 + (threadIdx.x >> 6);
    int c = threadIdx.x & 63;
    if (c < Hh * DEPTH) {
        float z = bp[c];
        #pragma unroll
        for (int s = 0; s < 4; s++)
            z += pp[(size_t)s * NTOK * 40 + (size_t)tok * 40 + c];
        paths[(size_t)tok * (Hh*DEPTH) + c] = 1.f / (1.f + expf(-z));
    }
}

// ---------------- staging: x round + Wp pad ----------------
__global__ __launch_bounds__(256) void prep_all(const float4* __restrict__ x,
                                                float4* __restrict__ xh,
                                                const float* __restrict__ Wp) {
    int i = blockIdx.x * 256 + threadIdx.x;
    if (i < NTOK*Dd/4) {
        float4 v = x[i];
        xh[i] = make_float4(rnaf(v.x), rnaf(v.y), rnaf(v.z), rnaf(v.w));
    }
    if (i < Dd*128) {
        int k = i >> 7, n = i & 127;
        float h = 0.f, l = 0.f;
        if (n < Hh * DEPTH) {
            float w = Wp[(size_t)k * (Hh * DEPTH) + n];
            h = rnaf(w);
            l = rnaf(w - h);
        }
        g_wph[i] = h;
        g_wpl[i] = l;
    }
}

// ---------------------------------------------------------------------------
extern "C" void kernel_launch(void* const* d_in, const int* in_sizes, int n_in,
                              void* d_out, int out_size) {
    const float* x  = (const float*)d_in[0];
    const float* Wp = (const float*)d_in[1];
    const float* bp = (const float*)d_in[2];
    const float* Wv = (const float*)d_in[3];
    const float* Wo = (const float*)d_in[4];
    float* out = (float*)d_out;

    float *paths, *xr, *wph, *wpl, *pp, *v, *ctx, *ctx2, *rs;
    cudaGetSymbolAddress((void**)&paths, g_paths);
    cudaGetSymbolAddress((void**)&xr,    g_xr);
    cudaGetSymbolAddress((void**)&wph,   g_wph);
    cudaGetSymbolAddress((void**)&wpl,   g_wpl);
    cudaGetSymbolAddress((void**)&pp,    g_pp);
    cudaGetSymbolAddress((void**)&v,     g_v);
    cudaGetSymbolAddress((void**)&ctx,   g_ctx);
    cudaGetSymbolAddress((void**)&ctx2,  g_ctx2);
    cudaGetSymbolAddress((void**)&rs,    g_rs);

    cudaFuncSetAttribute(fat_vp,   cudaFuncAttributeMaxDynamicSharedMemorySize, SMEM_GEMM2);
    cudaFuncSetAttribute(gemm128,  cudaFuncAttributeMaxDynamicSharedMemorySize, SMEM_GEMM2);
    cudaFuncSetAttribute(av_fused, cudaFuncAttributeMaxDynamicSharedMemorySize, SMEM_AV);

    // staging (x round + Wp hi/lo pad; Wv/Wo consumed raw)
    prep_all<<<(NTOK*Dd/4 + 255)/256, 256>>>((const float4*)x, (float4*)xr, Wp);

    // fat kernel: V = x@Wv (128 tiles) + paths partial GEMM (128 tiles)
    fat_vp<<<256, 256, SMEM_GEMM2>>>(xr, Wv, v, wph, wpl, pp);

    // sigmoid + split-K combine -> paths table
    sigmoid_comb<<<NTOK/4, 256>>>(pp, bp, paths);

    // fused sim+softmax+attn@V (pipelined, 3 CTAs/SM, MUFU exp)
    av_fused<<<dim3(24, Bb*Hh), 256, SMEM_AV>>>(paths, v, ctx, ctx2, rs);

    // combine split rows (t >= 512)
    ctx_norm<<<(Bb*512*Dd/4 + 255)/256, 256>>>((float4*)ctx, (const float4*)ctx2, rs);

    // out = ctx @ Wo
    gemm128<<<dim3(Dd/128, NTOK/128), 256, SMEM_GEMM2>>>(ctx, Wo, out, Dd, Dd, 0);
}

// round 16
// speedup vs baseline: 1.2072x; 1.0687x over previous
#include <cuda_runtime.h>
#include <math.h>
#include <stdint.h>

#define Bb 2
#define Tt 1024
#define Dd 1024
#define Hh 8
#define DEPTH 5
#define NTOK (Bb*Tt)

// ---------------- scratch (device globals; allocation-free) ----------------
__device__ float g_paths[NTOK*Hh*DEPTH];      // [token][h*5+d]
__device__ float g_wph[Dd*128];               // Wp hi, padded [k][128]
__device__ float g_wpl[Dd*128];               // Wp lo, padded [k][128]
__device__ float g_pp[4*NTOK*40];             // paths split-K partials (compact)
__device__ float g_v[NTOK*Dd];                // V = x@Wv, rounded
__device__ float g_ctx[NTOK*Dd];              // slot0 (final for qt<4 rows)
__device__ float g_ctx2[NTOK*Dd];             // slot1 (rows t>=256)
__device__ float g_ctx3[NTOK*Dd];             // slot2 (rows t>=768)
__device__ float g_rs[3*Bb*Hh*Tt];            // row sums [slot][bh][t]

// av jobs (32/bh, longest-first). qt<4 single chunk (self-normalized);
// qt 4..11 two chunks; qt 12..15 three chunks. max chunk = 12 KT units.
__constant__ int c_qt[32] = {11,11,15,15,10,10,15,14,14,14,13, 9, 9,13,13,12,12, 8, 8,12, 7, 7, 3, 6, 6, 5, 5, 2, 4, 4, 1, 0};
__constant__ int c_k0[32] = { 0,12, 0,11, 0,11,22, 0,10,20, 0, 0,10,10,19, 0, 9, 0, 9,18, 0, 8, 0, 0, 7, 0, 6, 0, 0, 5, 0, 0};
__constant__ int c_kt[32] = {12,12,11,11,11,11,10,10,10,10,10,10,10, 9, 9, 9, 9, 9, 9, 8, 8, 8, 8, 7, 7, 6, 6, 6, 5, 5, 4, 2};
__constant__ int c_ds[32] = { 0, 1, 0, 1, 0, 1, 2, 0, 1, 2, 0, 0, 1, 1, 2, 0, 1, 0, 1, 2, 0, 1, 0, 0, 1, 0, 1, 0, 0, 1, 0, 0};

// ---------------- helpers ----------------
__device__ __forceinline__ float rnaf(float f) {
    uint32_t r; asm("cvt.rna.tf32.f32 %0, %1;" : "=r"(r) : "f"(f));
    return __uint_as_float(r);
}
__device__ __forceinline__ uint32_t smem_u32(const void* p) {
    uint32_t a;
    asm("{ .reg .u64 t; cvta.to.shared.u64 t, %1; cvt.u32.u64 %0, t; }" : "=r"(a) : "l"(p));
    return a;
}
__device__ __forceinline__ void cp16(uint32_t dst, const void* src) {
    asm volatile("cp.async.cg.shared.global [%0], [%1], 16;" :: "r"(dst), "l"(src));
}
__device__ __forceinline__ void cp4(uint32_t dst, const void* src) {
    asm volatile("cp.async.ca.shared.global [%0], [%1], 4;" :: "r"(dst), "l"(src));
}
__device__ __forceinline__ void mma_tf32(float c[4],
                                         uint32_t a0, uint32_t a1, uint32_t a2, uint32_t a3,
                                         uint32_t b0, uint32_t b1) {
    asm volatile("mma.sync.aligned.m16n8k8.row.col.f32.tf32.tf32.f32 "
                 "{%0,%1,%2,%3}, {%4,%5,%6,%7}, {%8,%9}, {%0,%1,%2,%3};"
                 : "+f"(c[0]), "+f"(c[1]), "+f"(c[2]), "+f"(c[3])
                 : "r"(a0), "r"(a1), "r"(a2), "r"(a3), "r"(b0), "r"(b1));
}

#define ASTRIDE 36
#define BSTRIDE 136

// ---------------------------------------------------------------------------
// dense tf32 GEMM tile: C[128,128], 256 threads = 8 warps (2m x 4n,
// warp tile 64x32), BK=32, 3-stage cp.async. rna on B frags always; on A
// frags when rndA (raw x input).
// ---------------------------------------------------------------------------
#define A2FLOATS (128*ASTRIDE)                 // 4608
#define STAGEF2  (A2FLOATS + 32*BSTRIDE)       // 8960 floats
#define SMEM_GEMM2 (3*STAGEF2*4)               // 107520 B

__device__ __forceinline__ void load_stage2(uint32_t sb, int s,
                                            const float* A, int lda, int bm,
                                            const float* B, int ldb, int bn,
                                            int tid, int kt) {
    uint32_t sa = sb + s * (STAGEF2 * 4);
    uint32_t sB = sa + A2FLOATS * 4;
    int k0 = kt * 32;
    #pragma unroll
    for (int t = 0; t < 4; t++) {
        int c = tid + t * 256;
        int row = c >> 3, col = c & 7;
        cp16(sa + row * (ASTRIDE*4) + col * 16,
             A + (size_t)(bm + row) * lda + k0 + col * 4);
    }
    #pragma unroll
    for (int t = 0; t < 4; t++) {
        int c = tid + t * 256;
        int row = c >> 5, col = c & 31;
        cp16(sB + row * (BSTRIDE*4) + col * 16,
             B + (size_t)(k0 + row) * ldb + bn + col * 4);
    }
}

__device__ void dense_tile(const float* __restrict__ A, const float* __restrict__ Bw,
                           float* __restrict__ C, int K, int N, int mode, int rndA,
                           int bm, int bn, float* sm, uint32_t sb) {
    int tid = threadIdx.x;
    int warp = tid >> 5, lane = tid & 31;
    int wm = (warp & 1) * 64;
    int wn = (warp >> 1) * 32;
    int tg = lane >> 2, tk = lane & 3;
    int KT = K / 32;

    float acc[4][4][4];
    #pragma unroll
    for (int mt = 0; mt < 4; mt++)
        #pragma unroll
        for (int nt = 0; nt < 4; nt++)
            #pragma unroll
            for (int i = 0; i < 4; i++) acc[mt][nt][i] = 0.f;

    load_stage2(sb, 0, A, K, bm, Bw, N, bn, tid, 0);
    asm volatile("cp.async.commit_group;" ::: "memory");
    load_stage2(sb, 1, A, K, bm, Bw, N, bn, tid, 1);
    asm volatile("cp.async.commit_group;" ::: "memory");

    for (int it = 0; it < KT; it++) {
        asm volatile("cp.async.wait_group 1;" ::: "memory");
        __syncthreads();
        int pf = it + 2;
        if (pf < KT) load_stage2(sb, pf % 3, A, K, bm, Bw, N, bn, tid, pf);
        asm volatile("cp.async.commit_group;" ::: "memory");

        const float* As = sm + (it % 3) * STAGEF2;
        const float* Bs = As + A2FLOATS;
        #pragma unroll
        for (int kq = 0; kq < 32; kq += 8) {
            uint32_t af[4][4], bf[4][2];
            #pragma unroll
            for (int mt = 0; mt < 4; mt++) {
                int m = wm + mt * 16 + tg;
                float a0 = As[m * ASTRIDE + kq + tk];
                float a1 = As[(m + 8) * ASTRIDE + kq + tk];
                float a2 = As[m * ASTRIDE + kq + tk + 4];
                float a3 = As[(m + 8) * ASTRIDE + kq + tk + 4];
                if (rndA) { a0 = rnaf(a0); a1 = rnaf(a1); a2 = rnaf(a2); a3 = rnaf(a3); }
                af[mt][0] = __float_as_uint(a0);
                af[mt][1] = __float_as_uint(a1);
                af[mt][2] = __float_as_uint(a2);
                af[mt][3] = __float_as_uint(a3);
            }
            #pragma unroll
            for (int nt = 0; nt < 4; nt++) {
                int n = wn + nt * 8 + tg;
                bf[nt][0] = __float_as_uint(rnaf(Bs[(kq + tk) * BSTRIDE + n]));
                bf[nt][1] = __float_as_uint(rnaf(Bs[(kq + tk + 4) * BSTRIDE + n]));
            }
            #pragma unroll
            for (int mt = 0; mt < 4; mt++)
                #pragma unroll
                for (int nt = 0; nt < 4; nt++)
                    mma_tf32(acc[mt][nt], af[mt][0], af[mt][1], af[mt][2], af[mt][3],
                             bf[nt][0], bf[nt][1]);
        }
        __syncthreads();
    }

    #pragma unroll
    for (int mt = 0; mt < 4; mt++) {
        #pragma unroll
        for (int nt = 0; nt < 4; nt++) {
            int r0 = bm + wm + mt * 16 + tg;
            int cc = bn + wn + nt * 8 + tk * 2;
            float2 v0 = make_float2(acc[mt][nt][0], acc[mt][nt][1]);
            float2 v1 = make_float2(acc[mt][nt][2], acc[mt][nt][3]);
            if (mode == 1) {
                v0.x = rnaf(v0.x); v0.y = rnaf(v0.y);
                v1.x = rnaf(v1.x); v1.y = rnaf(v1.y);
            }
            *(float2*)&C[(size_t)r0 * N + cc]       = v0;
            *(float2*)&C[(size_t)(r0 + 8) * N + cc] = v1;
        }
    }
}

// ---------------------------------------------------------------------------
// paths GEMM tile: logits = rna(x) @ (Wph + Wpl). Split-K x4, compact pp.
// ---------------------------------------------------------------------------
#define PSTAGEF (64*36 + 2*32*136)    // 11008 floats
#define SMEM_PATHS (2*PSTAGEF*4)

__device__ __forceinline__ void paths_load(uint32_t sb, int s,
                                           const float* xh, int bm,
                                           const float* wh, const float* wl,
                                           int tid, int kt) {
    uint32_t base = sb + s * (PSTAGEF * 4);
    uint32_t xh_o = base;
    uint32_t wh_o = base + 64*36*4;
    uint32_t wl_o = wh_o + 32*136*4;
    int k0 = kt * 32;
    #pragma unroll
    for (int t = 0; t < 2; t++) {
        int c = tid + t * 256;
        int row = c >> 3, col = c & 7;
        cp16(xh_o + row * (36*4) + col * 16,
             xh + (size_t)(bm + row) * Dd + k0 + col * 4);
    }
    #pragma unroll
    for (int t = 0; t < 4; t++) {
        int c = tid + t * 256;
        int row = c >> 5, col = c & 31;
        size_t go = (size_t)(k0 + row) * 128 + col * 4;
        uint32_t so = row * (136*4) + col * 16;
        cp16(wh_o + so, wh + go);
        cp16(wl_o + so, wl + go);
    }
}

__device__ void paths_tile(const float* __restrict__ xh0,
                           const float* __restrict__ wh0, const float* __restrict__ wl0,
                           float* __restrict__ pp, int bm, int sp,
                           float* sm, uint32_t sb) {
    int tid = threadIdx.x;
    int warp = tid >> 5, lane = tid & 31;
    int wm = (warp & 1) * 32;
    int wn = (warp >> 1) * 32;
    int tg = lane >> 2, tk = lane & 3;
    const float* xh = xh0 + sp * 256;
    const float* wh = wh0 + (size_t)(sp * 256) * 128;
    const float* wl = wl0 + (size_t)(sp * 256) * 128;
    float* out = pp + (size_t)sp * NTOK * 40;
    const int KT = 8;

    float acc[2][4][4];
    #pragma unroll
    for (int mt = 0; mt < 2; mt++)
        #pragma unroll
        for (int nt = 0; nt < 4; nt++)
            #pragma unroll
            for (int i = 0; i < 4; i++) acc[mt][nt][i] = 0.f;

    paths_load(sb, 0, xh, bm, wh, wl, tid, 0);
    asm volatile("cp.async.commit_group;" ::: "memory");

    for (int it = 0; it < KT; it++) {
        int pf = it + 1;
        if (pf < KT) {
            paths_load(sb, pf & 1, xh, bm, wh, wl, tid, pf);
            asm volatile("cp.async.commit_group;" ::: "memory");
            asm volatile("cp.async.wait_group 1;" ::: "memory");
        } else {
            asm volatile("cp.async.wait_group 0;" ::: "memory");
        }
        __syncthreads();

        const float* Xh = sm + (it & 1) * PSTAGEF;
        const float* Wh = Xh + 64*36;
        const float* Wl = Wh + 32*136;
        #pragma unroll
        for (int kq = 0; kq < 32; kq += 8) {
            uint32_t ah[2][4], bh[4][2], bl[4][2];
            #pragma unroll
            for (int mt = 0; mt < 2; mt++) {
                int m = wm + mt * 16 + tg;
                ah[mt][0] = __float_as_uint(rnaf(Xh[m * 36 + kq + tk]));
                ah[mt][1] = __float_as_uint(rnaf(Xh[(m + 8) * 36 + kq + tk]));
                ah[mt][2] = __float_as_uint(rnaf(Xh[m * 36 + kq + tk + 4]));
                ah[mt][3] = __float_as_uint(rnaf(Xh[(m + 8) * 36 + kq + tk + 4]));
            }
            #pragma unroll
            for (int nt = 0; nt < 4; nt++) {
                int n = wn + nt * 8 + tg;
                bh[nt][0] = __float_as_uint(Wh[(kq + tk) * 136 + n]);
                bh[nt][1] = __float_as_uint(Wh[(kq + tk + 4) * 136 + n]);
                bl[nt][0] = __float_as_uint(Wl[(kq + tk) * 136 + n]);
                bl[nt][1] = __float_as_uint(Wl[(kq + tk + 4) * 136 + n]);
            }
            #pragma unroll
            for (int mt = 0; mt < 2; mt++)
                #pragma unroll
                for (int nt = 0; nt < 4; nt++) {
                    mma_tf32(acc[mt][nt], ah[mt][0], ah[mt][1], ah[mt][2], ah[mt][3],
                             bh[nt][0], bh[nt][1]);
                    mma_tf32(acc[mt][nt], ah[mt][0], ah[mt][1], ah[mt][2], ah[mt][3],
                             bl[nt][0], bl[nt][1]);
                }
        }
        __syncthreads();
    }

    #pragma unroll
    for (int mt = 0; mt < 2; mt++) {
        #pragma unroll
        for (int nt = 0; nt < 4; nt++) {
            int cc = wn + nt * 8 + tk * 2;
            if (cc < Hh * DEPTH) {
                int r0 = bm + wm + mt * 16 + tg;
                out[(size_t)r0 * 40 + cc]           = acc[mt][nt][0];
                out[(size_t)r0 * 40 + cc + 1]       = acc[mt][nt][1];
                out[(size_t)(r0 + 8) * 40 + cc]     = acc[mt][nt][2];
                out[(size_t)(r0 + 8) * 40 + cc + 1] = acc[mt][nt][3];
            }
        }
    }
}

// fat kernel: bid<128 -> V-gemm tile; bid>=128 -> paths tile. grid 256.
__global__ __launch_bounds__(256, 1) void fat_vp(const float* __restrict__ x,
                                                 const float* __restrict__ Wv,
                                                 float* __restrict__ v,
                                                 const float* __restrict__ wph,
                                                 const float* __restrict__ wpl,
                                                 float* __restrict__ pp) {
    extern __shared__ float sm[];
    uint32_t sb = smem_u32(sm);
    int bid = blockIdx.x;
    if (bid < 128) {
        dense_tile(x, Wv, v, Dd, Dd, 1, 1, (bid >> 3) * 128, (bid & 7) * 128, sm, sb);
    } else {
        int p = bid - 128;
        paths_tile(x, wph, wpl, pp, (p & 31) * 64, p >> 5, sm, sb);
    }
}

__global__ __launch_bounds__(256, 1) void gemm128(const float* __restrict__ A,
                                                  const float* __restrict__ Bw,
                                                  float* __restrict__ C,
                                                  int K, int N, int mode) {
    extern __shared__ float sm[];
    uint32_t sb = smem_u32(sm);
    dense_tile(A, Bw, C, K, N, mode, 0, blockIdx.y * 128, blockIdx.x * 128, sm, sb);
}

// ---------------------------------------------------------------------------
// Fused av: pipelined 3 CTAs/SM, e-tile double-buffered, k-paths in cp.async
// groups, MUFU exp. Jobs <=12 KT units via 3-way split; qt<4 self-normalized.
// ---------------------------------------------------------------------------
#define AV_AS     0
#define AV_BS     (2*64*ASTRIDE)                   // 4608
#define AV_PQ     (AV_BS + 3*32*BSTRIDE)           // 17664
#define AV_PKS    (AV_PQ + 320)                    // 17984
#define AV_RS     (AV_PKS + 320)                   // 18304
#define AV_FLOATS (AV_RS + 64)                     // 18368
#define SMEM_AV   (AV_FLOATS*4)                    // 73472 B

__device__ __forceinline__ void av_prefetch(uint32_t sb, const float* Bv,
                                            const float* pb, int kt, int tid) {
    uint32_t sB = sb + (AV_BS + (kt % 3) * (32*BSTRIDE)) * 4;
    int kb = kt * 32;
    #pragma unroll
    for (int t = 0; t < 4; t++) {
        int c = tid + t * 256;
        int row = c >> 5, col = c & 31;
        cp16(sB + row * (BSTRIDE*4) + col * 16,
             Bv + (size_t)(kb + row) * Dd + col * 4);
    }
    if (tid < 32 * DEPTH) {
        int k = tid / DEPTH, d = tid - k * DEPTH;
        cp4(sb + (AV_PKS + (kt & 1) * 160 + tid) * 4,
            pb + (size_t)(kb + k) * (Hh*DEPTH) + d);
    }
}

__device__ __forceinline__ void av_etile(float* Ab, const float* pks, const float* pqs,
                                         int kglob0, int qmax, int warp, int lane,
                                         float rsum[8]) {
    float k0v = pks[lane*5+0], k1v = pks[lane*5+1], k2v = pks[lane*5+2],
          k3v = pks[lane*5+3], k4v = pks[lane*5+4];
    float m0 = 1.f - k0v, m1 = 1.f - k1v, m2 = 1.f - k2v, m3 = 1.f - k3v, m4 = 1.f - k4v;
    int kglob = kglob0 + lane;
    #pragma unroll
    for (int jr = 0; jr < 8; jr++) {
        int row = warp * 8 + jr;
        const float* pq = pqs + row * 5;
        float p0 = pq[0], p1 = pq[1], p2 = pq[2], p3 = pq[3], p4 = pq[4];
        float prod = p0 * k0v + (1.f - p0) * m0;
        float s = prod;
        prod *= p1 * k1v + (1.f - p1) * m1; s += prod;
        prod *= p2 * k2v + (1.f - p2) * m2; s += prod;
        prod *= p3 * k3v + (1.f - p3) * m3; s += prod;
        prod *= p4 * k4v + (1.f - p4) * m4; s += prod;
        float ev = 0.f;
        if (kglob <= qmax + row) ev = rnaf(__expf(s * 0.2f));
        rsum[jr] += ev;
        Ab[row * ASTRIDE + lane] = ev;
    }
}

__global__ __launch_bounds__(256, 3) void av_fused(const float* __restrict__ paths,
                                                   const float* __restrict__ v,
                                                   float* __restrict__ ctx,
                                                   float* __restrict__ ctx2,
                                                   float* __restrict__ ctx3,
                                                   float* __restrict__ rs) {
    extern __shared__ float sm[];
    uint32_t sb = smem_u32(sm);
    int j = blockIdx.x, bh = blockIdx.y;
    int qt = c_qt[j], k0t = c_k0[j], KT = c_kt[j], ds = c_ds[j];
    int b = bh >> 3, h = bh & 7;
    int tid = threadIdx.x;
    int warp = tid >> 5, lane = tid & 31;

    const float* pb = paths + (size_t)(b * Tt) * (Hh*DEPTH) + h * DEPTH;
    const float* Bv = v + (size_t)b * Tt * Dd + h * 128;
    float* pqs = sm + AV_PQ;
    float* rsm = sm + AV_RS;
    int qmax = qt * 64;

    av_prefetch(sb, Bv, pb, k0t + 0, tid);
    asm volatile("cp.async.commit_group;" ::: "memory");
    av_prefetch(sb, Bv, pb, k0t + 1, tid);
    asm volatile("cp.async.commit_group;" ::: "memory");

    for (int idx = tid; idx < 64 * DEPTH; idx += 256)
        pqs[idx] = pb[(size_t)(qt * 64 + idx / DEPTH) * (Hh*DEPTH) + idx % DEPTH];

    int wm = (warp & 1) * 32;
    int wn = (warp >> 1) * 32;
    int tg = lane >> 2, tk = lane & 3;
    float acc[2][4][4];
    #pragma unroll
    for (int mt = 0; mt < 2; mt++)
        #pragma unroll
        for (int nt = 0; nt < 4; nt++)
            #pragma unroll
            for (int i = 0; i < 4; i++) acc[mt][nt][i] = 0.f;
    float rsum[8];
    #pragma unroll
    for (int i = 0; i < 8; i++) rsum[i] = 0.f;

    asm volatile("cp.async.wait_group 1;" ::: "memory");
    __syncthreads();

    av_etile(sm + AV_AS, sm + AV_PKS + (k0t & 1) * 160, pqs,
             (k0t + 0) * 32, qmax, warp, lane, rsum);

    for (int it = 0; it < KT; it++) {
        asm volatile("cp.async.wait_group 1;" ::: "memory");
        __syncthreads();

        int pf = it + 2;
        if (pf < KT) av_prefetch(sb, Bv, pb, k0t + pf, tid);
        asm volatile("cp.async.commit_group;" ::: "memory");

        {
            const float* As = sm + AV_AS + (it & 1) * (64*ASTRIDE);
            const float* Bs = sm + AV_BS + ((k0t + it) % 3) * (32*BSTRIDE);
            #pragma unroll
            for (int kq = 0; kq < 32; kq += 8) {
                uint32_t af[2][4], bf[4][2];
                #pragma unroll
                for (int mt = 0; mt < 2; mt++) {
                    int m = wm + mt * 16 + tg;
                    af[mt][0] = __float_as_uint(As[m * ASTRIDE + kq + tk]);
                    af[mt][1] = __float_as_uint(As[(m + 8) * ASTRIDE + kq + tk]);
                    af[mt][2] = __float_as_uint(As[m * ASTRIDE + kq + tk + 4]);
                    af[mt][3] = __float_as_uint(As[(m + 8) * ASTRIDE + kq + tk + 4]);
                }
                #pragma unroll
                for (int nt = 0; nt < 4; nt++) {
                    int n = wn + nt * 8 + tg;
                    bf[nt][0] = __float_as_uint(Bs[(kq + tk) * BSTRIDE + n]);
                    bf[nt][1] = __float_as_uint(Bs[(kq + tk + 4) * BSTRIDE + n]);
                }
                #pragma unroll
                for (int mt = 0; mt < 2; mt++)
                    #pragma unroll
                    for (int nt = 0; nt < 4; nt++)
                        mma_tf32(acc[mt][nt], af[mt][0], af[mt][1], af[mt][2], af[mt][3],
                                 bf[nt][0], bf[nt][1]);
            }
        }

        if (it + 1 < KT) {
            asm volatile("cp.async.wait_group 1;" ::: "memory");
            av_etile(sm + AV_AS + ((it + 1) & 1) * (64*ASTRIDE),
                     sm + AV_PKS + ((k0t + it + 1) & 1) * 160, pqs,
                     (k0t + it + 1) * 32, qmax, warp, lane, rsum);
        }
    }

    #pragma unroll
    for (int jr = 0; jr < 8; jr++) {
        float s = rsum[jr];
        #pragma unroll
        for (int o = 16; o > 0; o >>= 1) s += __shfl_xor_sync(0xffffffffu, s, o);
        if (lane == 0) rsm[warp * 8 + jr] = s;
    }
    __syncthreads();

    if (qt < 4) {
        // single-chunk job: self-normalized final store
        float* C = ctx + (size_t)b * Tt * Dd + h * 128;
        #pragma unroll
        for (int mt = 0; mt < 2; mt++) {
            int rl0 = wm + mt * 16 + tg;
            float i0 = 1.f / rsm[rl0], i1 = 1.f / rsm[rl0 + 8];
            #pragma unroll
            for (int nt = 0; nt < 4; nt++) {
                int r0 = qt * 64 + rl0;
                int cc = wn + nt * 8 + tk * 2;
                *(float2*)&C[(size_t)r0 * Dd + cc] =
                    make_float2(rnaf(acc[mt][nt][0] * i0), rnaf(acc[mt][nt][1] * i0));
                *(float2*)&C[(size_t)(r0 + 8) * Dd + cc] =
                    make_float2(rnaf(acc[mt][nt][2] * i1), rnaf(acc[mt][nt][3] * i1));
            }
        }
    } else {
        if (tid < 64) {
            float* rsp = rs + (size_t)ds * (Bb*Hh) * Tt + (size_t)bh * Tt + qt * 64;
            rsp[tid] = rsm[tid];
        }
        float* C = (ds == 0 ? ctx : (ds == 1 ? ctx2 : ctx3)) + (size_t)b * Tt * Dd + h * 128;
        #pragma unroll
        for (int mt = 0; mt < 2; mt++) {
            #pragma unroll
            for (int nt = 0; nt < 4; nt++) {
                int r0 = qt * 64 + wm + mt * 16 + tg;
                int cc = wn + nt * 8 + tk * 2;
                *(float2*)&C[(size_t)r0 * Dd + cc]       = make_float2(acc[mt][nt][0], acc[mt][nt][1]);
                *(float2*)&C[(size_t)(r0 + 8) * Dd + cc] = make_float2(acc[mt][nt][2], acc[mt][nt][3]);
            }
        }
    }
}

// normalize + combine rows t>=256: 2 slots for qt in [4,12), 3 for qt>=12
__global__ __launch_bounds__(256) void ctx_norm(float4* __restrict__ ctx,
                                                const float4* __restrict__ ctx2,
                                                const float4* __restrict__ ctx3,
                                                const float* __restrict__ rs) {
    int i = blockIdx.x * 256 + threadIdx.x;
    const int per_b = 768 * Dd / 4;
    if (i < Bb * per_b) {
        int b = i / per_b;
        int off = i - b * per_b;
        int t = 256 + off / (Dd / 4);
        int c4 = off % (Dd / 4);
        int bh = b * 8 + (c4 >> 5);
        int qt = t >> 6;
        size_t gi = (size_t)b * Tt * (Dd/4) + (size_t)t * (Dd/4) + c4;
        size_t ri = (size_t)bh * Tt + t;
        const size_t RSTRIDE = (size_t)(Bb*Hh) * Tt;
        float denom = rs[ri] + rs[RSTRIDE + ri];
        float4 xa = ctx[gi], xb = ctx2[gi];
        float sx = xa.x + xb.x, sy = xa.y + xb.y, sz = xa.z + xb.z, sw = xa.w + xb.w;
        if (qt >= 12) {
            denom += rs[2 * RSTRIDE + ri];
            float4 xc = ctx3[gi];
            sx += xc.x; sy += xc.y; sz += xc.z; sw += xc.w;
        }
        float inv = 1.f / denom;
        ctx[gi] = make_float4(rnaf(sx * inv), rnaf(sy * inv),
                              rnaf(sz * inv), rnaf(sw * inv));
    }
}

// sigmoid + split-K combine: one thread per (tok, c)
__global__ __launch_bounds__(256) void sigmoid_comb(const float* __restrict__ pp,
                                                    const float* __restrict__ bp,
                                                    float* __restrict__ paths) {
    int i = blockIdx.x * 256 + threadIdx.x;
    if (i < NTOK * 40) {
        int tok = i / 40, c = i - tok * 40;
        float z = bp[c];
        #pragma unroll
        for (int s = 0; s < 4; s++)
            z += pp[(size_t)s * NTOK * 40 + i];
        paths[i] = 1.f / (1.f + __expf(-z));
    }
}

// ---------------- staging: Wp pad only ----------------
__global__ __launch_bounds__(256) void wp_prep(const float* __restrict__ Wp) {
    int i = blockIdx.x * 256 + threadIdx.x;
    if (i < Dd * 128) {
        int k = i >> 7, n = i & 127;
        float h = 0.f, l = 0.f;
        if (n < Hh * DEPTH) {
            float w = Wp[(size_t)k * (Hh * DEPTH) + n];
            h = rnaf(w);
            l = rnaf(w - h);
        }
        g_wph[i] = h;
        g_wpl[i] = l;
    }
}

// ---------------------------------------------------------------------------
extern "C" void kernel_launch(void* const* d_in, const int* in_sizes, int n_in,
                              void* d_out, int out_size) {
    const float* x  = (const float*)d_in[0];
    const float* Wp = (const float*)d_in[1];
    const float* bp = (const float*)d_in[2];
    const float* Wv = (const float*)d_in[3];
    const float* Wo = (const float*)d_in[4];
    float* out = (float*)d_out;

    float *paths, *wph, *wpl, *pp, *v, *ctx, *ctx2, *ctx3, *rs;
    cudaGetSymbolAddress((void**)&paths, g_paths);
    cudaGetSymbolAddress((void**)&wph,   g_wph);
    cudaGetSymbolAddress((void**)&wpl,   g_wpl);
    cudaGetSymbolAddress((void**)&pp,    g_pp);
    cudaGetSymbolAddress((void**)&v,     g_v);
    cudaGetSymbolAddress((void**)&ctx,   g_ctx);
    cudaGetSymbolAddress((void**)&ctx2,  g_ctx2);
    cudaGetSymbolAddress((void**)&ctx3,  g_ctx3);
    cudaGetSymbolAddress((void**)&rs,    g_rs);

    cudaFuncSetAttribute(fat_vp,   cudaFuncAttributeMaxDynamicSharedMemorySize, SMEM_GEMM2);
    cudaFuncSetAttribute(gemm128,  cudaFuncAttributeMaxDynamicSharedMemorySize, SMEM_GEMM2);
    cudaFuncSetAttribute(av_fused, cudaFuncAttributeMaxDynamicSharedMemorySize, SMEM_AV);

    // staging: Wp hi/lo pad only (x, Wv, Wo consumed raw with in-reg rna)
    wp_prep<<<(Dd*128 + 255)/256, 256>>>(Wp);

    // fat kernel: V = x@Wv (128 tiles) + paths partial GEMM (128 tiles)
    fat_vp<<<256, 256, SMEM_GEMM2>>>(x, Wv, v, wph, wpl, pp);

    // sigmoid + split-K combine -> paths table
    sigmoid_comb<<<(NTOK*40 + 255)/256, 256>>>(pp, bp, paths);

    // fused sim+softmax+attn@V (32 balanced jobs/bh, max 12 KT units)
    av_fused<<<dim3(32, Bb*Hh), 256, SMEM_AV>>>(paths, v, ctx, ctx2, ctx3, rs);

    // combine split rows (t >= 256)
    ctx_norm<<<(Bb*768*Dd/4 + 255)/256, 256>>>((float4*)ctx, (const float4*)ctx2,
                                               (const float4*)ctx3, rs);

    // out = ctx @ Wo
    gemm128<<<dim3(Dd/128, NTOK/128), 256, SMEM_GEMM2>>>(ctx, Wo, out, Dd, Dd, 0);
}

// round 17
// speedup vs baseline: 1.2199x; 1.0105x over previous
#include <cuda_runtime.h>
#include <math.h>
#include <stdint.h>

#define Bb 2
#define Tt 1024
#define Dd 1024
#define Hh 8
#define DEPTH 5
#define NTOK (Bb*Tt)

// ---------------- scratch (device globals; allocation-free) ----------------
__device__ float g_paths[NTOK*Hh*DEPTH];      // [token][h*5+d]
__device__ float g_wph[Dd*128];               // Wp hi, padded [k][128]
__device__ float g_wpl[Dd*128];               // Wp lo, padded [k][128]
__device__ float g_pp[4*NTOK*40];             // paths split-K partials (compact)
__device__ float g_v[NTOK*Dd];                // V = x@Wv, rounded
__device__ float g_ctx[NTOK*Dd];              // slot0 (final for qt<4 rows)
__device__ float g_ctx2[NTOK*Dd];             // slot1 (rows t>=256)
__device__ float g_ctx3[NTOK*Dd];             // slot2 (rows t>=768)
__device__ float g_rs[3*Bb*Hh*Tt];            // row sums [slot][bh][t]

// av jobs (32/bh, longest-first). qt<4 single chunk (self-normalized);
// qt 4..11 two chunks; qt 12..15 three chunks. max chunk = 12 KT units.
__constant__ int c_qt[32] = {11,11,15,15,10,10,15,14,14,14,13, 9, 9,13,13,12,12, 8, 8,12, 7, 7, 3, 6, 6, 5, 5, 2, 4, 4, 1, 0};
__constant__ int c_k0[32] = { 0,12, 0,11, 0,11,22, 0,10,20, 0, 0,10,10,19, 0, 9, 0, 9,18, 0, 8, 0, 0, 7, 0, 6, 0, 0, 5, 0, 0};
__constant__ int c_kt[32] = {12,12,11,11,11,11,10,10,10,10,10,10,10, 9, 9, 9, 9, 9, 9, 8, 8, 8, 8, 7, 7, 6, 6, 6, 5, 5, 4, 2};
__constant__ int c_ds[32] = { 0, 1, 0, 1, 0, 1, 2, 0, 1, 2, 0, 0, 1, 1, 2, 0, 1, 0, 1, 2, 0, 1, 0, 0, 1, 0, 1, 0, 0, 1, 0, 0};

// ---------------- helpers ----------------
__device__ __forceinline__ float rnaf(float f) {
    uint32_t r; asm("cvt.rna.tf32.f32 %0, %1;" : "=r"(r) : "f"(f));
    return __uint_as_float(r);
}
__device__ __forceinline__ uint32_t smem_u32(const void* p) {
    uint32_t a;
    asm("{ .reg .u64 t; cvta.to.shared.u64 t, %1; cvt.u32.u64 %0, t; }" : "=r"(a) : "l"(p));
    return a;
}
__device__ __forceinline__ void cp16(uint32_t dst, const void* src) {
    asm volatile("cp.async.cg.shared.global [%0], [%1], 16;" :: "r"(dst), "l"(src));
}
__device__ __forceinline__ void cp4(uint32_t dst, const void* src) {
    asm volatile("cp.async.ca.shared.global [%0], [%1], 4;" :: "r"(dst), "l"(src));
}
__device__ __forceinline__ void mma_tf32(float c[4],
                                         uint32_t a0, uint32_t a1, uint32_t a2, uint32_t a3,
                                         uint32_t b0, uint32_t b1) {
    asm volatile("mma.sync.aligned.m16n8k8.row.col.f32.tf32.tf32.f32 "
                 "{%0,%1,%2,%3}, {%4,%5,%6,%7}, {%8,%9}, {%0,%1,%2,%3};"
                 : "+f"(c[0]), "+f"(c[1]), "+f"(c[2]), "+f"(c[3])
                 : "r"(a0), "r"(a1), "r"(a2), "r"(a3), "r"(b0), "r"(b1));
}

#define ASTRIDE 36
#define BSTRIDE 136

// ---------------------------------------------------------------------------
// dense tf32 GEMM tile: C[128,128], 256 threads = 8 warps (2m x 4n,
// warp tile 64x32), BK=32, 3-stage cp.async. rna on B frags always; on A
// frags when rndA (raw x input).
// ---------------------------------------------------------------------------
#define A2FLOATS (128*ASTRIDE)                 // 4608
#define STAGEF2  (A2FLOATS + 32*BSTRIDE)       // 8960 floats
#define SMEM_GEMM2 (3*STAGEF2*4)               // 107520 B

__device__ __forceinline__ void load_stage2(uint32_t sb, int s,
                                            const float* A, int lda, int bm,
                                            const float* B, int ldb, int bn,
                                            int tid, int kt) {
    uint32_t sa = sb + s * (STAGEF2 * 4);
    uint32_t sB = sa + A2FLOATS * 4;
    int k0 = kt * 32;
    #pragma unroll
    for (int t = 0; t < 4; t++) {
        int c = tid + t * 256;
        int row = c >> 3, col = c & 7;
        cp16(sa + row * (ASTRIDE*4) + col * 16,
             A + (size_t)(bm + row) * lda + k0 + col * 4);
    }
    #pragma unroll
    for (int t = 0; t < 4; t++) {
        int c = tid + t * 256;
        int row = c >> 5, col = c & 31;
        cp16(sB + row * (BSTRIDE*4) + col * 16,
             B + (size_t)(k0 + row) * ldb + bn + col * 4);
    }
}

__device__ void dense_tile(const float* __restrict__ A, const float* __restrict__ Bw,
                           float* __restrict__ C, int K, int N, int mode, int rndA,
                           int bm, int bn, float* sm, uint32_t sb) {
    int tid = threadIdx.x;
    int warp = tid >> 5, lane = tid & 31;
    int wm = (warp & 1) * 64;
    int wn = (warp >> 1) * 32;
    int tg = lane >> 2, tk = lane & 3;
    int KT = K / 32;

    float acc[4][4][4];
    #pragma unroll
    for (int mt = 0; mt < 4; mt++)
        #pragma unroll
        for (int nt = 0; nt < 4; nt++)
            #pragma unroll
            for (int i = 0; i < 4; i++) acc[mt][nt][i] = 0.f;

    load_stage2(sb, 0, A, K, bm, Bw, N, bn, tid, 0);
    asm volatile("cp.async.commit_group;" ::: "memory");
    load_stage2(sb, 1, A, K, bm, Bw, N, bn, tid, 1);
    asm volatile("cp.async.commit_group;" ::: "memory");

    for (int it = 0; it < KT; it++) {
        asm volatile("cp.async.wait_group 1;" ::: "memory");
        __syncthreads();
        int pf = it + 2;
        if (pf < KT) load_stage2(sb, pf % 3, A, K, bm, Bw, N, bn, tid, pf);
        asm volatile("cp.async.commit_group;" ::: "memory");

        const float* As = sm + (it % 3) * STAGEF2;
        const float* Bs = As + A2FLOATS;
        #pragma unroll
        for (int kq = 0; kq < 32; kq += 8) {
            uint32_t af[4][4], bf[4][2];
            #pragma unroll
            for (int mt = 0; mt < 4; mt++) {
                int m = wm + mt * 16 + tg;
                float a0 = As[m * ASTRIDE + kq + tk];
                float a1 = As[(m + 8) * ASTRIDE + kq + tk];
                float a2 = As[m * ASTRIDE + kq + tk + 4];
                float a3 = As[(m + 8) * ASTRIDE + kq + tk + 4];
                if (rndA) { a0 = rnaf(a0); a1 = rnaf(a1); a2 = rnaf(a2); a3 = rnaf(a3); }
                af[mt][0] = __float_as_uint(a0);
                af[mt][1] = __float_as_uint(a1);
                af[mt][2] = __float_as_uint(a2);
                af[mt][3] = __float_as_uint(a3);
            }
            #pragma unroll
            for (int nt = 0; nt < 4; nt++) {
                int n = wn + nt * 8 + tg;
                bf[nt][0] = __float_as_uint(rnaf(Bs[(kq + tk) * BSTRIDE + n]));
                bf[nt][1] = __float_as_uint(rnaf(Bs[(kq + tk + 4) * BSTRIDE + n]));
            }
            #pragma unroll
            for (int mt = 0; mt < 4; mt++)
                #pragma unroll
                for (int nt = 0; nt < 4; nt++)
                    mma_tf32(acc[mt][nt], af[mt][0], af[mt][1], af[mt][2], af[mt][3],
                             bf[nt][0], bf[nt][1]);
        }
        __syncthreads();
    }

    #pragma unroll
    for (int mt = 0; mt < 4; mt++) {
        #pragma unroll
        for (int nt = 0; nt < 4; nt++) {
            int r0 = bm + wm + mt * 16 + tg;
            int cc = bn + wn + nt * 8 + tk * 2;
            float2 v0 = make_float2(acc[mt][nt][0], acc[mt][nt][1]);
            float2 v1 = make_float2(acc[mt][nt][2], acc[mt][nt][3]);
            if (mode == 1) {
                v0.x = rnaf(v0.x); v0.y = rnaf(v0.y);
                v1.x = rnaf(v1.x); v1.y = rnaf(v1.y);
            }
            *(float2*)&C[(size_t)r0 * N + cc]       = v0;
            *(float2*)&C[(size_t)(r0 + 8) * N + cc] = v1;
        }
    }
}

// ---------------------------------------------------------------------------
// paths GEMM tile: logits = rna(x) @ (Wph + Wpl). Split-K x4, compact pp.
// ---------------------------------------------------------------------------
#define PSTAGEF (64*36 + 2*32*136)    // 11008 floats
#define SMEM_PATHS (2*PSTAGEF*4)

__device__ __forceinline__ void paths_load(uint32_t sb, int s,
                                           const float* xh, int bm,
                                           const float* wh, const float* wl,
                                           int tid, int kt) {
    uint32_t base = sb + s * (PSTAGEF * 4);
    uint32_t xh_o = base;
    uint32_t wh_o = base + 64*36*4;
    uint32_t wl_o = wh_o + 32*136*4;
    int k0 = kt * 32;
    #pragma unroll
    for (int t = 0; t < 2; t++) {
        int c = tid + t * 256;
        int row = c >> 3, col = c & 7;
        cp16(xh_o + row * (36*4) + col * 16,
             xh + (size_t)(bm + row) * Dd + k0 + col * 4);
    }
    #pragma unroll
    for (int t = 0; t < 4; t++) {
        int c = tid + t * 256;
        int row = c >> 5, col = c & 31;
        size_t go = (size_t)(k0 + row) * 128 + col * 4;
        uint32_t so = row * (136*4) + col * 16;
        cp16(wh_o + so, wh + go);
        cp16(wl_o + so, wl + go);
    }
}

__device__ void paths_tile(const float* __restrict__ xh0,
                           const float* __restrict__ wh0, const float* __restrict__ wl0,
                           float* __restrict__ pp, int bm, int sp,
                           float* sm, uint32_t sb) {
    int tid = threadIdx.x;
    int warp = tid >> 5, lane = tid & 31;
    int wm = (warp & 1) * 32;
    int wn = (warp >> 1) * 32;
    int tg = lane >> 2, tk = lane & 3;
    const float* xh = xh0 + sp * 256;
    const float* wh = wh0 + (size_t)(sp * 256) * 128;
    const float* wl = wl0 + (size_t)(sp * 256) * 128;
    float* out = pp + (size_t)sp * NTOK * 40;
    const int KT = 8;

    float acc[2][4][4];
    #pragma unroll
    for (int mt = 0; mt < 2; mt++)
        #pragma unroll
        for (int nt = 0; nt < 4; nt++)
            #pragma unroll
            for (int i = 0; i < 4; i++) acc[mt][nt][i] = 0.f;

    paths_load(sb, 0, xh, bm, wh, wl, tid, 0);
    asm volatile("cp.async.commit_group;" ::: "memory");

    for (int it = 0; it < KT; it++) {
        int pf = it + 1;
        if (pf < KT) {
            paths_load(sb, pf & 1, xh, bm, wh, wl, tid, pf);
            asm volatile("cp.async.commit_group;" ::: "memory");
            asm volatile("cp.async.wait_group 1;" ::: "memory");
        } else {
            asm volatile("cp.async.wait_group 0;" ::: "memory");
        }
        __syncthreads();

        const float* Xh = sm + (it & 1) * PSTAGEF;
        const float* Wh = Xh + 64*36;
        const float* Wl = Wh + 32*136;
        #pragma unroll
        for (int kq = 0; kq < 32; kq += 8) {
            uint32_t ah[2][4], bh[4][2], bl[4][2];
            #pragma unroll
            for (int mt = 0; mt < 2; mt++) {
                int m = wm + mt * 16 + tg;
                ah[mt][0] = __float_as_uint(rnaf(Xh[m * 36 + kq + tk]));
                ah[mt][1] = __float_as_uint(rnaf(Xh[(m + 8) * 36 + kq + tk]));
                ah[mt][2] = __float_as_uint(rnaf(Xh[m * 36 + kq + tk + 4]));
                ah[mt][3] = __float_as_uint(rnaf(Xh[(m + 8) * 36 + kq + tk + 4]));
            }
            #pragma unroll
            for (int nt = 0; nt < 4; nt++) {
                int n = wn + nt * 8 + tg;
                bh[nt][0] = __float_as_uint(Wh[(kq + tk) * 136 + n]);
                bh[nt][1] = __float_as_uint(Wh[(kq + tk + 4) * 136 + n]);
                bl[nt][0] = __float_as_uint(Wl[(kq + tk) * 136 + n]);
                bl[nt][1] = __float_as_uint(Wl[(kq + tk + 4) * 136 + n]);
            }
            #pragma unroll
            for (int mt = 0; mt < 2; mt++)
                #pragma unroll
                for (int nt = 0; nt < 4; nt++) {
                    mma_tf32(acc[mt][nt], ah[mt][0], ah[mt][1], ah[mt][2], ah[mt][3],
                             bh[nt][0], bh[nt][1]);
                    mma_tf32(acc[mt][nt], ah[mt][0], ah[mt][1], ah[mt][2], ah[mt][3],
                             bl[nt][0], bl[nt][1]);
                }
        }
        __syncthreads();
    }

    #pragma unroll
    for (int mt = 0; mt < 2; mt++) {
        #pragma unroll
        for (int nt = 0; nt < 4; nt++) {
            int cc = wn + nt * 8 + tk * 2;
            if (cc < Hh * DEPTH) {
                int r0 = bm + wm + mt * 16 + tg;
                out[(size_t)r0 * 40 + cc]           = acc[mt][nt][0];
                out[(size_t)r0 * 40 + cc + 1]       = acc[mt][nt][1];
                out[(size_t)(r0 + 8) * 40 + cc]     = acc[mt][nt][2];
                out[(size_t)(r0 + 8) * 40 + cc + 1] = acc[mt][nt][3];
            }
        }
    }
}

// fat kernel: bid<128 -> V-gemm tile; bid>=128 -> paths tile. grid 256.
__global__ __launch_bounds__(256, 1) void fat_vp(const float* __restrict__ x,
                                                 const float* __restrict__ Wv,
                                                 float* __restrict__ v,
                                                 const float* __restrict__ wph,
                                                 const float* __restrict__ wpl,
                                                 float* __restrict__ pp) {
    extern __shared__ float sm[];
    uint32_t sb = smem_u32(sm);
    int bid = blockIdx.x;
    if (bid < 128) {
        dense_tile(x, Wv, v, Dd, Dd, 1, 1, (bid >> 3) * 128, (bid & 7) * 128, sm, sb);
    } else {
        int p = bid - 128;
        paths_tile(x, wph, wpl, pp, (p & 31) * 64, p >> 5, sm, sb);
    }
}

__global__ __launch_bounds__(256, 1) void gemm128(const float* __restrict__ A,
                                                  const float* __restrict__ Bw,
                                                  float* __restrict__ C,
                                                  int K, int N, int mode) {
    extern __shared__ float sm[];
    uint32_t sb = smem_u32(sm);
    dense_tile(A, Bw, C, K, N, mode, 0, blockIdx.y * 128, blockIdx.x * 128, sm, sb);
}

// ---------------------------------------------------------------------------
// Fused av: pipelined 3 CTAs/SM, e-tile double-buffered, k-paths in cp.async
// groups, MUFU exp. Per-row coefficients precomputed: a = 2p-1, b = 1-p, so
// each depth step is fma(a,k,b) + cumprod + add (3 ops vs 5).
// ---------------------------------------------------------------------------
#define AV_AS     0
#define AV_BS     (2*64*ASTRIDE)                   // 4608
#define AV_PQ     (AV_BS + 3*32*BSTRIDE)           // 17664 (a:320 | b:320)
#define AV_PKS    (AV_PQ + 640)                    // 18304
#define AV_RS     (AV_PKS + 320)                   // 18624
#define AV_FLOATS (AV_RS + 64)                     // 18688
#define SMEM_AV   (AV_FLOATS*4)                    // 74752 B

__device__ __forceinline__ void av_prefetch(uint32_t sb, const float* Bv,
                                            const float* pb, int kt, int tid) {
    uint32_t sB = sb + (AV_BS + (kt % 3) * (32*BSTRIDE)) * 4;
    int kb = kt * 32;
    #pragma unroll
    for (int t = 0; t < 4; t++) {
        int c = tid + t * 256;
        int row = c >> 5, col = c & 31;
        cp16(sB + row * (BSTRIDE*4) + col * 16,
             Bv + (size_t)(kb + row) * Dd + col * 4);
    }
    if (tid < 32 * DEPTH) {
        int k = tid / DEPTH, d = tid - k * DEPTH;
        cp4(sb + (AV_PKS + (kt & 1) * 160 + tid) * 4,
            pb + (size_t)(kb + k) * (Hh*DEPTH) + d);
    }
}

__device__ __forceinline__ void av_etile(float* Ab, const float* pks, const float* pqs,
                                         int kglob0, int qmax, int warp, int lane,
                                         float rsum[8]) {
    float k0v = pks[lane*5+0], k1v = pks[lane*5+1], k2v = pks[lane*5+2],
          k3v = pks[lane*5+3], k4v = pks[lane*5+4];
    int kglob = kglob0 + lane;
    #pragma unroll
    for (int jr = 0; jr < 8; jr++) {
        int row = warp * 8 + jr;
        const float* pa = pqs + row * 5;
        const float* pc = pqs + 320 + row * 5;
        float t0 = fmaf(pa[0], k0v, pc[0]);
        float s = t0;
        float prod = t0;
        float t1 = fmaf(pa[1], k1v, pc[1]); prod *= t1; s += prod;
        float t2 = fmaf(pa[2], k2v, pc[2]); prod *= t2; s += prod;
        float t3 = fmaf(pa[3], k3v, pc[3]); prod *= t3; s += prod;
        float t4 = fmaf(pa[4], k4v, pc[4]); prod *= t4; s += prod;
        float ev = 0.f;
        if (kglob <= qmax + row) ev = rnaf(__expf(s * 0.2f));
        rsum[jr] += ev;
        Ab[row * ASTRIDE + lane] = ev;
    }
}

__global__ __launch_bounds__(256, 3) void av_fused(const float* __restrict__ paths,
                                                   const float* __restrict__ v,
                                                   float* __restrict__ ctx,
                                                   float* __restrict__ ctx2,
                                                   float* __restrict__ ctx3,
                                                   float* __restrict__ rs) {
    extern __shared__ float sm[];
    uint32_t sb = smem_u32(sm);
    int j = blockIdx.x, bh = blockIdx.y;
    int qt = c_qt[j], k0t = c_k0[j], KT = c_kt[j], ds = c_ds[j];
    int b = bh >> 3, h = bh & 7;
    int tid = threadIdx.x;
    int warp = tid >> 5, lane = tid & 31;

    const float* pb = paths + (size_t)(b * Tt) * (Hh*DEPTH) + h * DEPTH;
    const float* Bv = v + (size_t)b * Tt * Dd + h * 128;
    float* pqs = sm + AV_PQ;
    float* rsm = sm + AV_RS;
    int qmax = qt * 64;

    av_prefetch(sb, Bv, pb, k0t + 0, tid);
    asm volatile("cp.async.commit_group;" ::: "memory");
    av_prefetch(sb, Bv, pb, k0t + 1, tid);
    asm volatile("cp.async.commit_group;" ::: "memory");

    // q-row coefficients: a = 2p-1, b = 1-p
    for (int idx = tid; idx < 64 * DEPTH; idx += 256) {
        float p = pb[(size_t)(qt * 64 + idx / DEPTH) * (Hh*DEPTH) + idx % DEPTH];
        pqs[idx]       = 2.f * p - 1.f;
        pqs[320 + idx] = 1.f - p;
    }

    int wm = (warp & 1) * 32;
    int wn = (warp >> 1) * 32;
    int tg = lane >> 2, tk = lane & 3;
    float acc[2][4][4];
    #pragma unroll
    for (int mt = 0; mt < 2; mt++)
        #pragma unroll
        for (int nt = 0; nt < 4; nt++)
            #pragma unroll
            for (int i = 0; i < 4; i++) acc[mt][nt][i] = 0.f;
    float rsum[8];
    #pragma unroll
    for (int i = 0; i < 8; i++) rsum[i] = 0.f;

    asm volatile("cp.async.wait_group 1;" ::: "memory");
    __syncthreads();

    av_etile(sm + AV_AS, sm + AV_PKS + (k0t & 1) * 160, pqs,
             (k0t + 0) * 32, qmax, warp, lane, rsum);

    for (int it = 0; it < KT; it++) {
        asm volatile("cp.async.wait_group 1;" ::: "memory");
        __syncthreads();

        int pf = it + 2;
        if (pf < KT) av_prefetch(sb, Bv, pb, k0t + pf, tid);
        asm volatile("cp.async.commit_group;" ::: "memory");

        {
            const float* As = sm + AV_AS + (it & 1) * (64*ASTRIDE);
            const float* Bs = sm + AV_BS + ((k0t + it) % 3) * (32*BSTRIDE);
            #pragma unroll
            for (int kq = 0; kq < 32; kq += 8) {
                uint32_t af[2][4], bf[4][2];
                #pragma unroll
                for (int mt = 0; mt < 2; mt++) {
                    int m = wm + mt * 16 + tg;
                    af[mt][0] = __float_as_uint(As[m * ASTRIDE + kq + tk]);
                    af[mt][1] = __float_as_uint(As[(m + 8) * ASTRIDE + kq + tk]);
                    af[mt][2] = __float_as_uint(As[m * ASTRIDE + kq + tk + 4]);
                    af[mt][3] = __float_as_uint(As[(m + 8) * ASTRIDE + kq + tk + 4]);
                }
                #pragma unroll
                for (int nt = 0; nt < 4; nt++) {
                    int n = wn + nt * 8 + tg;
                    bf[nt][0] = __float_as_uint(Bs[(kq + tk) * BSTRIDE + n]);
                    bf[nt][1] = __float_as_uint(Bs[(kq + tk + 4) * BSTRIDE + n]);
                }
                #pragma unroll
                for (int mt = 0; mt < 2; mt++)
                    #pragma unroll
                    for (int nt = 0; nt < 4; nt++)
                        mma_tf32(acc[mt][nt], af[mt][0], af[mt][1], af[mt][2], af[mt][3],
                                 bf[nt][0], bf[nt][1]);
            }
        }

        if (it + 1 < KT) {
            asm volatile("cp.async.wait_group 1;" ::: "memory");
            av_etile(sm + AV_AS + ((it + 1) & 1) * (64*ASTRIDE),
                     sm + AV_PKS + ((k0t + it + 1) & 1) * 160, pqs,
                     (k0t + it + 1) * 32, qmax, warp, lane, rsum);
        }
    }

    #pragma unroll
    for (int jr = 0; jr < 8; jr++) {
        float s = rsum[jr];
        #pragma unroll
        for (int o = 16; o > 0; o >>= 1) s += __shfl_xor_sync(0xffffffffu, s, o);
        if (lane == 0) rsm[warp * 8 + jr] = s;
    }
    __syncthreads();

    if (qt < 4) {
        float* C = ctx + (size_t)b * Tt * Dd + h * 128;
        #pragma unroll
        for (int mt = 0; mt < 2; mt++) {
            int rl0 = wm + mt * 16 + tg;
            float i0 = 1.f / rsm[rl0], i1 = 1.f / rsm[rl0 + 8];
            #pragma unroll
            for (int nt = 0; nt < 4; nt++) {
                int r0 = qt * 64 + rl0;
                int cc = wn + nt * 8 + tk * 2;
                *(float2*)&C[(size_t)r0 * Dd + cc] =
                    make_float2(rnaf(acc[mt][nt][0] * i0), rnaf(acc[mt][nt][1] * i0));
                *(float2*)&C[(size_t)(r0 + 8) * Dd + cc] =
                    make_float2(rnaf(acc[mt][nt][2] * i1), rnaf(acc[mt][nt][3] * i1));
            }
        }
    } else {
        if (tid < 64) {
            float* rsp = rs + (size_t)ds * (Bb*Hh) * Tt + (size_t)bh * Tt + qt * 64;
            rsp[tid] = rsm[tid];
        }
        float* C = (ds == 0 ? ctx : (ds == 1 ? ctx2 : ctx3)) + (size_t)b * Tt * Dd + h * 128;
        #pragma unroll
        for (int mt = 0; mt < 2; mt++) {
            #pragma unroll
            for (int nt = 0; nt < 4; nt++) {
                int r0 = qt * 64 + wm + mt * 16 + tg;
                int cc = wn + nt * 8 + tk * 2;
                *(float2*)&C[(size_t)r0 * Dd + cc]       = make_float2(acc[mt][nt][0], acc[mt][nt][1]);
                *(float2*)&C[(size_t)(r0 + 8) * Dd + cc] = make_float2(acc[mt][nt][2], acc[mt][nt][3]);
            }
        }
    }
}

// normalize + combine rows t>=256: 2 slots for qt in [4,12), 3 for qt>=12
__global__ __launch_bounds__(256) void ctx_norm(float4* __restrict__ ctx,
                                                const float4* __restrict__ ctx2,
                                                const float4* __restrict__ ctx3,
                                                const float* __restrict__ rs) {
    int i = blockIdx.x * 256 + threadIdx.x;
    const int per_b = 768 * Dd / 4;
    if (i < Bb * per_b) {
        int b = i / per_b;
        int off = i - b * per_b;
        int t = 256 + off / (Dd / 4);
        int c4 = off % (Dd / 4);
        int bh = b * 8 + (c4 >> 5);
        int qt = t >> 6;
        size_t gi = (size_t)b * Tt * (Dd/4) + (size_t)t * (Dd/4) + c4;
        size_t ri = (size_t)bh * Tt + t;
        const size_t RSTRIDE = (size_t)(Bb*Hh) * Tt;
        float denom = rs[ri] + rs[RSTRIDE + ri];
        float4 xa = ctx[gi], xb = ctx2[gi];
        float sx = xa.x + xb.x, sy = xa.y + xb.y, sz = xa.z + xb.z, sw = xa.w + xb.w;
        if (qt >= 12) {
            denom += rs[2 * RSTRIDE + ri];
            float4 xc = ctx3[gi];
            sx += xc.x; sy += xc.y; sz += xc.z; sw += xc.w;
        }
        float inv = 1.f / denom;
        ctx[gi] = make_float4(rnaf(sx * inv), rnaf(sy * inv),
                              rnaf(sz * inv), rnaf(sw * inv));
    }
}

// sigmoid + split-K combine: one thread per (tok, c)
__global__ __launch_bounds__(256) void sigmoid_comb(const float* __restrict__ pp,
                                                    const float* __restrict__ bp,
                                                    float* __restrict__ paths) {
    int i = blockIdx.x * 256 + threadIdx.x;
    if (i < NTOK * 40) {
        int tok = i / 40, c = i - tok * 40;
        float z = bp[c];
        #pragma unroll
        for (int s = 0; s < 4; s++)
            z += pp[(size_t)s * NTOK * 40 + i];
        paths[i] = 1.f / (1.f + __expf(-z));
    }
}

// ---------------- staging: Wp pad only ----------------
__global__ __launch_bounds__(256) void wp_prep(const float* __restrict__ Wp) {
    int i = blockIdx.x * 256 + threadIdx.x;
    if (i < Dd * 128) {
        int k = i >> 7, n = i & 127;
        float h = 0.f, l = 0.f;
        if (n < Hh * DEPTH) {
            float w = Wp[(size_t)k * (Hh * DEPTH) + n];
            h = rnaf(w);
            l = rnaf(w - h);
        }
        g_wph[i] = h;
        g_wpl[i] = l;
    }
}

// ---------------------------------------------------------------------------
extern "C" void kernel_launch(void* const* d_in, const int* in_sizes, int n_in,
                              void* d_out, int out_size) {
    const float* x  = (const float*)d_in[0];
    const float* Wp = (const float*)d_in[1];
    const float* bp = (const float*)d_in[2];
    const float* Wv = (const float*)d_in[3];
    const float* Wo = (const float*)d_in[4];
    float* out = (float*)d_out;

    float *paths, *wph, *wpl, *pp, *v, *ctx, *ctx2, *ctx3, *rs;
    cudaGetSymbolAddress((void**)&paths, g_paths);
    cudaGetSymbolAddress((void**)&wph,   g_wph);
    cudaGetSymbolAddress((void**)&wpl,   g_wpl);
    cudaGetSymbolAddress((void**)&pp,    g_pp);
    cudaGetSymbolAddress((void**)&v,     g_v);
    cudaGetSymbolAddress((void**)&ctx,   g_ctx);
    cudaGetSymbolAddress((void**)&ctx2,  g_ctx2);
    cudaGetSymbolAddress((void**)&ctx3,  g_ctx3);
    cudaGetSymbolAddress((void**)&rs,    g_rs);

    cudaFuncSetAttribute(fat_vp,   cudaFuncAttributeMaxDynamicSharedMemorySize, SMEM_GEMM2);
    cudaFuncSetAttribute(gemm128,  cudaFuncAttributeMaxDynamicSharedMemorySize, SMEM_GEMM2);
    cudaFuncSetAttribute(av_fused, cudaFuncAttributeMaxDynamicSharedMemorySize, SMEM_AV);

    // staging: Wp hi/lo pad only
    wp_prep<<<(Dd*128 + 255)/256, 256>>>(Wp);

    // fat kernel: V = x@Wv (128 tiles) + paths partial GEMM (128 tiles)
    fat_vp<<<256, 256, SMEM_GEMM2>>>(x, Wv, v, wph, wpl, pp);

    // sigmoid + split-K combine -> paths table
    sigmoid_comb<<<(NTOK*40 + 255)/256, 256>>>(pp, bp, paths);

    // fused sim+softmax+attn@V (32 balanced jobs/bh, max 12 KT units)
    av_fused<<<dim3(32, Bb*Hh), 256, SMEM_AV>>>(paths, v, ctx, ctx2, ctx3, rs);

    // combine split rows (t >= 256)
    ctx_norm<<<(Bb*768*Dd/4 + 255)/256, 256>>>((float4*)ctx, (const float4*)ctx2,
                                               (const float4*)ctx3, rs);

    // out = ctx @ Wo
    gemm128<<<dim3(Dd/128, NTOK/128), 256, SMEM_GEMM2>>>(ctx, Wo, out, Dd, Dd, 0);
}